// round 8
// baseline (speedup 1.0000x reference)
#include <cuda_runtime.h>
#include <cuda_bf16.h>
#include <cstdint>

// ---------------- problem constants ----------------
#define BATCH 8
#define CCH   64
#define HH    64
#define WW    64
#define NPOS  4096
#define LSEQ  77
#define DTXT  512
#define NBLK  16
#define NHEAD 8
#define HDIM  8

// ---------------- device scratch ----------------
__device__ float g_tf  [BATCH*LSEQ*CCH];
__device__ float g_kn  [NBLK*BATCH*LSEQ*CCH];
__device__ float g_v   [NBLK*BATCH*LSEQ*CCH];
__device__ float g_feat[BATCH*CCH*HH*WW];
__device__ float g_u1  [BATCH*CCH*128*128];
__device__ float g_u2  [(size_t)BATCH*CCH*256*256];
__device__ float g_wupT[2*9*4*64*64];   // [lvl][tap][ocg][oc(64)][ic(64)], tf32

__device__ __forceinline__ float to_tf32(float x) {
    float r; asm("cvt.rna.tf32.f32 %0, %1;" : "=f"(r) : "f"(x)); return r;
}
__device__ __forceinline__ void mma_tf32(float* d, const uint32_t* a, const uint32_t* b) {
    asm volatile(
        "mma.sync.aligned.m16n8k8.row.col.f32.tf32.tf32.f32 "
        "{%0,%1,%2,%3}, {%4,%5,%6,%7}, {%8,%9}, {%0,%1,%2,%3};"
        : "+f"(d[0]), "+f"(d[1]), "+f"(d[2]), "+f"(d[3])
        : "r"(a[0]), "r"(a[1]), "r"(a[2]), "r"(a[3]), "r"(b[0]), "r"(b[1]));
}
// permuted channel index: ic = ks*8 + tig + 4h  ->  pic = ks*8 + tig*2 + h
__device__ __forceinline__ int picf(int ic) {
    int r = ic & 7;
    return (ic & ~7) + ((r & 3) * 2) + (r >> 2);
}

// ---------------- text projection (+ fused tf32 up-weight transpose) ----------------
__global__ void k_textproj(const float* __restrict__ th,
                           const float* __restrict__ pw,
                           const float* __restrict__ pb,
                           const float* __restrict__ upw) {
    __shared__ float s[DTXT];
    int bl = blockIdx.x;
    const float* row = th + (size_t)bl * DTXT;
    for (int i = threadIdx.x; i < DTXT; i += 64) s[i] = row[i];
    __syncthreads();
    int c = threadIdx.x;
    const float* w = pw + (size_t)c * DTXT;
    float acc = pb[c];
#pragma unroll 8
    for (int d = 0; d < DTXT; ++d) acc += s[d] * w[d];
    g_tf[bl * CCH + c] = acc;
    for (int idx = blockIdx.x * 64 + threadIdx.x; idx < 2 * 256 * 64 * 9;
         idx += gridDim.x * 64) {
        int k = idx % 9;
        int t = idx / 9;
        int ic = t % 64; t /= 64;
        int oc4 = t % 256;
        int lvl = t / 256;
        g_wupT[((((lvl * 9 + k) * 4 + (oc4 >> 6)) * 64 + (oc4 & 63)) * 64) + ic]
            = to_tf32(upw[idx]);
    }
}

// ---------------- input conv 3->64, 3x3 ----------------
__global__ void k_convin(const float* __restrict__ x,
                         const float* __restrict__ w,
                         const float* __restrict__ bias) {
    __shared__ float sw[64 * 27];
    __shared__ float sb[64];
    __shared__ float sin_[3][3][66];
    int bid = blockIdx.x; int b = bid >> 6; int y = bid & 63;
    int tid = threadIdx.x;
    for (int i = tid; i < 64 * 27; i += 64) sw[i] = w[i];
    sb[tid] = bias[tid];
    for (int ic = 0; ic < 3; ic++)
        for (int r = 0; r < 3; r++) {
            int yy = y + r - 1;
            float v = 0.f;
            if (yy >= 0 && yy < HH) v = x[(((size_t)b * 3 + ic) * HH + yy) * WW + tid];
            sin_[ic][r][tid + 1] = v;
            if (tid == 0) { sin_[ic][r][0] = 0.f; sin_[ic][r][65] = 0.f; }
        }
    __syncthreads();
    int xx = tid;
    for (int oc = 0; oc < 64; oc++) {
        float acc = sb[oc];
#pragma unroll
        for (int ic = 0; ic < 3; ic++)
#pragma unroll
            for (int r = 0; r < 3; r++)
#pragma unroll
                for (int kx = 0; kx < 3; kx++)
                    acc += sin_[ic][r][xx + kx] * sw[(oc * 3 + ic) * 9 + r * 3 + kx];
        g_feat[(((size_t)b * CCH + oc) * HH + y) * WW + xx] = acc;
    }
}

// ---------------- K/V projection + LN(K), all blocks, L-split ----------------
__global__ void __launch_bounds__(256) k_kvall(
        const float* __restrict__ kw, const float* __restrict__ kb,
        const float* __restrict__ vw, const float* __restrict__ vb,
        const float* __restrict__ l2w, const float* __restrict__ l2b) {
    __shared__ float tfs[LSEQ * 64];
    __shared__ float kws[64 * 68];
    __shared__ float vws[64 * 68];
    __shared__ float ksm[4 * 64];
    int blk = blockIdx.x, b = blockIdx.y, z = blockIdx.z;
    int tid = threadIdx.x;
    for (int i = tid; i < LSEQ * 64; i += 256) tfs[i] = g_tf[b * LSEQ * 64 + i];
    for (int idx = tid; idx < 4096; idx += 256) {
        int o = idx >> 6, c = idx & 63;
        kws[c * 68 + o] = kw[blk * 4096 + idx];
        vws[c * 68 + o] = vw[blk * 4096 + idx];
    }
    __syncthreads();
    int o = tid & 63, rr = tid >> 6;
    float kbv = kb[blk * 64 + o], vbv = vb[blk * 64 + o];
    float lwv = l2w[blk * 64 + o], lbv = l2b[blk * 64 + o];
    size_t base = ((size_t)(blk * BATCH + b)) * LSEQ * 64;
    int rbeg = z * 40, rend = rbeg + 40;
    for (int r0 = rbeg; r0 < rend; r0 += 4) {
        int r = r0 + rr;
        bool act = r < LSEQ;
        float ka = kbv, va = vbv;
        if (act) {
#pragma unroll 8
            for (int c = 0; c < 64; c++) {
                float t = tfs[r * 64 + c];
                ka += t * kws[c * 68 + o];
                va += t * vws[c * 68 + o];
            }
            ksm[rr * 64 + o] = ka;
        }
        __syncthreads();
        if (act) {
            float m = 0.f;
#pragma unroll 8
            for (int i = 0; i < 64; i++) m += ksm[rr * 64 + i];
            m *= (1.f / 64.f);
            float vv = 0.f;
#pragma unroll 8
            for (int i = 0; i < 64; i++) { float d = ksm[rr * 64 + i] - m; vv += d * d; }
            vv *= (1.f / 64.f);
            float rs = rsqrtf(vv + 1e-5f);
            g_kn[base + r * 64 + o] = (ka - m) * rs * lwv + lbv;
            g_v [base + r * 64 + o] = va;
        }
        __syncthreads();
    }
}

// ---------------- FUSED attention stack, TF32 MMA for q-proj & out-proj ----------------
// sF/sQ: [x][pic(c)] stride 72. U1: Wq[o*72+pic]->K[l*64+pic]. U2: V[l*64+pic]->Wo[o*72+pic].
__global__ void __launch_bounds__(256, 3) k_attn_stack(
        const float* __restrict__ qw, const float* __restrict__ qb,
        const float* __restrict__ ow, const float* __restrict__ ob,
        const float* __restrict__ l1w, const float* __restrict__ l1b) {
    __shared__ __align__(16) float U1[LSEQ * 64];
    __shared__ __align__(16) float U2[LSEQ * 64];
    __shared__ __align__(16) float sF[64 * 72];
    __shared__ __align__(16) float sQ[64 * 72];
    __shared__ float cq[64], cw[64], cb[64], cob[64];

    int b = blockIdx.x >> 6, y = blockIdx.x & 63;
    int tid = threadIdx.x;
    int w = tid >> 5, lane = tid & 31;
    int g = lane >> 2, tig = lane & 3;
    int wm = w & 3, wn = w >> 2;
    int m0r = wm * 16 + g, m1r = m0r + 8;

    // load feat row -> sF[x][pic(c)]
    for (int idx = tid; idx < 4096; idx += 256) {
        int c = idx >> 6, xx = idx & 63;
        sF[xx * 72 + picf(c)] = g_feat[(((size_t)b * 64 + c) * 64 + y) * 64 + xx];
    }

    float pey = (float)y * (0.05f / 63.f);
    const float scale = 0.35355339059327373f;

#pragma unroll 1
    for (int blk = 0; blk < NBLK; blk++) {
        size_t kvbase = ((size_t)(blk * BATCH + b)) * LSEQ * 64;
        __syncthreads();   // prev iter done; buffers free; sF stable
        // stage Wq (tf32) -> U1, V -> U2, consts (pic order)
        for (int idx = tid; idx < 4096; idx += 256) {
            int o = idx >> 6, i = idx & 63;
            U1[o * 72 + picf(i)] = to_tf32(qw[blk * 4096 + idx]);
        }
        for (int idx = tid; idx < LSEQ * 64; idx += 256) {
            int l = idx >> 6, c = idx & 63;
            U2[l * 64 + picf(c)] = g_v[kvbase + idx];
        }
        if (tid < 64) {
            int s = picf(tid);
            cq[s]  = qb[blk * 64 + tid];
            cw[s]  = l1w[blk * 64 + tid];
            cb[s]  = l1b[blk * 64 + tid];
            cob[s] = ob[blk * 64 + tid];
        }
        __syncthreads();

        // ---- phase B: q_raw = sF @ Wq via MMA ----
        {
            float d[4][4];
#pragma unroll
            for (int nt = 0; nt < 4; nt++)
#pragma unroll
                for (int e = 0; e < 4; e++) d[nt][e] = 0.f;
#pragma unroll
            for (int ks = 0; ks < 8; ks++) {
                int po = ks * 8 + tig * 2;
                float2 alo = *(const float2*)&sF[m0r * 72 + po];
                float2 ahi = *(const float2*)&sF[m1r * 72 + po];
                uint32_t A[4] = { __float_as_uint(alo.x), __float_as_uint(ahi.x),
                                  __float_as_uint(alo.y), __float_as_uint(ahi.y) };
#pragma unroll
                for (int nt = 0; nt < 4; nt++) {
                    int n = wn * 32 + nt * 8 + g;
                    float2 bv = *(const float2*)&U1[n * 72 + po];
                    uint32_t B[2] = { __float_as_uint(bv.x), __float_as_uint(bv.y) };
                    mma_tf32(d[nt], A, B);
                }
            }
            // store q_raw + bias to sQ (pic slots)
#pragma unroll
            for (int nt = 0; nt < 4; nt++) {
                int c0 = wn * 32 + nt * 8 + tig * 2;
                int s0 = picf(c0), s1 = picf(c0 + 1);
                sQ[m0r * 72 + s0] = d[nt][0] + cq[s0];
                sQ[m0r * 72 + s1] = d[nt][1] + cq[s1];
                sQ[m1r * 72 + s0] = d[nt][2] + cq[s0];
                sQ[m1r * 72 + s1] = d[nt][3] + cq[s1];
            }
        }
        __syncthreads();

        // ---- LN pass (4 lanes per position) + stage K -> U1 ----
        {
            int xx = tid >> 2, j = tid & 3;
            float v[16];
#pragma unroll
            for (int q = 0; q < 4; q++) {
                float4 t = *(const float4*)&sQ[xx * 72 + j * 16 + q * 4];
                v[q * 4 + 0] = t.x; v[q * 4 + 1] = t.y;
                v[q * 4 + 2] = t.z; v[q * 4 + 3] = t.w;
            }
            float pe = (j < 2) ? (float)xx * (0.05f / 63.f) : pey;
            float s = 0.f;
#pragma unroll
            for (int e = 0; e < 16; e++) { v[e] += pe; s += v[e]; }
            s += __shfl_xor_sync(0xffffffffu, s, 1);
            s += __shfl_xor_sync(0xffffffffu, s, 2);
            float mean = s * (1.f / 64.f);
            float sq = 0.f;
#pragma unroll
            for (int e = 0; e < 16; e++) { float dl = v[e] - mean; sq += dl * dl; }
            sq += __shfl_xor_sync(0xffffffffu, sq, 1);
            sq += __shfl_xor_sync(0xffffffffu, sq, 2);
            float rs = rsqrtf(sq * (1.f / 64.f) + 1e-5f);
#pragma unroll
            for (int q = 0; q < 4; q++) {
                int s0 = j * 16 + q * 4;
                float4 o;
                o.x = (v[q * 4 + 0] - mean) * rs * cw[s0 + 0] + cb[s0 + 0];
                o.y = (v[q * 4 + 1] - mean) * rs * cw[s0 + 1] + cb[s0 + 1];
                o.z = (v[q * 4 + 2] - mean) * rs * cw[s0 + 2] + cb[s0 + 2];
                o.w = (v[q * 4 + 3] - mean) * rs * cw[s0 + 3] + cb[s0 + 3];
                *(float4*)&sQ[xx * 72 + s0] = o;
            }
        }
        for (int idx = tid; idx < LSEQ * 64; idx += 256) {
            int l = idx >> 6, c = idx & 63;
            U1[l * 64 + picf(c)] = g_kn[kvbase + idx];
        }
        __syncthreads();

        // ---- phase C: attention (scalar, pic slot space) ----
        {
            int hp = tid & 3, pl = tid >> 2;
            int cs = hp * 16;
            const float4* qp = (const float4*)&sQ[pl * 72 + cs];
            float4 qa0 = qp[0], qa1 = qp[1], qb0 = qp[2], qb1 = qp[3];
            __syncthreads();   // q in regs before ao overwrites sQ
            float denA = 0.f, denB = 0.f;
            float4 a0 = make_float4(0, 0, 0, 0), a1 = a0, b0 = a0, b1 = a0;
#pragma unroll 2
            for (int l = 0; l < LSEQ; l++) {
                const float4* kp = (const float4*)&U1[l * 64 + cs];
                float4 k0 = kp[0], k1 = kp[1], k2 = kp[2], k3 = kp[3];
                float tA0 = qa0.x * k0.x + qa0.y * k0.y;
                float tA1 = qa0.z * k0.z + qa0.w * k0.w;
                float tA2 = qa1.x * k1.x + qa1.y * k1.y;
                float tA3 = qa1.z * k1.z + qa1.w * k1.w;
                float tB0 = qb0.x * k2.x + qb0.y * k2.y;
                float tB1 = qb0.z * k2.z + qb0.w * k2.w;
                float tB2 = qb1.x * k3.x + qb1.y * k3.y;
                float tB3 = qb1.z * k3.z + qb1.w * k3.w;
                float lgA = (tA0 + tA1) + (tA2 + tA3);
                float lgB = (tB0 + tB1) + (tB2 + tB3);
                float eA = __expf(lgA * scale);
                float eB = __expf(lgB * scale);
                denA += eA; denB += eB;
                const float4* vp = (const float4*)&U2[l * 64 + cs];
                float4 v0 = vp[0], v1 = vp[1], v2 = vp[2], v3 = vp[3];
                a0.x += eA * v0.x; a0.y += eA * v0.y; a0.z += eA * v0.z; a0.w += eA * v0.w;
                a1.x += eA * v1.x; a1.y += eA * v1.y; a1.z += eA * v1.z; a1.w += eA * v1.w;
                b0.x += eB * v2.x; b0.y += eB * v2.y; b0.z += eB * v2.z; b0.w += eB * v2.w;
                b1.x += eB * v3.x; b1.y += eB * v3.y; b1.z += eB * v3.z; b1.w += eB * v3.w;
            }
            float iA = 1.f / denA, iB = 1.f / denB;
            float4* op = (float4*)&sQ[pl * 72 + cs];
            op[0] = make_float4(a0.x * iA, a0.y * iA, a0.z * iA, a0.w * iA);
            op[1] = make_float4(a1.x * iA, a1.y * iA, a1.z * iA, a1.w * iA);
            op[2] = make_float4(b0.x * iB, b0.y * iB, b0.z * iB, b0.w * iB);
            op[3] = make_float4(b1.x * iB, b1.y * iB, b1.z * iB, b1.w * iB);
        }
        __syncthreads();
        // stage Wo (tf32) -> U2
        for (int idx = tid; idx < 4096; idx += 256) {
            int o = idx >> 6, i = idx & 63;
            U2[o * 72 + picf(i)] = to_tf32(ow[blk * 4096 + idx]);
        }
        __syncthreads();

        // ---- phase E: out-proj via MMA + residual into sF ----
        {
            float d[4][4];
#pragma unroll
            for (int nt = 0; nt < 4; nt++)
#pragma unroll
                for (int e = 0; e < 4; e++) d[nt][e] = 0.f;
#pragma unroll
            for (int ks = 0; ks < 8; ks++) {
                int po = ks * 8 + tig * 2;
                float2 alo = *(const float2*)&sQ[m0r * 72 + po];
                float2 ahi = *(const float2*)&sQ[m1r * 72 + po];
                uint32_t A[4] = { __float_as_uint(alo.x), __float_as_uint(ahi.x),
                                  __float_as_uint(alo.y), __float_as_uint(ahi.y) };
#pragma unroll
                for (int nt = 0; nt < 4; nt++) {
                    int n = wn * 32 + nt * 8 + g;
                    float2 bv = *(const float2*)&U2[n * 72 + po];
                    uint32_t B[2] = { __float_as_uint(bv.x), __float_as_uint(bv.y) };
                    mma_tf32(d[nt], A, B);
                }
            }
#pragma unroll
            for (int nt = 0; nt < 4; nt++) {
                int c0 = wn * 32 + nt * 8 + tig * 2;
                int s0 = picf(c0), s1 = picf(c0 + 1);
                sF[m0r * 72 + s0] += d[nt][0] + cob[s0];
                sF[m0r * 72 + s1] += d[nt][1] + cob[s1];
                sF[m1r * 72 + s0] += d[nt][2] + cob[s0];
                sF[m1r * 72 + s1] += d[nt][3] + cob[s1];
            }
        }
    }
    __syncthreads();
    // write final feat row back (depermute)
    for (int idx = tid; idx < 4096; idx += 256) {
        int c = idx >> 6, xx = idx & 63;
        g_feat[(((size_t)b * 64 + c) * 64 + y) * 64 + xx] = sF[xx * 72 + picf(c)];
    }
}

// ---------------- TF32 tensor-core up-conv + pixel-shuffle + relu ----------------
__global__ void __launch_bounds__(256, 3) k_upconv_tc(int lvl, int IH, int IW,
                                                      const float* __restrict__ up_b) {
    const float* in   = lvl ? g_u1 : g_feat;
    float*       outp = lvl ? g_u2 : g_u1;
    __shared__ float sA[180 * 72];
    __shared__ float sBT[64 * 72];
    int x0 = blockIdx.x * 16, y0 = blockIdx.y * 8;
    int bz = blockIdx.z; int b = bz >> 2, ocg = bz & 3;
    int tid = threadIdx.x;
    int w = tid >> 5, lane = tid & 31;
    int g = lane >> 2, tig = lane & 3;
    int wm = w & 3, wn = w >> 2;

    for (int idx = tid; idx < 180 * 64; idx += 256) {
        int ic = idx / 180; int sp = idx % 180;
        int r = sp / 18, c = sp % 18;
        int gy = y0 - 1 + r, gx = x0 - 1 + c;
        float v = 0.f;
        if (gy >= 0 && gy < IH && gx >= 0 && gx < IW)
            v = in[(((size_t)b * 64 + ic) * IH + gy) * IW + gx];
        sA[sp * 72 + picf(ic)] = to_tf32(v);
    }

    float d[2][4][4];
#pragma unroll
    for (int nt = 0; nt < 4; nt++) {
        int oc = ocg * 64 + wn * 32 + nt * 8 + tig * 2;
        float b0v = up_b[lvl * 256 + oc];
        float b1v = up_b[lvl * 256 + oc + 1];
#pragma unroll
        for (int mt = 0; mt < 2; mt++) {
            d[mt][nt][0] = b0v; d[mt][nt][1] = b1v;
            d[mt][nt][2] = b0v; d[mt][nt][3] = b1v;
        }
    }

#pragma unroll 1
    for (int t = 0; t < 9; t++) {
        int ky = t / 3, kx = t % 3;
        __syncthreads();
        for (int idx = tid; idx < 4096; idx += 256) {
            int ic = idx & 63, oc = idx >> 6;
            sBT[oc * 72 + picf(ic)] =
                g_wupT[((((lvl * 9 + t) * 4 + ocg) * 64 + oc) * 64) + ic];
        }
        __syncthreads();
        int sp_base[2][2];
#pragma unroll
        for (int mt = 0; mt < 2; mt++) {
            int m_lo = wm * 32 + mt * 16 + g;
            int m_hi = m_lo + 8;
            sp_base[mt][0] = ((m_lo >> 4) + ky) * 18 + (m_lo & 15) + kx;
            sp_base[mt][1] = ((m_hi >> 4) + ky) * 18 + (m_hi & 15) + kx;
        }
#pragma unroll
        for (int ks = 0; ks < 8; ks++) {
            int po = ks * 8 + tig * 2;
            uint32_t A[2][4];
#pragma unroll
            for (int mt = 0; mt < 2; mt++) {
                float2 lo = *(const float2*)&sA[sp_base[mt][0] * 72 + po];
                float2 hi = *(const float2*)&sA[sp_base[mt][1] * 72 + po];
                A[mt][0] = __float_as_uint(lo.x);
                A[mt][1] = __float_as_uint(hi.x);
                A[mt][2] = __float_as_uint(lo.y);
                A[mt][3] = __float_as_uint(hi.y);
            }
            uint32_t Bf[4][2];
#pragma unroll
            for (int nt = 0; nt < 4; nt++) {
                int nc = wn * 32 + nt * 8 + g;
                float2 bv = *(const float2*)&sBT[nc * 72 + po];
                Bf[nt][0] = __float_as_uint(bv.x);
                Bf[nt][1] = __float_as_uint(bv.y);
            }
#pragma unroll
            for (int mt = 0; mt < 2; mt++)
#pragma unroll
                for (int nt = 0; nt < 4; nt++)
                    mma_tf32(d[mt][nt], A[mt], Bf[nt]);
        }
    }

    int OW = IW * 2;
#pragma unroll
    for (int mt = 0; mt < 2; mt++) {
#pragma unroll
        for (int half = 0; half < 2; half++) {
            int m = wm * 32 + mt * 16 + g + half * 8;
            int gy = y0 + (m >> 4), gx = x0 + (m & 15);
#pragma unroll
            for (int nt = 0; nt < 4; nt++) {
                int oc4a = ocg * 64 + wn * 32 + nt * 8 + tig * 2;
                float v0 = d[mt][nt][half * 2 + 0];
                float v1 = d[mt][nt][half * 2 + 1];
                int ca = oc4a >> 2, r1a = (oc4a >> 1) & 1, r2a = oc4a & 1;
                int oc4b = oc4a + 1;
                int cb = oc4b >> 2, r1b = (oc4b >> 1) & 1, r2b = oc4b & 1;
                outp[(((size_t)b * 64 + ca) * (size_t)(IH * 2) + (size_t)(2 * gy + r1a)) * (size_t)OW
                     + 2 * gx + r2a] = fmaxf(v0, 0.f);
                outp[(((size_t)b * 64 + cb) * (size_t)(IH * 2) + (size_t)(2 * gy + r1b)) * (size_t)OW
                     + 2 * gx + r2b] = fmaxf(v1, 0.f);
            }
        }
    }
}

// ---------------- final conv 64->3 at 256x256 ----------------
__global__ void __launch_bounds__(256) k_cl(const float* __restrict__ w,
                                            const float* __restrict__ bias,
                                            float* __restrict__ out) {
    __shared__ float sw[3 * 64 * 9];
    __shared__ float sin_[4][10][132];
    int xbase = blockIdx.x * 128;
    int y0 = blockIdx.y * 8;
    int b = blockIdx.z;
    int tid = threadIdx.x;
    int xg = tid & 31; int yr = tid >> 5;
    int x0 = xg * 4;
    for (int i = tid; i < 1728; i += 256) sw[i] = w[i];
    float acc[3][4];
#pragma unroll
    for (int oc = 0; oc < 3; oc++) {
        float bb = bias[oc];
#pragma unroll
        for (int xi = 0; xi < 4; xi++) acc[oc][xi] = bb;
    }
    for (int ic0 = 0; ic0 < 64; ic0 += 4) {
        __syncthreads();
        for (int idx = tid; idx < 4 * 10 * 130; idx += 256) {
            int c = idx % 130; int r = (idx / 130) % 10; int icc = idx / 1300;
            int gy = y0 - 1 + r, gx = xbase - 1 + c;
            float v = 0.f;
            if (gy >= 0 && gy < 256 && gx >= 0 && gx < 256)
                v = g_u2[(((size_t)b * 64 + ic0 + icc) * 256 + gy) * 256 + gx];
            sin_[icc][r][c] = v;
        }
        __syncthreads();
        for (int icc = 0; icc < 4; icc++) {
#pragma unroll
            for (int ky = 0; ky < 3; ky++) {
                float in6[6];
#pragma unroll
                for (int t = 0; t < 6; t++) in6[t] = sin_[icc][yr + ky][x0 + t];
#pragma unroll
                for (int kx = 0; kx < 3; kx++) {
#pragma unroll
                    for (int oc = 0; oc < 3; oc++) {
                        float wv = sw[(oc * 64 + ic0 + icc) * 9 + ky * 3 + kx];
#pragma unroll
                        for (int xi = 0; xi < 4; xi++)
                            acc[oc][xi] += wv * in6[kx + xi];
                    }
                }
            }
        }
    }
    int gy = y0 + yr, gx0 = xbase + x0;
#pragma unroll
    for (int oc = 0; oc < 3; oc++) {
        float4 v = make_float4(acc[oc][0], acc[oc][1], acc[oc][2], acc[oc][3]);
        *(float4*)&out[(((size_t)b * 3 + oc) * 256 + gy) * 256 + gx0] = v;
    }
}

// ---------------- launcher ----------------
extern "C" void kernel_launch(void* const* d_in, const int* in_sizes, int n_in,
                              void* d_out, int out_size) {
    const float* x      = (const float*)d_in[0];
    const float* th     = (const float*)d_in[1];
    const float* proj_w = (const float*)d_in[2];
    const float* proj_b = (const float*)d_in[3];
    const float* cf_w   = (const float*)d_in[4];
    const float* cf_b   = (const float*)d_in[5];
    const float* qw     = (const float*)d_in[6];
    const float* qb     = (const float*)d_in[7];
    const float* kw     = (const float*)d_in[8];
    const float* kb     = (const float*)d_in[9];
    const float* vw     = (const float*)d_in[10];
    const float* vb     = (const float*)d_in[11];
    const float* ow     = (const float*)d_in[12];
    const float* ob     = (const float*)d_in[13];
    const float* l1w    = (const float*)d_in[14];
    const float* l1b    = (const float*)d_in[15];
    const float* l2w    = (const float*)d_in[16];
    const float* l2b    = (const float*)d_in[17];
    const float* up_w   = (const float*)d_in[18];
    const float* up_b   = (const float*)d_in[19];
    const float* cl_w   = (const float*)d_in[20];
    const float* cl_b   = (const float*)d_in[21];
    float* out = (float*)d_out;

    k_textproj<<<BATCH * LSEQ, 64>>>(th, proj_w, proj_b, up_w);
    k_convin<<<BATCH * HH, 64>>>(x, cf_w, cf_b);
    k_kvall<<<dim3(NBLK, BATCH, 2), 256>>>(kw, kb, vw, vb, l2w, l2b);
    k_attn_stack<<<BATCH * HH, 256>>>(qw, qb, ow, ob, l1w, l1b);
    k_upconv_tc<<<dim3(4, 8, BATCH * 4), 256>>>(0, 64, 64, up_b);
    k_upconv_tc<<<dim3(8, 16, BATCH * 4), 256>>>(1, 128, 128, up_b);
    k_cl<<<dim3(2, 32, BATCH), 256>>>(cl_w, cl_b, out);

    (void)in_sizes; (void)n_in; (void)out_size;
}

// round 9
// speedup vs baseline: 1.0157x; 1.0157x over previous
#include <cuda_runtime.h>
#include <cuda_bf16.h>
#include <cstdint>

// ---------------- problem constants ----------------
#define BATCH 8
#define CCH   64
#define HH    64
#define WW    64
#define NPOS  4096
#define LSEQ  77
#define DTXT  512
#define NBLK  16
#define NHEAD 8
#define HDIM  8

// ---------------- device scratch ----------------
__device__ float g_tf  [BATCH*LSEQ*CCH];
__device__ float g_kn  [NBLK*BATCH*LSEQ*CCH];
__device__ float g_v   [NBLK*BATCH*LSEQ*CCH];
__device__ float g_feat[BATCH*CCH*HH*WW];
__device__ float g_u1  [BATCH*CCH*128*128];
__device__ float g_u2  [(size_t)BATCH*CCH*256*256];
__device__ float g_wupT[2*9*4*64*64];   // [lvl][tap][ocg][oc(64)][ic(64)], tf32

__device__ __forceinline__ float to_tf32(float x) {
    float r; asm("cvt.rna.tf32.f32 %0, %1;" : "=f"(r) : "f"(x)); return r;
}
__device__ __forceinline__ void mma_tf32(float* d, const uint32_t* a, const uint32_t* b) {
    asm volatile(
        "mma.sync.aligned.m16n8k8.row.col.f32.tf32.tf32.f32 "
        "{%0,%1,%2,%3}, {%4,%5,%6,%7}, {%8,%9}, {%0,%1,%2,%3};"
        : "+f"(d[0]), "+f"(d[1]), "+f"(d[2]), "+f"(d[3])
        : "r"(a[0]), "r"(a[1]), "r"(a[2]), "r"(a[3]), "r"(b[0]), "r"(b[1]));
}
// permuted channel index: ic = ks*8 + tig + 4h  ->  pic = ks*8 + tig*2 + h
__device__ __forceinline__ int picf(int ic) {
    int r = ic & 7;
    return (ic & ~7) + ((r & 3) * 2) + (r >> 2);
}

// ---------------- text projection (+ fused tf32 up-weight transpose) ----------------
__global__ void k_textproj(const float* __restrict__ th,
                           const float* __restrict__ pw,
                           const float* __restrict__ pb,
                           const float* __restrict__ upw) {
    __shared__ float s[DTXT];
    int bl = blockIdx.x;
    const float* row = th + (size_t)bl * DTXT;
    for (int i = threadIdx.x; i < DTXT; i += 64) s[i] = row[i];
    __syncthreads();
    int c = threadIdx.x;
    const float* w = pw + (size_t)c * DTXT;
    float acc = pb[c];
#pragma unroll 8
    for (int d = 0; d < DTXT; ++d) acc += s[d] * w[d];
    g_tf[bl * CCH + c] = acc;
    for (int idx = blockIdx.x * 64 + threadIdx.x; idx < 2 * 256 * 64 * 9;
         idx += gridDim.x * 64) {
        int k = idx % 9;
        int t = idx / 9;
        int ic = t % 64; t /= 64;
        int oc4 = t % 256;
        int lvl = t / 256;
        g_wupT[((((lvl * 9 + k) * 4 + (oc4 >> 6)) * 64 + (oc4 & 63)) * 64) + ic]
            = to_tf32(upw[idx]);
    }
}

// ---------------- input conv 3->64, 3x3 ----------------
__global__ void k_convin(const float* __restrict__ x,
                         const float* __restrict__ w,
                         const float* __restrict__ bias) {
    __shared__ float sw[64 * 27];
    __shared__ float sb[64];
    __shared__ float sin_[3][3][66];
    int bid = blockIdx.x; int b = bid >> 6; int y = bid & 63;
    int tid = threadIdx.x;
    for (int i = tid; i < 64 * 27; i += 64) sw[i] = w[i];
    sb[tid] = bias[tid];
    for (int ic = 0; ic < 3; ic++)
        for (int r = 0; r < 3; r++) {
            int yy = y + r - 1;
            float v = 0.f;
            if (yy >= 0 && yy < HH) v = x[(((size_t)b * 3 + ic) * HH + yy) * WW + tid];
            sin_[ic][r][tid + 1] = v;
            if (tid == 0) { sin_[ic][r][0] = 0.f; sin_[ic][r][65] = 0.f; }
        }
    __syncthreads();
    int xx = tid;
    for (int oc = 0; oc < 64; oc++) {
        float acc = sb[oc];
#pragma unroll
        for (int ic = 0; ic < 3; ic++)
#pragma unroll
            for (int r = 0; r < 3; r++)
#pragma unroll
                for (int kx = 0; kx < 3; kx++)
                    acc += sin_[ic][r][xx + kx] * sw[(oc * 3 + ic) * 9 + r * 3 + kx];
        g_feat[(((size_t)b * CCH + oc) * HH + y) * WW + xx] = acc;
    }
}

// ---------------- K/V projection + LN(K), all blocks, L-split ----------------
__global__ void __launch_bounds__(256) k_kvall(
        const float* __restrict__ kw, const float* __restrict__ kb,
        const float* __restrict__ vw, const float* __restrict__ vb,
        const float* __restrict__ l2w, const float* __restrict__ l2b) {
    __shared__ float tfs[LSEQ * 64];
    __shared__ float kws[64 * 68];
    __shared__ float vws[64 * 68];
    __shared__ float ksm[4 * 64];
    int blk = blockIdx.x, b = blockIdx.y, z = blockIdx.z;
    int tid = threadIdx.x;
    for (int i = tid; i < LSEQ * 64; i += 256) tfs[i] = g_tf[b * LSEQ * 64 + i];
    for (int idx = tid; idx < 4096; idx += 256) {
        int o = idx >> 6, c = idx & 63;
        kws[c * 68 + o] = kw[blk * 4096 + idx];
        vws[c * 68 + o] = vw[blk * 4096 + idx];
    }
    __syncthreads();
    int o = tid & 63, rr = tid >> 6;
    float kbv = kb[blk * 64 + o], vbv = vb[blk * 64 + o];
    float lwv = l2w[blk * 64 + o], lbv = l2b[blk * 64 + o];
    size_t base = ((size_t)(blk * BATCH + b)) * LSEQ * 64;
    int rbeg = z * 40, rend = rbeg + 40;
    for (int r0 = rbeg; r0 < rend; r0 += 4) {
        int r = r0 + rr;
        bool act = r < LSEQ;
        float ka = kbv, va = vbv;
        if (act) {
#pragma unroll 8
            for (int c = 0; c < 64; c++) {
                float t = tfs[r * 64 + c];
                ka += t * kws[c * 68 + o];
                va += t * vws[c * 68 + o];
            }
            ksm[rr * 64 + o] = ka;
        }
        __syncthreads();
        if (act) {
            float m = 0.f;
#pragma unroll 8
            for (int i = 0; i < 64; i++) m += ksm[rr * 64 + i];
            m *= (1.f / 64.f);
            float vv = 0.f;
#pragma unroll 8
            for (int i = 0; i < 64; i++) { float d = ksm[rr * 64 + i] - m; vv += d * d; }
            vv *= (1.f / 64.f);
            float rs = rsqrtf(vv + 1e-5f);
            g_kn[base + r * 64 + o] = (ka - m) * rs * lwv + lbv;
            g_v [base + r * 64 + o] = va;
        }
        __syncthreads();
    }
}

// ---------------- FUSED attention stack, TF32 MMA, consts stashed in sF tails ----------------
// sF/sQ: [x][pic(c)] stride 72; slots 64..67 of sF rows hold qb/l1w/l1b/ob for the
// current block (written at iter start). Total smem 74.5KB -> 3 CTAs/SM.
__global__ void __launch_bounds__(256, 3) k_attn_stack(
        const float* __restrict__ qw, const float* __restrict__ qb,
        const float* __restrict__ ow, const float* __restrict__ ob,
        const float* __restrict__ l1w, const float* __restrict__ l1b) {
    __shared__ __align__(16) float U1[LSEQ * 64];
    __shared__ __align__(16) float U2[LSEQ * 64];
    __shared__ __align__(16) float sF[64 * 72];
    __shared__ __align__(16) float sQ[64 * 72];

    int b = blockIdx.x >> 6, y = blockIdx.x & 63;
    int tid = threadIdx.x;
    int w = tid >> 5, lane = tid & 31;
    int g = lane >> 2, tig = lane & 3;
    int wm = w & 3, wn = w >> 2;
    int m0r = wm * 16 + g, m1r = m0r + 8;

    // load feat row -> sF[x][pic(c)]
    for (int idx = tid; idx < 4096; idx += 256) {
        int c = idx >> 6, xx = idx & 63;
        sF[xx * 72 + picf(c)] = g_feat[(((size_t)b * 64 + c) * 64 + y) * 64 + xx];
    }

    float pey = (float)y * (0.05f / 63.f);
    const float scale = 0.35355339059327373f;

#pragma unroll 1
    for (int blk = 0; blk < NBLK; blk++) {
        size_t kvbase = ((size_t)(blk * BATCH + b)) * LSEQ * 64;
        __syncthreads();   // prev iter fully done (incl. phase E const reads)
        // stage Wq (tf32) -> U1, V -> U2, consts -> sF row tails (pic order)
        for (int idx = tid; idx < 4096; idx += 256) {
            int o = idx >> 6, i = idx & 63;
            U1[o * 72 + picf(i)] = to_tf32(qw[blk * 4096 + idx]);
        }
        for (int idx = tid; idx < LSEQ * 64; idx += 256) {
            int l = idx >> 6, c = idx & 63;
            U2[l * 64 + picf(c)] = g_v[kvbase + idx];
        }
        if (tid < 64) {
            int s = picf(tid);
            sF[s * 72 + 64] = qb[blk * 64 + tid];
            sF[s * 72 + 65] = l1w[blk * 64 + tid];
            sF[s * 72 + 66] = l1b[blk * 64 + tid];
            sF[s * 72 + 67] = ob[blk * 64 + tid];
        }
        __syncthreads();

        // ---- phase B: q_raw = sF @ Wq via MMA ----
        {
            float d[4][4];
#pragma unroll
            for (int nt = 0; nt < 4; nt++)
#pragma unroll
                for (int e = 0; e < 4; e++) d[nt][e] = 0.f;
#pragma unroll
            for (int ks = 0; ks < 8; ks++) {
                int po = ks * 8 + tig * 2;
                float2 alo = *(const float2*)&sF[m0r * 72 + po];
                float2 ahi = *(const float2*)&sF[m1r * 72 + po];
                uint32_t A[4] = { __float_as_uint(alo.x), __float_as_uint(ahi.x),
                                  __float_as_uint(alo.y), __float_as_uint(ahi.y) };
#pragma unroll
                for (int nt = 0; nt < 4; nt++) {
                    int n = wn * 32 + nt * 8 + g;
                    float2 bv = *(const float2*)&U1[n * 72 + po];
                    uint32_t B[2] = { __float_as_uint(bv.x), __float_as_uint(bv.y) };
                    mma_tf32(d[nt], A, B);
                }
            }
#pragma unroll
            for (int nt = 0; nt < 4; nt++) {
                int c0 = wn * 32 + nt * 8 + tig * 2;
                int s0 = picf(c0), s1 = picf(c0 + 1);
                float q0 = sF[s0 * 72 + 64], q1 = sF[s1 * 72 + 64];
                sQ[m0r * 72 + s0] = d[nt][0] + q0;
                sQ[m0r * 72 + s1] = d[nt][1] + q1;
                sQ[m1r * 72 + s0] = d[nt][2] + q0;
                sQ[m1r * 72 + s1] = d[nt][3] + q1;
            }
        }
        __syncthreads();

        // ---- LN pass (4 lanes per position) + stage K -> U1 ----
        {
            int xx = tid >> 2, j = tid & 3;
            float v[16];
#pragma unroll
            for (int q = 0; q < 4; q++) {
                float4 t = *(const float4*)&sQ[xx * 72 + j * 16 + q * 4];
                v[q * 4 + 0] = t.x; v[q * 4 + 1] = t.y;
                v[q * 4 + 2] = t.z; v[q * 4 + 3] = t.w;
            }
            float pe = (j < 2) ? (float)xx * (0.05f / 63.f) : pey;
            float s = 0.f;
#pragma unroll
            for (int e = 0; e < 16; e++) { v[e] += pe; s += v[e]; }
            s += __shfl_xor_sync(0xffffffffu, s, 1);
            s += __shfl_xor_sync(0xffffffffu, s, 2);
            float mean = s * (1.f / 64.f);
            float sq = 0.f;
#pragma unroll
            for (int e = 0; e < 16; e++) { float dl = v[e] - mean; sq += dl * dl; }
            sq += __shfl_xor_sync(0xffffffffu, sq, 1);
            sq += __shfl_xor_sync(0xffffffffu, sq, 2);
            float rs = rsqrtf(sq * (1.f / 64.f) + 1e-5f);
#pragma unroll
            for (int q = 0; q < 4; q++) {
                int s0 = j * 16 + q * 4;
                float4 o;
                o.x = (v[q * 4 + 0] - mean) * rs * sF[(s0 + 0) * 72 + 65] + sF[(s0 + 0) * 72 + 66];
                o.y = (v[q * 4 + 1] - mean) * rs * sF[(s0 + 1) * 72 + 65] + sF[(s0 + 1) * 72 + 66];
                o.z = (v[q * 4 + 2] - mean) * rs * sF[(s0 + 2) * 72 + 65] + sF[(s0 + 2) * 72 + 66];
                o.w = (v[q * 4 + 3] - mean) * rs * sF[(s0 + 3) * 72 + 65] + sF[(s0 + 3) * 72 + 66];
                *(float4*)&sQ[xx * 72 + s0] = o;
            }
        }
        for (int idx = tid; idx < LSEQ * 64; idx += 256) {
            int l = idx >> 6, c = idx & 63;
            U1[l * 64 + picf(c)] = g_kn[kvbase + idx];
        }
        __syncthreads();

        // ---- phase C: attention (scalar, pic slot space) ----
        {
            int hp = tid & 3, pl = tid >> 2;
            int cs = hp * 16;
            const float4* qp = (const float4*)&sQ[pl * 72 + cs];
            float4 qa0 = qp[0], qa1 = qp[1], qb0 = qp[2], qb1 = qp[3];
            __syncthreads();   // q in regs before ao overwrites sQ
            float denA = 0.f, denB = 0.f;
            float4 a0 = make_float4(0, 0, 0, 0), a1 = a0, b0 = a0, b1 = a0;
#pragma unroll 2
            for (int l = 0; l < LSEQ; l++) {
                const float4* kp = (const float4*)&U1[l * 64 + cs];
                float4 k0 = kp[0], k1 = kp[1], k2 = kp[2], k3 = kp[3];
                float tA0 = qa0.x * k0.x + qa0.y * k0.y;
                float tA1 = qa0.z * k0.z + qa0.w * k0.w;
                float tA2 = qa1.x * k1.x + qa1.y * k1.y;
                float tA3 = qa1.z * k1.z + qa1.w * k1.w;
                float tB0 = qb0.x * k2.x + qb0.y * k2.y;
                float tB1 = qb0.z * k2.z + qb0.w * k2.w;
                float tB2 = qb1.x * k3.x + qb1.y * k3.y;
                float tB3 = qb1.z * k3.z + qb1.w * k3.w;
                float lgA = (tA0 + tA1) + (tA2 + tA3);
                float lgB = (tB0 + tB1) + (tB2 + tB3);
                float eA = __expf(lgA * scale);
                float eB = __expf(lgB * scale);
                denA += eA; denB += eB;
                const float4* vp = (const float4*)&U2[l * 64 + cs];
                float4 v0 = vp[0], v1 = vp[1], v2 = vp[2], v3 = vp[3];
                a0.x += eA * v0.x; a0.y += eA * v0.y; a0.z += eA * v0.z; a0.w += eA * v0.w;
                a1.x += eA * v1.x; a1.y += eA * v1.y; a1.z += eA * v1.z; a1.w += eA * v1.w;
                b0.x += eB * v2.x; b0.y += eB * v2.y; b0.z += eB * v2.z; b0.w += eB * v2.w;
                b1.x += eB * v3.x; b1.y += eB * v3.y; b1.z += eB * v3.z; b1.w += eB * v3.w;
            }
            float iA = 1.f / denA, iB = 1.f / denB;
            float4* op = (float4*)&sQ[pl * 72 + cs];
            op[0] = make_float4(a0.x * iA, a0.y * iA, a0.z * iA, a0.w * iA);
            op[1] = make_float4(a1.x * iA, a1.y * iA, a1.z * iA, a1.w * iA);
            op[2] = make_float4(b0.x * iB, b0.y * iB, b0.z * iB, b0.w * iB);
            op[3] = make_float4(b1.x * iB, b1.y * iB, b1.z * iB, b1.w * iB);
        }
        __syncthreads();
        // stage Wo (tf32) -> U2
        for (int idx = tid; idx < 4096; idx += 256) {
            int o = idx >> 6, i = idx & 63;
            U2[o * 72 + picf(i)] = to_tf32(ow[blk * 4096 + idx]);
        }
        __syncthreads();

        // ---- phase E: out-proj via MMA + residual into sF ----
        {
            float d[4][4];
#pragma unroll
            for (int nt = 0; nt < 4; nt++)
#pragma unroll
                for (int e = 0; e < 4; e++) d[nt][e] = 0.f;
#pragma unroll
            for (int ks = 0; ks < 8; ks++) {
                int po = ks * 8 + tig * 2;
                float2 alo = *(const float2*)&sQ[m0r * 72 + po];
                float2 ahi = *(const float2*)&sQ[m1r * 72 + po];
                uint32_t A[4] = { __float_as_uint(alo.x), __float_as_uint(ahi.x),
                                  __float_as_uint(alo.y), __float_as_uint(ahi.y) };
#pragma unroll
                for (int nt = 0; nt < 4; nt++) {
                    int n = wn * 32 + nt * 8 + g;
                    float2 bv = *(const float2*)&U2[n * 72 + po];
                    uint32_t B[2] = { __float_as_uint(bv.x), __float_as_uint(bv.y) };
                    mma_tf32(d[nt], A, B);
                }
            }
#pragma unroll
            for (int nt = 0; nt < 4; nt++) {
                int c0 = wn * 32 + nt * 8 + tig * 2;
                int s0 = picf(c0), s1 = picf(c0 + 1);
                float o0 = sF[s0 * 72 + 67], o1 = sF[s1 * 72 + 67];
                sF[m0r * 72 + s0] += d[nt][0] + o0;
                sF[m0r * 72 + s1] += d[nt][1] + o1;
                sF[m1r * 72 + s0] += d[nt][2] + o0;
                sF[m1r * 72 + s1] += d[nt][3] + o1;
            }
        }
    }
    __syncthreads();
    // write final feat row back (depermute)
    for (int idx = tid; idx < 4096; idx += 256) {
        int c = idx >> 6, xx = idx & 63;
        g_feat[(((size_t)b * 64 + c) * 64 + y) * 64 + xx] = sF[xx * 72 + picf(c)];
    }
}

// ---------------- TF32 tensor-core up-conv + pixel-shuffle + relu ----------------
__global__ void __launch_bounds__(256, 3) k_upconv_tc(int lvl, int IH, int IW,
                                                      const float* __restrict__ up_b) {
    const float* in   = lvl ? g_u1 : g_feat;
    float*       outp = lvl ? g_u2 : g_u1;
    __shared__ float sA[180 * 72];
    __shared__ float sBT[64 * 72];
    int x0 = blockIdx.x * 16, y0 = blockIdx.y * 8;
    int bz = blockIdx.z; int b = bz >> 2, ocg = bz & 3;
    int tid = threadIdx.x;
    int w = tid >> 5, lane = tid & 31;
    int g = lane >> 2, tig = lane & 3;
    int wm = w & 3, wn = w >> 2;

    for (int idx = tid; idx < 180 * 64; idx += 256) {
        int ic = idx / 180; int sp = idx % 180;
        int r = sp / 18, c = sp % 18;
        int gy = y0 - 1 + r, gx = x0 - 1 + c;
        float v = 0.f;
        if (gy >= 0 && gy < IH && gx >= 0 && gx < IW)
            v = in[(((size_t)b * 64 + ic) * IH + gy) * IW + gx];
        sA[sp * 72 + picf(ic)] = to_tf32(v);
    }

    float d[2][4][4];
#pragma unroll
    for (int nt = 0; nt < 4; nt++) {
        int oc = ocg * 64 + wn * 32 + nt * 8 + tig * 2;
        float b0v = up_b[lvl * 256 + oc];
        float b1v = up_b[lvl * 256 + oc + 1];
#pragma unroll
        for (int mt = 0; mt < 2; mt++) {
            d[mt][nt][0] = b0v; d[mt][nt][1] = b1v;
            d[mt][nt][2] = b0v; d[mt][nt][3] = b1v;
        }
    }

#pragma unroll 1
    for (int t = 0; t < 9; t++) {
        int ky = t / 3, kx = t % 3;
        __syncthreads();
        for (int idx = tid; idx < 4096; idx += 256) {
            int ic = idx & 63, oc = idx >> 6;
            sBT[oc * 72 + picf(ic)] =
                g_wupT[((((lvl * 9 + t) * 4 + ocg) * 64 + oc) * 64) + ic];
        }
        __syncthreads();
        int sp_base[2][2];
#pragma unroll
        for (int mt = 0; mt < 2; mt++) {
            int m_lo = wm * 32 + mt * 16 + g;
            int m_hi = m_lo + 8;
            sp_base[mt][0] = ((m_lo >> 4) + ky) * 18 + (m_lo & 15) + kx;
            sp_base[mt][1] = ((m_hi >> 4) + ky) * 18 + (m_hi & 15) + kx;
        }
#pragma unroll
        for (int ks = 0; ks < 8; ks++) {
            int po = ks * 8 + tig * 2;
            uint32_t A[2][4];
#pragma unroll
            for (int mt = 0; mt < 2; mt++) {
                float2 lo = *(const float2*)&sA[sp_base[mt][0] * 72 + po];
                float2 hi = *(const float2*)&sA[sp_base[mt][1] * 72 + po];
                A[mt][0] = __float_as_uint(lo.x);
                A[mt][1] = __float_as_uint(hi.x);
                A[mt][2] = __float_as_uint(lo.y);
                A[mt][3] = __float_as_uint(hi.y);
            }
            uint32_t Bf[4][2];
#pragma unroll
            for (int nt = 0; nt < 4; nt++) {
                int nc = wn * 32 + nt * 8 + g;
                float2 bv = *(const float2*)&sBT[nc * 72 + po];
                Bf[nt][0] = __float_as_uint(bv.x);
                Bf[nt][1] = __float_as_uint(bv.y);
            }
#pragma unroll
            for (int mt = 0; mt < 2; mt++)
#pragma unroll
                for (int nt = 0; nt < 4; nt++)
                    mma_tf32(d[mt][nt], A[mt], Bf[nt]);
        }
    }

    int OW = IW * 2;
#pragma unroll
    for (int mt = 0; mt < 2; mt++) {
#pragma unroll
        for (int half = 0; half < 2; half++) {
            int m = wm * 32 + mt * 16 + g + half * 8;
            int gy = y0 + (m >> 4), gx = x0 + (m & 15);
#pragma unroll
            for (int nt = 0; nt < 4; nt++) {
                int oc4a = ocg * 64 + wn * 32 + nt * 8 + tig * 2;
                float v0 = d[mt][nt][half * 2 + 0];
                float v1 = d[mt][nt][half * 2 + 1];
                int ca = oc4a >> 2, r1a = (oc4a >> 1) & 1, r2a = oc4a & 1;
                int oc4b = oc4a + 1;
                int cb = oc4b >> 2, r1b = (oc4b >> 1) & 1, r2b = oc4b & 1;
                outp[(((size_t)b * 64 + ca) * (size_t)(IH * 2) + (size_t)(2 * gy + r1a)) * (size_t)OW
                     + 2 * gx + r2a] = fmaxf(v0, 0.f);
                outp[(((size_t)b * 64 + cb) * (size_t)(IH * 2) + (size_t)(2 * gy + r1b)) * (size_t)OW
                     + 2 * gx + r2b] = fmaxf(v1, 0.f);
            }
        }
    }
}

// ---------------- final conv 64->3 at 256x256 ----------------
__global__ void __launch_bounds__(256) k_cl(const float* __restrict__ w,
                                            const float* __restrict__ bias,
                                            float* __restrict__ out) {
    __shared__ float sw[3 * 64 * 9];
    __shared__ float sin_[4][10][132];
    int xbase = blockIdx.x * 128;
    int y0 = blockIdx.y * 8;
    int b = blockIdx.z;
    int tid = threadIdx.x;
    int xg = tid & 31; int yr = tid >> 5;
    int x0 = xg * 4;
    for (int i = tid; i < 1728; i += 256) sw[i] = w[i];
    float acc[3][4];
#pragma unroll
    for (int oc = 0; oc < 3; oc++) {
        float bb = bias[oc];
#pragma unroll
        for (int xi = 0; xi < 4; xi++) acc[oc][xi] = bb;
    }
    for (int ic0 = 0; ic0 < 64; ic0 += 4) {
        __syncthreads();
        for (int idx = tid; idx < 4 * 10 * 130; idx += 256) {
            int c = idx % 130; int r = (idx / 130) % 10; int icc = idx / 1300;
            int gy = y0 - 1 + r, gx = xbase - 1 + c;
            float v = 0.f;
            if (gy >= 0 && gy < 256 && gx >= 0 && gx < 256)
                v = g_u2[(((size_t)b * 64 + ic0 + icc) * 256 + gy) * 256 + gx];
            sin_[icc][r][c] = v;
        }
        __syncthreads();
        for (int icc = 0; icc < 4; icc++) {
#pragma unroll
            for (int ky = 0; ky < 3; ky++) {
                float in6[6];
#pragma unroll
                for (int t = 0; t < 6; t++) in6[t] = sin_[icc][yr + ky][x0 + t];
#pragma unroll
                for (int kx = 0; kx < 3; kx++) {
#pragma unroll
                    for (int oc = 0; oc < 3; oc++) {
                        float wv = sw[(oc * 64 + ic0 + icc) * 9 + ky * 3 + kx];
#pragma unroll
                        for (int xi = 0; xi < 4; xi++)
                            acc[oc][xi] += wv * in6[kx + xi];
                    }
                }
            }
        }
    }
    int gy = y0 + yr, gx0 = xbase + x0;
#pragma unroll
    for (int oc = 0; oc < 3; oc++) {
        float4 v = make_float4(acc[oc][0], acc[oc][1], acc[oc][2], acc[oc][3]);
        *(float4*)&out[(((size_t)b * 3 + oc) * 256 + gy) * 256 + gx0] = v;
    }
}

// ---------------- launcher ----------------
extern "C" void kernel_launch(void* const* d_in, const int* in_sizes, int n_in,
                              void* d_out, int out_size) {
    const float* x      = (const float*)d_in[0];
    const float* th     = (const float*)d_in[1];
    const float* proj_w = (const float*)d_in[2];
    const float* proj_b = (const float*)d_in[3];
    const float* cf_w   = (const float*)d_in[4];
    const float* cf_b   = (const float*)d_in[5];
    const float* qw     = (const float*)d_in[6];
    const float* qb     = (const float*)d_in[7];
    const float* kw     = (const float*)d_in[8];
    const float* kb     = (const float*)d_in[9];
    const float* vw     = (const float*)d_in[10];
    const float* vb     = (const float*)d_in[11];
    const float* ow     = (const float*)d_in[12];
    const float* ob     = (const float*)d_in[13];
    const float* l1w    = (const float*)d_in[14];
    const float* l1b    = (const float*)d_in[15];
    const float* l2w    = (const float*)d_in[16];
    const float* l2b    = (const float*)d_in[17];
    const float* up_w   = (const float*)d_in[18];
    const float* up_b   = (const float*)d_in[19];
    const float* cl_w   = (const float*)d_in[20];
    const float* cl_b   = (const float*)d_in[21];
    float* out = (float*)d_out;

    k_textproj<<<BATCH * LSEQ, 64>>>(th, proj_w, proj_b, up_w);
    k_convin<<<BATCH * HH, 64>>>(x, cf_w, cf_b);
    k_kvall<<<dim3(NBLK, BATCH, 2), 256>>>(kw, kb, vw, vb, l2w, l2b);
    k_attn_stack<<<BATCH * HH, 256>>>(qw, qb, ow, ob, l1w, l1b);
    k_upconv_tc<<<dim3(4, 8, BATCH * 4), 256>>>(0, 64, 64, up_b);
    k_upconv_tc<<<dim3(8, 16, BATCH * 4), 256>>>(1, 128, 128, up_b);
    k_cl<<<dim3(2, 32, BATCH), 256>>>(cl_w, cl_b, out);

    (void)in_sizes; (void)n_in; (void)out_size;
}

// round 10
// speedup vs baseline: 1.4081x; 1.3864x over previous
#include <cuda_runtime.h>
#include <cuda_bf16.h>
#include <cstdint>

// ---------------- problem constants ----------------
#define BATCH 8
#define CCH   64
#define HH    64
#define WW    64
#define NPOS  4096
#define LSEQ  77
#define DTXT  512
#define NBLK  16
#define NHEAD 8
#define HDIM  8

// ---------------- device scratch ----------------
__device__ float g_tf  [BATCH*LSEQ*CCH];
__device__ float g_kn  [NBLK*BATCH*LSEQ*CCH];
__device__ float g_v   [NBLK*BATCH*LSEQ*CCH];
__device__ float g_feat[BATCH*CCH*HH*WW];
__device__ float g_u1  [BATCH*CCH*128*128];
__device__ float g_u2  [(size_t)BATCH*CCH*256*256];
__device__ float g_wupT[2*9*4*64*64];   // [lvl][tap][ocg][oc(64)][ic(64)], tf32

__device__ __forceinline__ float to_tf32(float x) {
    float r; asm("cvt.rna.tf32.f32 %0, %1;" : "=f"(r) : "f"(x)); return r;
}
__device__ __forceinline__ void mma_tf32(float* d, const uint32_t* a, const uint32_t* b) {
    asm volatile(
        "mma.sync.aligned.m16n8k8.row.col.f32.tf32.tf32.f32 "
        "{%0,%1,%2,%3}, {%4,%5,%6,%7}, {%8,%9}, {%0,%1,%2,%3};"
        : "+f"(d[0]), "+f"(d[1]), "+f"(d[2]), "+f"(d[3])
        : "r"(a[0]), "r"(a[1]), "r"(a[2]), "r"(a[3]), "r"(b[0]), "r"(b[1]));
}
// permuted channel index: ic = ks*8 + tig + 4h  ->  pic = ks*8 + tig*2 + h
__device__ __forceinline__ int picf(int ic) {
    int r = ic & 7;
    return (ic & ~7) + ((r & 3) * 2) + (r >> 2);
}

// ---------------- text projection (+ fused tf32 up-weight transpose) ----------------
__global__ void k_textproj(const float* __restrict__ th,
                           const float* __restrict__ pw,
                           const float* __restrict__ pb,
                           const float* __restrict__ upw) {
    __shared__ float s[DTXT];
    int bl = blockIdx.x;
    const float* row = th + (size_t)bl * DTXT;
    for (int i = threadIdx.x; i < DTXT; i += 64) s[i] = row[i];
    __syncthreads();
    int c = threadIdx.x;
    const float* w = pw + (size_t)c * DTXT;
    float acc = pb[c];
#pragma unroll 8
    for (int d = 0; d < DTXT; ++d) acc += s[d] * w[d];
    g_tf[bl * CCH + c] = acc;
    for (int idx = blockIdx.x * 64 + threadIdx.x; idx < 2 * 256 * 64 * 9;
         idx += gridDim.x * 64) {
        int k = idx % 9;
        int t = idx / 9;
        int ic = t % 64; t /= 64;
        int oc4 = t % 256;
        int lvl = t / 256;
        g_wupT[((((lvl * 9 + k) * 4 + (oc4 >> 6)) * 64 + (oc4 & 63)) * 64) + ic]
            = to_tf32(upw[idx]);
    }
}

// ---------------- input conv 3->64, 3x3 ----------------
__global__ void k_convin(const float* __restrict__ x,
                         const float* __restrict__ w,
                         const float* __restrict__ bias) {
    __shared__ float sw[64 * 27];
    __shared__ float sb[64];
    __shared__ float sin_[3][3][66];
    int bid = blockIdx.x; int b = bid >> 6; int y = bid & 63;
    int tid = threadIdx.x;
    for (int i = tid; i < 64 * 27; i += 64) sw[i] = w[i];
    sb[tid] = bias[tid];
    for (int ic = 0; ic < 3; ic++)
        for (int r = 0; r < 3; r++) {
            int yy = y + r - 1;
            float v = 0.f;
            if (yy >= 0 && yy < HH) v = x[(((size_t)b * 3 + ic) * HH + yy) * WW + tid];
            sin_[ic][r][tid + 1] = v;
            if (tid == 0) { sin_[ic][r][0] = 0.f; sin_[ic][r][65] = 0.f; }
        }
    __syncthreads();
    int xx = tid;
    for (int oc = 0; oc < 64; oc++) {
        float acc = sb[oc];
#pragma unroll
        for (int ic = 0; ic < 3; ic++)
#pragma unroll
            for (int r = 0; r < 3; r++)
#pragma unroll
                for (int kx = 0; kx < 3; kx++)
                    acc += sin_[ic][r][xx + kx] * sw[(oc * 3 + ic) * 9 + r * 3 + kx];
        g_feat[(((size_t)b * CCH + oc) * HH + y) * WW + xx] = acc;
    }
}

// ---------------- K/V projection + LN(K), all blocks, L-split ----------------
__global__ void __launch_bounds__(256) k_kvall(
        const float* __restrict__ kw, const float* __restrict__ kb,
        const float* __restrict__ vw, const float* __restrict__ vb,
        const float* __restrict__ l2w, const float* __restrict__ l2b) {
    __shared__ float tfs[LSEQ * 64];
    __shared__ float kws[64 * 68];
    __shared__ float vws[64 * 68];
    __shared__ float ksm[4 * 64];
    int blk = blockIdx.x, b = blockIdx.y, z = blockIdx.z;
    int tid = threadIdx.x;
    for (int i = tid; i < LSEQ * 64; i += 256) tfs[i] = g_tf[b * LSEQ * 64 + i];
    for (int idx = tid; idx < 4096; idx += 256) {
        int o = idx >> 6, c = idx & 63;
        kws[c * 68 + o] = kw[blk * 4096 + idx];
        vws[c * 68 + o] = vw[blk * 4096 + idx];
    }
    __syncthreads();
    int o = tid & 63, rr = tid >> 6;
    float kbv = kb[blk * 64 + o], vbv = vb[blk * 64 + o];
    float lwv = l2w[blk * 64 + o], lbv = l2b[blk * 64 + o];
    size_t base = ((size_t)(blk * BATCH + b)) * LSEQ * 64;
    int rbeg = z * 40, rend = rbeg + 40;
    for (int r0 = rbeg; r0 < rend; r0 += 4) {
        int r = r0 + rr;
        bool act = r < LSEQ;
        float ka = kbv, va = vbv;
        if (act) {
#pragma unroll 8
            for (int c = 0; c < 64; c++) {
                float t = tfs[r * 64 + c];
                ka += t * kws[c * 68 + o];
                va += t * vws[c * 68 + o];
            }
            ksm[rr * 64 + o] = ka;
        }
        __syncthreads();
        if (act) {
            float m = 0.f;
#pragma unroll 8
            for (int i = 0; i < 64; i++) m += ksm[rr * 64 + i];
            m *= (1.f / 64.f);
            float vv = 0.f;
#pragma unroll 8
            for (int i = 0; i < 64; i++) { float d = ksm[rr * 64 + i] - m; vv += d * d; }
            vv *= (1.f / 64.f);
            float rs = rsqrtf(vv + 1e-5f);
            g_kn[base + r * 64 + o] = (ka - m) * rs * lwv + lbv;
            g_v [base + r * 64 + o] = va;
        }
        __syncthreads();
    }
}

// ---------------- FUSED attention stack, TF32 MMA, 2-pos/1-head phase C ----------------
__global__ void __launch_bounds__(256, 3) k_attn_stack(
        const float* __restrict__ qw, const float* __restrict__ qb,
        const float* __restrict__ ow, const float* __restrict__ ob,
        const float* __restrict__ l1w, const float* __restrict__ l1b) {
    __shared__ __align__(16) float U1[LSEQ * 64];
    __shared__ __align__(16) float U2[LSEQ * 64];
    __shared__ __align__(16) float sF[64 * 72];
    __shared__ __align__(16) float sQ[64 * 72];

    int b = blockIdx.x >> 6, y = blockIdx.x & 63;
    int tid = threadIdx.x;
    int w = tid >> 5, lane = tid & 31;
    int g = lane >> 2, tig = lane & 3;
    int wm = w & 3, wn = w >> 2;
    int m0r = wm * 16 + g, m1r = m0r + 8;

    // load feat row -> sF[x][pic(c)]
    for (int idx = tid; idx < 4096; idx += 256) {
        int c = idx >> 6, xx = idx & 63;
        sF[xx * 72 + picf(c)] = g_feat[(((size_t)b * 64 + c) * 64 + y) * 64 + xx];
    }

    float pey = (float)y * (0.05f / 63.f);
    const float scale = 0.35355339059327373f;

#pragma unroll 1
    for (int blk = 0; blk < NBLK; blk++) {
        size_t kvbase = ((size_t)(blk * BATCH + b)) * LSEQ * 64;
        __syncthreads();
        // stage Wq (tf32) -> U1, V -> U2, consts -> sF row tails (pic order)
        for (int idx = tid; idx < 4096; idx += 256) {
            int o = idx >> 6, i = idx & 63;
            U1[o * 72 + picf(i)] = to_tf32(qw[blk * 4096 + idx]);
        }
        for (int idx = tid; idx < LSEQ * 64; idx += 256) {
            int l = idx >> 6, c = idx & 63;
            U2[l * 64 + picf(c)] = g_v[kvbase + idx];
        }
        if (tid < 64) {
            int s = picf(tid);
            sF[s * 72 + 64] = qb[blk * 64 + tid];
            sF[s * 72 + 65] = l1w[blk * 64 + tid];
            sF[s * 72 + 66] = l1b[blk * 64 + tid];
            sF[s * 72 + 67] = ob[blk * 64 + tid];
        }
        __syncthreads();

        // ---- phase B: q_raw = sF @ Wq via MMA ----
        {
            float d[4][4];
#pragma unroll
            for (int nt = 0; nt < 4; nt++)
#pragma unroll
                for (int e = 0; e < 4; e++) d[nt][e] = 0.f;
#pragma unroll
            for (int ks = 0; ks < 8; ks++) {
                int po = ks * 8 + tig * 2;
                float2 alo = *(const float2*)&sF[m0r * 72 + po];
                float2 ahi = *(const float2*)&sF[m1r * 72 + po];
                uint32_t A[4] = { __float_as_uint(alo.x), __float_as_uint(ahi.x),
                                  __float_as_uint(alo.y), __float_as_uint(ahi.y) };
#pragma unroll
                for (int nt = 0; nt < 4; nt++) {
                    int n = wn * 32 + nt * 8 + g;
                    float2 bv = *(const float2*)&U1[n * 72 + po];
                    uint32_t B[2] = { __float_as_uint(bv.x), __float_as_uint(bv.y) };
                    mma_tf32(d[nt], A, B);
                }
            }
#pragma unroll
            for (int nt = 0; nt < 4; nt++) {
                int c0 = wn * 32 + nt * 8 + tig * 2;
                int s0 = picf(c0), s1 = picf(c0 + 1);
                float q0 = sF[s0 * 72 + 64], q1 = sF[s1 * 72 + 64];
                sQ[m0r * 72 + s0] = d[nt][0] + q0;
                sQ[m0r * 72 + s1] = d[nt][1] + q1;
                sQ[m1r * 72 + s0] = d[nt][2] + q0;
                sQ[m1r * 72 + s1] = d[nt][3] + q1;
            }
        }
        __syncthreads();

        // ---- LN pass (4 lanes per position) + stage K -> U1 ----
        {
            int xx = tid >> 2, j = tid & 3;
            float v[16];
#pragma unroll
            for (int q = 0; q < 4; q++) {
                float4 t = *(const float4*)&sQ[xx * 72 + j * 16 + q * 4];
                v[q * 4 + 0] = t.x; v[q * 4 + 1] = t.y;
                v[q * 4 + 2] = t.z; v[q * 4 + 3] = t.w;
            }
            float pe = (j < 2) ? (float)xx * (0.05f / 63.f) : pey;
            float s = 0.f;
#pragma unroll
            for (int e = 0; e < 16; e++) { v[e] += pe; s += v[e]; }
            s += __shfl_xor_sync(0xffffffffu, s, 1);
            s += __shfl_xor_sync(0xffffffffu, s, 2);
            float mean = s * (1.f / 64.f);
            float sq = 0.f;
#pragma unroll
            for (int e = 0; e < 16; e++) { float dl = v[e] - mean; sq += dl * dl; }
            sq += __shfl_xor_sync(0xffffffffu, sq, 1);
            sq += __shfl_xor_sync(0xffffffffu, sq, 2);
            float rs = rsqrtf(sq * (1.f / 64.f) + 1e-5f);
#pragma unroll
            for (int q = 0; q < 4; q++) {
                int s0 = j * 16 + q * 4;
                float4 o;
                o.x = (v[q * 4 + 0] - mean) * rs * sF[(s0 + 0) * 72 + 65] + sF[(s0 + 0) * 72 + 66];
                o.y = (v[q * 4 + 1] - mean) * rs * sF[(s0 + 1) * 72 + 65] + sF[(s0 + 1) * 72 + 66];
                o.z = (v[q * 4 + 2] - mean) * rs * sF[(s0 + 2) * 72 + 65] + sF[(s0 + 2) * 72 + 66];
                o.w = (v[q * 4 + 3] - mean) * rs * sF[(s0 + 3) * 72 + 65] + sF[(s0 + 3) * 72 + 66];
                *(float4*)&sQ[xx * 72 + s0] = o;
            }
        }
        for (int idx = tid; idx < LSEQ * 64; idx += 256) {
            int l = idx >> 6, c = idx & 63;
            U1[l * 64 + picf(c)] = g_kn[kvbase + idx];
        }
        __syncthreads();

        // ---- phase C: attention, 2 positions x 1 head per thread ----
        // Each sQ cell is read and written by the SAME thread -> no inner barrier.
        {
            int hp = tid & 7, pp = tid >> 3;
            int cs = hp * 8;
            int p0 = pp * 2, p1 = p0 + 1;
            const float4* q0p = (const float4*)&sQ[p0 * 72 + cs];
            const float4* q1p = (const float4*)&sQ[p1 * 72 + cs];
            float4 qa0 = q0p[0], qa1 = q0p[1];
            float4 qb0 = q1p[0], qb1 = q1p[1];
            float denA = 0.f, denB = 0.f;
            float4 a0 = make_float4(0, 0, 0, 0), a1 = a0, b0 = a0, b1 = a0;
#pragma unroll 2
            for (int l = 0; l < LSEQ; l++) {
                const float4* kp = (const float4*)&U1[l * 64 + cs];
                float4 k0 = kp[0], k1 = kp[1];
                float tA0 = qa0.x * k0.x + qa0.y * k0.y;
                float tA1 = qa0.z * k0.z + qa0.w * k0.w;
                float tA2 = qa1.x * k1.x + qa1.y * k1.y;
                float tA3 = qa1.z * k1.z + qa1.w * k1.w;
                float tB0 = qb0.x * k0.x + qb0.y * k0.y;
                float tB1 = qb0.z * k0.z + qb0.w * k0.w;
                float tB2 = qb1.x * k1.x + qb1.y * k1.y;
                float tB3 = qb1.z * k1.z + qb1.w * k1.w;
                float eA = __expf(((tA0 + tA1) + (tA2 + tA3)) * scale);
                float eB = __expf(((tB0 + tB1) + (tB2 + tB3)) * scale);
                denA += eA; denB += eB;
                const float4* vp = (const float4*)&U2[l * 64 + cs];
                float4 v0 = vp[0], v1 = vp[1];
                a0.x += eA * v0.x; a0.y += eA * v0.y; a0.z += eA * v0.z; a0.w += eA * v0.w;
                a1.x += eA * v1.x; a1.y += eA * v1.y; a1.z += eA * v1.z; a1.w += eA * v1.w;
                b0.x += eB * v0.x; b0.y += eB * v0.y; b0.z += eB * v0.z; b0.w += eB * v0.w;
                b1.x += eB * v1.x; b1.y += eB * v1.y; b1.z += eB * v1.z; b1.w += eB * v1.w;
            }
            float iA = 1.f / denA, iB = 1.f / denB;
            float4* o0 = (float4*)&sQ[p0 * 72 + cs];
            o0[0] = make_float4(a0.x * iA, a0.y * iA, a0.z * iA, a0.w * iA);
            o0[1] = make_float4(a1.x * iA, a1.y * iA, a1.z * iA, a1.w * iA);
            float4* o1 = (float4*)&sQ[p1 * 72 + cs];
            o1[0] = make_float4(b0.x * iB, b0.y * iB, b0.z * iB, b0.w * iB);
            o1[1] = make_float4(b1.x * iB, b1.y * iB, b1.z * iB, b1.w * iB);
        }
        __syncthreads();
        // stage Wo (tf32) -> U2
        for (int idx = tid; idx < 4096; idx += 256) {
            int o = idx >> 6, i = idx & 63;
            U2[o * 72 + picf(i)] = to_tf32(ow[blk * 4096 + idx]);
        }
        __syncthreads();

        // ---- phase E: out-proj via MMA + residual into sF ----
        {
            float d[4][4];
#pragma unroll
            for (int nt = 0; nt < 4; nt++)
#pragma unroll
                for (int e = 0; e < 4; e++) d[nt][e] = 0.f;
#pragma unroll
            for (int ks = 0; ks < 8; ks++) {
                int po = ks * 8 + tig * 2;
                float2 alo = *(const float2*)&sQ[m0r * 72 + po];
                float2 ahi = *(const float2*)&sQ[m1r * 72 + po];
                uint32_t A[4] = { __float_as_uint(alo.x), __float_as_uint(ahi.x),
                                  __float_as_uint(alo.y), __float_as_uint(ahi.y) };
#pragma unroll
                for (int nt = 0; nt < 4; nt++) {
                    int n = wn * 32 + nt * 8 + g;
                    float2 bv = *(const float2*)&U2[n * 72 + po];
                    uint32_t B[2] = { __float_as_uint(bv.x), __float_as_uint(bv.y) };
                    mma_tf32(d[nt], A, B);
                }
            }
#pragma unroll
            for (int nt = 0; nt < 4; nt++) {
                int c0 = wn * 32 + nt * 8 + tig * 2;
                int s0 = picf(c0), s1 = picf(c0 + 1);
                float o0 = sF[s0 * 72 + 67], o1 = sF[s1 * 72 + 67];
                sF[m0r * 72 + s0] += d[nt][0] + o0;
                sF[m0r * 72 + s1] += d[nt][1] + o1;
                sF[m1r * 72 + s0] += d[nt][2] + o0;
                sF[m1r * 72 + s1] += d[nt][3] + o1;
            }
        }
    }
    __syncthreads();
    // write final feat row back (depermute)
    for (int idx = tid; idx < 4096; idx += 256) {
        int c = idx >> 6, xx = idx & 63;
        g_feat[(((size_t)b * 64 + c) * 64 + y) * 64 + xx] = sF[xx * 72 + picf(c)];
    }
}

// ---------------- TF32 tensor-core up-conv + pixel-shuffle + relu ----------------
__global__ void __launch_bounds__(256, 3) k_upconv_tc(int lvl, int IH, int IW,
                                                      const float* __restrict__ up_b) {
    const float* in   = lvl ? g_u1 : g_feat;
    float*       outp = lvl ? g_u2 : g_u1;
    __shared__ float sA[180 * 72];
    __shared__ float sBT[64 * 72];
    int x0 = blockIdx.x * 16, y0 = blockIdx.y * 8;
    int bz = blockIdx.z; int b = bz >> 2, ocg = bz & 3;
    int tid = threadIdx.x;
    int w = tid >> 5, lane = tid & 31;
    int g = lane >> 2, tig = lane & 3;
    int wm = w & 3, wn = w >> 2;

    for (int idx = tid; idx < 180 * 64; idx += 256) {
        int ic = idx / 180; int sp = idx % 180;
        int r = sp / 18, c = sp % 18;
        int gy = y0 - 1 + r, gx = x0 - 1 + c;
        float v = 0.f;
        if (gy >= 0 && gy < IH && gx >= 0 && gx < IW)
            v = in[(((size_t)b * 64 + ic) * IH + gy) * IW + gx];
        sA[sp * 72 + picf(ic)] = to_tf32(v);
    }

    float d[2][4][4];
#pragma unroll
    for (int nt = 0; nt < 4; nt++) {
        int oc = ocg * 64 + wn * 32 + nt * 8 + tig * 2;
        float b0v = up_b[lvl * 256 + oc];
        float b1v = up_b[lvl * 256 + oc + 1];
#pragma unroll
        for (int mt = 0; mt < 2; mt++) {
            d[mt][nt][0] = b0v; d[mt][nt][1] = b1v;
            d[mt][nt][2] = b0v; d[mt][nt][3] = b1v;
        }
    }

#pragma unroll 1
    for (int t = 0; t < 9; t++) {
        int ky = t / 3, kx = t % 3;
        __syncthreads();
        for (int idx = tid; idx < 4096; idx += 256) {
            int ic = idx & 63, oc = idx >> 6;
            sBT[oc * 72 + picf(ic)] =
                g_wupT[((((lvl * 9 + t) * 4 + ocg) * 64 + oc) * 64) + ic];
        }
        __syncthreads();
        int sp_base[2][2];
#pragma unroll
        for (int mt = 0; mt < 2; mt++) {
            int m_lo = wm * 32 + mt * 16 + g;
            int m_hi = m_lo + 8;
            sp_base[mt][0] = ((m_lo >> 4) + ky) * 18 + (m_lo & 15) + kx;
            sp_base[mt][1] = ((m_hi >> 4) + ky) * 18 + (m_hi & 15) + kx;
        }
#pragma unroll
        for (int ks = 0; ks < 8; ks++) {
            int po = ks * 8 + tig * 2;
            uint32_t A[2][4];
#pragma unroll
            for (int mt = 0; mt < 2; mt++) {
                float2 lo = *(const float2*)&sA[sp_base[mt][0] * 72 + po];
                float2 hi = *(const float2*)&sA[sp_base[mt][1] * 72 + po];
                A[mt][0] = __float_as_uint(lo.x);
                A[mt][1] = __float_as_uint(hi.x);
                A[mt][2] = __float_as_uint(lo.y);
                A[mt][3] = __float_as_uint(hi.y);
            }
            uint32_t Bf[4][2];
#pragma unroll
            for (int nt = 0; nt < 4; nt++) {
                int nc = wn * 32 + nt * 8 + g;
                float2 bv = *(const float2*)&sBT[nc * 72 + po];
                Bf[nt][0] = __float_as_uint(bv.x);
                Bf[nt][1] = __float_as_uint(bv.y);
            }
#pragma unroll
            for (int mt = 0; mt < 2; mt++)
#pragma unroll
                for (int nt = 0; nt < 4; nt++)
                    mma_tf32(d[mt][nt], A[mt], Bf[nt]);
        }
    }

    int OW = IW * 2;
#pragma unroll
    for (int mt = 0; mt < 2; mt++) {
#pragma unroll
        for (int half = 0; half < 2; half++) {
            int m = wm * 32 + mt * 16 + g + half * 8;
            int gy = y0 + (m >> 4), gx = x0 + (m & 15);
#pragma unroll
            for (int nt = 0; nt < 4; nt++) {
                int oc4a = ocg * 64 + wn * 32 + nt * 8 + tig * 2;
                float v0 = d[mt][nt][half * 2 + 0];
                float v1 = d[mt][nt][half * 2 + 1];
                int ca = oc4a >> 2, r1a = (oc4a >> 1) & 1, r2a = oc4a & 1;
                int oc4b = oc4a + 1;
                int cb = oc4b >> 2, r1b = (oc4b >> 1) & 1, r2b = oc4b & 1;
                outp[(((size_t)b * 64 + ca) * (size_t)(IH * 2) + (size_t)(2 * gy + r1a)) * (size_t)OW
                     + 2 * gx + r2a] = fmaxf(v0, 0.f);
                outp[(((size_t)b * 64 + cb) * (size_t)(IH * 2) + (size_t)(2 * gy + r1b)) * (size_t)OW
                     + 2 * gx + r2b] = fmaxf(v1, 0.f);
            }
        }
    }
}

// ---------------- final conv 64->3 at 256x256 ----------------
__global__ void __launch_bounds__(256) k_cl(const float* __restrict__ w,
                                            const float* __restrict__ bias,
                                            float* __restrict__ out) {
    __shared__ float sw[3 * 64 * 9];
    __shared__ float sin_[4][10][132];
    int xbase = blockIdx.x * 128;
    int y0 = blockIdx.y * 8;
    int b = blockIdx.z;
    int tid = threadIdx.x;
    int xg = tid & 31; int yr = tid >> 5;
    int x0 = xg * 4;
    for (int i = tid; i < 1728; i += 256) sw[i] = w[i];
    float acc[3][4];
#pragma unroll
    for (int oc = 0; oc < 3; oc++) {
        float bb = bias[oc];
#pragma unroll
        for (int xi = 0; xi < 4; xi++) acc[oc][xi] = bb;
    }
    for (int ic0 = 0; ic0 < 64; ic0 += 4) {
        __syncthreads();
        for (int idx = tid; idx < 4 * 10 * 130; idx += 256) {
            int c = idx % 130; int r = (idx / 130) % 10; int icc = idx / 1300;
            int gy = y0 - 1 + r, gx = xbase - 1 + c;
            float v = 0.f;
            if (gy >= 0 && gy < 256 && gx >= 0 && gx < 256)
                v = g_u2[(((size_t)b * 64 + ic0 + icc) * 256 + gy) * 256 + gx];
            sin_[icc][r][c] = v;
        }
        __syncthreads();
        for (int icc = 0; icc < 4; icc++) {
#pragma unroll
            for (int ky = 0; ky < 3; ky++) {
                float in6[6];
#pragma unroll
                for (int t = 0; t < 6; t++) in6[t] = sin_[icc][yr + ky][x0 + t];
#pragma unroll
                for (int kx = 0; kx < 3; kx++) {
#pragma unroll
                    for (int oc = 0; oc < 3; oc++) {
                        float wv = sw[(oc * 64 + ic0 + icc) * 9 + ky * 3 + kx];
#pragma unroll
                        for (int xi = 0; xi < 4; xi++)
                            acc[oc][xi] += wv * in6[kx + xi];
                    }
                }
            }
        }
    }
    int gy = y0 + yr, gx0 = xbase + x0;
#pragma unroll
    for (int oc = 0; oc < 3; oc++) {
        float4 v = make_float4(acc[oc][0], acc[oc][1], acc[oc][2], acc[oc][3]);
        *(float4*)&out[(((size_t)b * 3 + oc) * 256 + gy) * 256 + gx0] = v;
    }
}

// ---------------- launcher ----------------
extern "C" void kernel_launch(void* const* d_in, const int* in_sizes, int n_in,
                              void* d_out, int out_size) {
    const float* x      = (const float*)d_in[0];
    const float* th     = (const float*)d_in[1];
    const float* proj_w = (const float*)d_in[2];
    const float* proj_b = (const float*)d_in[3];
    const float* cf_w   = (const float*)d_in[4];
    const float* cf_b   = (const float*)d_in[5];
    const float* qw     = (const float*)d_in[6];
    const float* qb     = (const float*)d_in[7];
    const float* kw     = (const float*)d_in[8];
    const float* kb     = (const float*)d_in[9];
    const float* vw     = (const float*)d_in[10];
    const float* vb     = (const float*)d_in[11];
    const float* ow     = (const float*)d_in[12];
    const float* ob     = (const float*)d_in[13];
    const float* l1w    = (const float*)d_in[14];
    const float* l1b    = (const float*)d_in[15];
    const float* l2w    = (const float*)d_in[16];
    const float* l2b    = (const float*)d_in[17];
    const float* up_w   = (const float*)d_in[18];
    const float* up_b   = (const float*)d_in[19];
    const float* cl_w   = (const float*)d_in[20];
    const float* cl_b   = (const float*)d_in[21];
    float* out = (float*)d_out;

    k_textproj<<<BATCH * LSEQ, 64>>>(th, proj_w, proj_b, up_w);
    k_convin<<<BATCH * HH, 64>>>(x, cf_w, cf_b);
    k_kvall<<<dim3(NBLK, BATCH, 2), 256>>>(kw, kb, vw, vb, l2w, l2b);
    k_attn_stack<<<BATCH * HH, 256>>>(qw, qb, ow, ob, l1w, l1b);
    k_upconv_tc<<<dim3(4, 8, BATCH * 4), 256>>>(0, 64, 64, up_b);
    k_upconv_tc<<<dim3(8, 16, BATCH * 4), 256>>>(1, 128, 128, up_b);
    k_cl<<<dim3(2, 32, BATCH), 256>>>(cl_w, cl_b, out);

    (void)in_sizes; (void)n_in; (void)out_size;
}

// round 11
// speedup vs baseline: 1.4869x; 1.0559x over previous
#include <cuda_runtime.h>
#include <cuda_bf16.h>
#include <cstdint>

// ---------------- problem constants ----------------
#define BATCH 8
#define CCH   64
#define HH    64
#define WW    64
#define NPOS  4096
#define LSEQ  77
#define DTXT  512
#define NBLK  16
#define NHEAD 8
#define HDIM  8

// ---------------- device scratch ----------------
__device__ float g_tf  [BATCH*LSEQ*CCH];
__device__ float g_kn  [NBLK*BATCH*LSEQ*CCH];
__device__ float g_v   [NBLK*BATCH*LSEQ*CCH];
__device__ float g_feat[BATCH*CCH*HH*WW];
__device__ float g_u1  [BATCH*CCH*128*128];
__device__ float g_u2  [(size_t)BATCH*CCH*256*256];
__device__ float g_wupT[2*9*4*64*64];   // [lvl][tap][ocg][oc(64)][ic(64)], tf32

__device__ __forceinline__ float to_tf32(float x) {
    float r; asm("cvt.rna.tf32.f32 %0, %1;" : "=f"(r) : "f"(x)); return r;
}
__device__ __forceinline__ void mma_tf32(float* d, const uint32_t* a, const uint32_t* b) {
    asm volatile(
        "mma.sync.aligned.m16n8k8.row.col.f32.tf32.tf32.f32 "
        "{%0,%1,%2,%3}, {%4,%5,%6,%7}, {%8,%9}, {%0,%1,%2,%3};"
        : "+f"(d[0]), "+f"(d[1]), "+f"(d[2]), "+f"(d[3])
        : "r"(a[0]), "r"(a[1]), "r"(a[2]), "r"(a[3]), "r"(b[0]), "r"(b[1]));
}
// permuted channel index: ic = ks*8 + tig + 4h  ->  pic = ks*8 + tig*2 + h
__device__ __forceinline__ int picf(int ic) {
    int r = ic & 7;
    return (ic & ~7) + ((r & 3) * 2) + (r >> 2);
}

// ---------------- text projection (+ fused tf32 up-weight transpose) ----------------
__global__ void k_textproj(const float* __restrict__ th,
                           const float* __restrict__ pw,
                           const float* __restrict__ pb,
                           const float* __restrict__ upw) {
    __shared__ float s[DTXT];
    int bl = blockIdx.x;
    const float* row = th + (size_t)bl * DTXT;
    for (int i = threadIdx.x; i < DTXT; i += 64) s[i] = row[i];
    __syncthreads();
    int c = threadIdx.x;
    const float* w = pw + (size_t)c * DTXT;
    float acc = pb[c];
#pragma unroll 8
    for (int d = 0; d < DTXT; ++d) acc += s[d] * w[d];
    g_tf[bl * CCH + c] = acc;
    for (int idx = blockIdx.x * 64 + threadIdx.x; idx < 2 * 256 * 64 * 9;
         idx += gridDim.x * 64) {
        int k = idx % 9;
        int t = idx / 9;
        int ic = t % 64; t /= 64;
        int oc4 = t % 256;
        int lvl = t / 256;
        g_wupT[((((lvl * 9 + k) * 4 + (oc4 >> 6)) * 64 + (oc4 & 63)) * 64) + ic]
            = to_tf32(upw[idx]);
    }
}

// ---------------- input conv 3->64, 3x3 ----------------
__global__ void k_convin(const float* __restrict__ x,
                         const float* __restrict__ w,
                         const float* __restrict__ bias) {
    __shared__ float sw[64 * 27];
    __shared__ float sb[64];
    __shared__ float sin_[3][3][66];
    int bid = blockIdx.x; int b = bid >> 6; int y = bid & 63;
    int tid = threadIdx.x;
    for (int i = tid; i < 64 * 27; i += 64) sw[i] = w[i];
    sb[tid] = bias[tid];
    for (int ic = 0; ic < 3; ic++)
        for (int r = 0; r < 3; r++) {
            int yy = y + r - 1;
            float v = 0.f;
            if (yy >= 0 && yy < HH) v = x[(((size_t)b * 3 + ic) * HH + yy) * WW + tid];
            sin_[ic][r][tid + 1] = v;
            if (tid == 0) { sin_[ic][r][0] = 0.f; sin_[ic][r][65] = 0.f; }
        }
    __syncthreads();
    int xx = tid;
    for (int oc = 0; oc < 64; oc++) {
        float acc = sb[oc];
#pragma unroll
        for (int ic = 0; ic < 3; ic++)
#pragma unroll
            for (int r = 0; r < 3; r++)
#pragma unroll
                for (int kx = 0; kx < 3; kx++)
                    acc += sin_[ic][r][xx + kx] * sw[(oc * 3 + ic) * 9 + r * 3 + kx];
        g_feat[(((size_t)b * CCH + oc) * HH + y) * WW + xx] = acc;
    }
}

// ---------------- K/V projection + LN(K), all blocks, L-split ----------------
__global__ void __launch_bounds__(256) k_kvall(
        const float* __restrict__ kw, const float* __restrict__ kb,
        const float* __restrict__ vw, const float* __restrict__ vb,
        const float* __restrict__ l2w, const float* __restrict__ l2b) {
    __shared__ float tfs[LSEQ * 64];
    __shared__ float kws[64 * 68];
    __shared__ float vws[64 * 68];
    __shared__ float ksm[4 * 64];
    int blk = blockIdx.x, b = blockIdx.y, z = blockIdx.z;
    int tid = threadIdx.x;
    for (int i = tid; i < LSEQ * 64; i += 256) tfs[i] = g_tf[b * LSEQ * 64 + i];
    for (int idx = tid; idx < 4096; idx += 256) {
        int o = idx >> 6, c = idx & 63;
        kws[c * 68 + o] = kw[blk * 4096 + idx];
        vws[c * 68 + o] = vw[blk * 4096 + idx];
    }
    __syncthreads();
    int o = tid & 63, rr = tid >> 6;
    float kbv = kb[blk * 64 + o], vbv = vb[blk * 64 + o];
    float lwv = l2w[blk * 64 + o], lbv = l2b[blk * 64 + o];
    size_t base = ((size_t)(blk * BATCH + b)) * LSEQ * 64;
    int rbeg = z * 40, rend = rbeg + 40;
    for (int r0 = rbeg; r0 < rend; r0 += 4) {
        int r = r0 + rr;
        bool act = r < LSEQ;
        float ka = kbv, va = vbv;
        if (act) {
#pragma unroll 8
            for (int c = 0; c < 64; c++) {
                float t = tfs[r * 64 + c];
                ka += t * kws[c * 68 + o];
                va += t * vws[c * 68 + o];
            }
            ksm[rr * 64 + o] = ka;
        }
        __syncthreads();
        if (act) {
            float m = 0.f;
#pragma unroll 8
            for (int i = 0; i < 64; i++) m += ksm[rr * 64 + i];
            m *= (1.f / 64.f);
            float vv = 0.f;
#pragma unroll 8
            for (int i = 0; i < 64; i++) { float d = ksm[rr * 64 + i] - m; vv += d * d; }
            vv *= (1.f / 64.f);
            float rs = rsqrtf(vv + 1e-5f);
            g_kn[base + r * 64 + o] = (ka - m) * rs * lwv + lbv;
            g_v [base + r * 64 + o] = va;
        }
        __syncthreads();
    }
}

// ---------------- FUSED attention stack: 2 rows/CTA, 512 threads, dyn smem ----------------
// Layout (floats): U1[77*64] | U2[77*64] | sF[128*72] | sQ[128*72]  = 113152 B
__global__ void __launch_bounds__(512, 2) k_attn_stack(
        const float* __restrict__ qw, const float* __restrict__ qb,
        const float* __restrict__ ow, const float* __restrict__ ob,
        const float* __restrict__ l1w, const float* __restrict__ l1b) {
    extern __shared__ __align__(16) float dyn[];
    float* U1 = dyn;                      // 4928
    float* U2 = U1 + LSEQ * 64;           // 4928
    float* sF = U2 + LSEQ * 64;           // 9216
    float* sQ = sF + 128 * 72;            // 9216

    int b = blockIdx.x >> 5, yp = blockIdx.x & 31;
    int tid = threadIdx.x;
    int w = tid >> 5, lane = tid & 31;
    int g = lane >> 2, tig = lane & 3;
    int wm = w & 7, wn = w >> 3;
    int m0r = wm * 16 + g, m1r = m0r + 8;

    // load 2 feat rows -> sF[p][pic(c)], p = row*64 + x
    for (int idx = tid; idx < 8192; idx += 512) {
        int c = idx >> 7, p = idx & 127;
        int row = p >> 6, xx = p & 63;
        sF[p * 72 + picf(c)] =
            g_feat[(((size_t)b * 64 + c) * 64 + (yp * 2 + row)) * 64 + xx];
    }

    const float scale = 0.35355339059327373f;

#pragma unroll 1
    for (int blk = 0; blk < NBLK; blk++) {
        size_t kvbase = ((size_t)(blk * BATCH + b)) * LSEQ * 64;
        __syncthreads();
        // stage Wq (tf32) -> U1, V -> U2, consts -> sF row tails (pic order)
        for (int idx = tid; idx < 4096; idx += 512) {
            int o = idx >> 6, i = idx & 63;
            U1[o * 72 + picf(i)] = to_tf32(qw[blk * 4096 + idx]);
        }
        for (int idx = tid; idx < LSEQ * 64; idx += 512) {
            int l = idx >> 6, c = idx & 63;
            U2[l * 64 + picf(c)] = g_v[kvbase + idx];
        }
        if (tid < 64) {
            int s = picf(tid);
            sF[s * 72 + 64] = qb[blk * 64 + tid];
            sF[s * 72 + 65] = l1w[blk * 64 + tid];
            sF[s * 72 + 66] = l1b[blk * 64 + tid];
            sF[s * 72 + 67] = ob[blk * 64 + tid];
        }
        __syncthreads();

        // ---- phase B: q_raw = sF @ Wq via MMA (M=128) ----
        {
            float d[4][4];
#pragma unroll
            for (int nt = 0; nt < 4; nt++)
#pragma unroll
                for (int e = 0; e < 4; e++) d[nt][e] = 0.f;
#pragma unroll
            for (int ks = 0; ks < 8; ks++) {
                int po = ks * 8 + tig * 2;
                float2 alo = *(const float2*)&sF[m0r * 72 + po];
                float2 ahi = *(const float2*)&sF[m1r * 72 + po];
                uint32_t A[4] = { __float_as_uint(alo.x), __float_as_uint(ahi.x),
                                  __float_as_uint(alo.y), __float_as_uint(ahi.y) };
#pragma unroll
                for (int nt = 0; nt < 4; nt++) {
                    int n = wn * 32 + nt * 8 + g;
                    float2 bv = *(const float2*)&U1[n * 72 + po];
                    uint32_t B[2] = { __float_as_uint(bv.x), __float_as_uint(bv.y) };
                    mma_tf32(d[nt], A, B);
                }
            }
#pragma unroll
            for (int nt = 0; nt < 4; nt++) {
                int c0 = wn * 32 + nt * 8 + tig * 2;
                int s0 = picf(c0), s1 = picf(c0 + 1);
                float q0 = sF[s0 * 72 + 64], q1 = sF[s1 * 72 + 64];
                sQ[m0r * 72 + s0] = d[nt][0] + q0;
                sQ[m0r * 72 + s1] = d[nt][1] + q1;
                sQ[m1r * 72 + s0] = d[nt][2] + q0;
                sQ[m1r * 72 + s1] = d[nt][3] + q1;
            }
        }
        __syncthreads();

        // ---- LN pass (4 lanes per position, 128 positions) + stage K -> U1 ----
        {
            int pp = tid >> 2, j = tid & 3;
            int xx = pp & 63, yl = pp >> 6;
            float v[16];
#pragma unroll
            for (int q = 0; q < 4; q++) {
                float4 t = *(const float4*)&sQ[pp * 72 + j * 16 + q * 4];
                v[q * 4 + 0] = t.x; v[q * 4 + 1] = t.y;
                v[q * 4 + 2] = t.z; v[q * 4 + 3] = t.w;
            }
            float pe = (j < 2) ? (float)xx * (0.05f / 63.f)
                               : (float)(yp * 2 + yl) * (0.05f / 63.f);
            float s = 0.f;
#pragma unroll
            for (int e = 0; e < 16; e++) { v[e] += pe; s += v[e]; }
            s += __shfl_xor_sync(0xffffffffu, s, 1);
            s += __shfl_xor_sync(0xffffffffu, s, 2);
            float mean = s * (1.f / 64.f);
            float sq = 0.f;
#pragma unroll
            for (int e = 0; e < 16; e++) { float dl = v[e] - mean; sq += dl * dl; }
            sq += __shfl_xor_sync(0xffffffffu, sq, 1);
            sq += __shfl_xor_sync(0xffffffffu, sq, 2);
            float rs = rsqrtf(sq * (1.f / 64.f) + 1e-5f);
#pragma unroll
            for (int q = 0; q < 4; q++) {
                int s0 = j * 16 + q * 4;
                float4 o;
                o.x = (v[q * 4 + 0] - mean) * rs * sF[(s0 + 0) * 72 + 65] + sF[(s0 + 0) * 72 + 66];
                o.y = (v[q * 4 + 1] - mean) * rs * sF[(s0 + 1) * 72 + 65] + sF[(s0 + 1) * 72 + 66];
                o.z = (v[q * 4 + 2] - mean) * rs * sF[(s0 + 2) * 72 + 65] + sF[(s0 + 2) * 72 + 66];
                o.w = (v[q * 4 + 3] - mean) * rs * sF[(s0 + 3) * 72 + 65] + sF[(s0 + 3) * 72 + 66];
                *(float4*)&sQ[pp * 72 + s0] = o;
            }
        }
        for (int idx = tid; idx < LSEQ * 64; idx += 512) {
            int l = idx >> 6, c = idx & 63;
            U1[l * 64 + picf(c)] = g_kn[kvbase + idx];
        }
        __syncthreads();

        // ---- phase C: attention, 2 positions x 1 head per thread (512 thr = 128x8/2) ----
        {
            int hp = tid & 7, pp = tid >> 3;
            int cs = hp * 8;
            int p0 = pp * 2, p1 = p0 + 1;
            const float4* q0p = (const float4*)&sQ[p0 * 72 + cs];
            const float4* q1p = (const float4*)&sQ[p1 * 72 + cs];
            float4 qa0 = q0p[0], qa1 = q0p[1];
            float4 qb0 = q1p[0], qb1 = q1p[1];
            float denA = 0.f, denB = 0.f;
            float4 a0 = make_float4(0, 0, 0, 0), a1 = a0, b0 = a0, b1 = a0;
#pragma unroll 2
            for (int l = 0; l < LSEQ; l++) {
                const float4* kp = (const float4*)&U1[l * 64 + cs];
                float4 k0 = kp[0], k1 = kp[1];
                float tA0 = qa0.x * k0.x + qa0.y * k0.y;
                float tA1 = qa0.z * k0.z + qa0.w * k0.w;
                float tA2 = qa1.x * k1.x + qa1.y * k1.y;
                float tA3 = qa1.z * k1.z + qa1.w * k1.w;
                float tB0 = qb0.x * k0.x + qb0.y * k0.y;
                float tB1 = qb0.z * k0.z + qb0.w * k0.w;
                float tB2 = qb1.x * k1.x + qb1.y * k1.y;
                float tB3 = qb1.z * k1.z + qb1.w * k1.w;
                float eA = __expf(((tA0 + tA1) + (tA2 + tA3)) * scale);
                float eB = __expf(((tB0 + tB1) + (tB2 + tB3)) * scale);
                denA += eA; denB += eB;
                const float4* vp = (const float4*)&U2[l * 64 + cs];
                float4 v0 = vp[0], v1 = vp[1];
                a0.x += eA * v0.x; a0.y += eA * v0.y; a0.z += eA * v0.z; a0.w += eA * v0.w;
                a1.x += eA * v1.x; a1.y += eA * v1.y; a1.z += eA * v1.z; a1.w += eA * v1.w;
                b0.x += eB * v0.x; b0.y += eB * v0.y; b0.z += eB * v0.z; b0.w += eB * v0.w;
                b1.x += eB * v1.x; b1.y += eB * v1.y; b1.z += eB * v1.z; b1.w += eB * v1.w;
            }
            float iA = 1.f / denA, iB = 1.f / denB;
            float4* o0 = (float4*)&sQ[p0 * 72 + cs];
            o0[0] = make_float4(a0.x * iA, a0.y * iA, a0.z * iA, a0.w * iA);
            o0[1] = make_float4(a1.x * iA, a1.y * iA, a1.z * iA, a1.w * iA);
            float4* o1 = (float4*)&sQ[p1 * 72 + cs];
            o1[0] = make_float4(b0.x * iB, b0.y * iB, b0.z * iB, b0.w * iB);
            o1[1] = make_float4(b1.x * iB, b1.y * iB, b1.z * iB, b1.w * iB);
        }
        __syncthreads();
        // stage Wo (tf32) -> U2
        for (int idx = tid; idx < 4096; idx += 512) {
            int o = idx >> 6, i = idx & 63;
            U2[o * 72 + picf(i)] = to_tf32(ow[blk * 4096 + idx]);
        }
        __syncthreads();

        // ---- phase E: out-proj via MMA + residual into sF ----
        {
            float d[4][4];
#pragma unroll
            for (int nt = 0; nt < 4; nt++)
#pragma unroll
                for (int e = 0; e < 4; e++) d[nt][e] = 0.f;
#pragma unroll
            for (int ks = 0; ks < 8; ks++) {
                int po = ks * 8 + tig * 2;
                float2 alo = *(const float2*)&sQ[m0r * 72 + po];
                float2 ahi = *(const float2*)&sQ[m1r * 72 + po];
                uint32_t A[4] = { __float_as_uint(alo.x), __float_as_uint(ahi.x),
                                  __float_as_uint(alo.y), __float_as_uint(ahi.y) };
#pragma unroll
                for (int nt = 0; nt < 4; nt++) {
                    int n = wn * 32 + nt * 8 + g;
                    float2 bv = *(const float2*)&U2[n * 72 + po];
                    uint32_t B[2] = { __float_as_uint(bv.x), __float_as_uint(bv.y) };
                    mma_tf32(d[nt], A, B);
                }
            }
#pragma unroll
            for (int nt = 0; nt < 4; nt++) {
                int c0 = wn * 32 + nt * 8 + tig * 2;
                int s0 = picf(c0), s1 = picf(c0 + 1);
                float o0 = sF[s0 * 72 + 67], o1 = sF[s1 * 72 + 67];
                sF[m0r * 72 + s0] += d[nt][0] + o0;
                sF[m0r * 72 + s1] += d[nt][1] + o1;
                sF[m1r * 72 + s0] += d[nt][2] + o0;
                sF[m1r * 72 + s1] += d[nt][3] + o1;
            }
        }
    }
    __syncthreads();
    // write final feat rows back (depermute)
    for (int idx = tid; idx < 8192; idx += 512) {
        int c = idx >> 7, p = idx & 127;
        int row = p >> 6, xx = p & 63;
        g_feat[(((size_t)b * 64 + c) * 64 + (yp * 2 + row)) * 64 + xx]
            = sF[p * 72 + picf(c)];
    }
}

// ---------------- TF32 tensor-core up-conv + pixel-shuffle + relu ----------------
__global__ void __launch_bounds__(256, 3) k_upconv_tc(int lvl, int IH, int IW,
                                                      const float* __restrict__ up_b) {
    const float* in   = lvl ? g_u1 : g_feat;
    float*       outp = lvl ? g_u2 : g_u1;
    __shared__ float sA[180 * 72];
    __shared__ float sBT[64 * 72];
    int x0 = blockIdx.x * 16, y0 = blockIdx.y * 8;
    int bz = blockIdx.z; int b = bz >> 2, ocg = bz & 3;
    int tid = threadIdx.x;
    int w = tid >> 5, lane = tid & 31;
    int g = lane >> 2, tig = lane & 3;
    int wm = w & 3, wn = w >> 2;

    for (int idx = tid; idx < 180 * 64; idx += 256) {
        int ic = idx / 180; int sp = idx % 180;
        int r = sp / 18, c = sp % 18;
        int gy = y0 - 1 + r, gx = x0 - 1 + c;
        float v = 0.f;
        if (gy >= 0 && gy < IH && gx >= 0 && gx < IW)
            v = in[(((size_t)b * 64 + ic) * IH + gy) * IW + gx];
        sA[sp * 72 + picf(ic)] = to_tf32(v);
    }

    float d[2][4][4];
#pragma unroll
    for (int nt = 0; nt < 4; nt++) {
        int oc = ocg * 64 + wn * 32 + nt * 8 + tig * 2;
        float b0v = up_b[lvl * 256 + oc];
        float b1v = up_b[lvl * 256 + oc + 1];
#pragma unroll
        for (int mt = 0; mt < 2; mt++) {
            d[mt][nt][0] = b0v; d[mt][nt][1] = b1v;
            d[mt][nt][2] = b0v; d[mt][nt][3] = b1v;
        }
    }

#pragma unroll 1
    for (int t = 0; t < 9; t++) {
        int ky = t / 3, kx = t % 3;
        __syncthreads();
        for (int idx = tid; idx < 4096; idx += 256) {
            int ic = idx & 63, oc = idx >> 6;
            sBT[oc * 72 + picf(ic)] =
                g_wupT[((((lvl * 9 + t) * 4 + ocg) * 64 + oc) * 64) + ic];
        }
        __syncthreads();
        int sp_base[2][2];
#pragma unroll
        for (int mt = 0; mt < 2; mt++) {
            int m_lo = wm * 32 + mt * 16 + g;
            int m_hi = m_lo + 8;
            sp_base[mt][0] = ((m_lo >> 4) + ky) * 18 + (m_lo & 15) + kx;
            sp_base[mt][1] = ((m_hi >> 4) + ky) * 18 + (m_hi & 15) + kx;
        }
#pragma unroll
        for (int ks = 0; ks < 8; ks++) {
            int po = ks * 8 + tig * 2;
            uint32_t A[2][4];
#pragma unroll
            for (int mt = 0; mt < 2; mt++) {
                float2 lo = *(const float2*)&sA[sp_base[mt][0] * 72 + po];
                float2 hi = *(const float2*)&sA[sp_base[mt][1] * 72 + po];
                A[mt][0] = __float_as_uint(lo.x);
                A[mt][1] = __float_as_uint(hi.x);
                A[mt][2] = __float_as_uint(lo.y);
                A[mt][3] = __float_as_uint(hi.y);
            }
            uint32_t Bf[4][2];
#pragma unroll
            for (int nt = 0; nt < 4; nt++) {
                int nc = wn * 32 + nt * 8 + g;
                float2 bv = *(const float2*)&sBT[nc * 72 + po];
                Bf[nt][0] = __float_as_uint(bv.x);
                Bf[nt][1] = __float_as_uint(bv.y);
            }
#pragma unroll
            for (int mt = 0; mt < 2; mt++)
#pragma unroll
                for (int nt = 0; nt < 4; nt++)
                    mma_tf32(d[mt][nt], A[mt], Bf[nt]);
        }
    }

    int OW = IW * 2;
#pragma unroll
    for (int mt = 0; mt < 2; mt++) {
#pragma unroll
        for (int half = 0; half < 2; half++) {
            int m = wm * 32 + mt * 16 + g + half * 8;
            int gy = y0 + (m >> 4), gx = x0 + (m & 15);
#pragma unroll
            for (int nt = 0; nt < 4; nt++) {
                int oc4a = ocg * 64 + wn * 32 + nt * 8 + tig * 2;
                float v0 = d[mt][nt][half * 2 + 0];
                float v1 = d[mt][nt][half * 2 + 1];
                int ca = oc4a >> 2, r1a = (oc4a >> 1) & 1, r2a = oc4a & 1;
                int oc4b = oc4a + 1;
                int cb = oc4b >> 2, r1b = (oc4b >> 1) & 1, r2b = oc4b & 1;
                outp[(((size_t)b * 64 + ca) * (size_t)(IH * 2) + (size_t)(2 * gy + r1a)) * (size_t)OW
                     + 2 * gx + r2a] = fmaxf(v0, 0.f);
                outp[(((size_t)b * 64 + cb) * (size_t)(IH * 2) + (size_t)(2 * gy + r1b)) * (size_t)OW
                     + 2 * gx + r2b] = fmaxf(v1, 0.f);
            }
        }
    }
}

// ---------------- final conv 64->3 at 256x256 ----------------
__global__ void __launch_bounds__(256) k_cl(const float* __restrict__ w,
                                            const float* __restrict__ bias,
                                            float* __restrict__ out) {
    __shared__ float sw[3 * 64 * 9];
    __shared__ float sin_[4][10][132];
    int xbase = blockIdx.x * 128;
    int y0 = blockIdx.y * 8;
    int b = blockIdx.z;
    int tid = threadIdx.x;
    int xg = tid & 31; int yr = tid >> 5;
    int x0 = xg * 4;
    for (int i = tid; i < 1728; i += 256) sw[i] = w[i];
    float acc[3][4];
#pragma unroll
    for (int oc = 0; oc < 3; oc++) {
        float bb = bias[oc];
#pragma unroll
        for (int xi = 0; xi < 4; xi++) acc[oc][xi] = bb;
    }
    for (int ic0 = 0; ic0 < 64; ic0 += 4) {
        __syncthreads();
        for (int idx = tid; idx < 4 * 10 * 130; idx += 256) {
            int c = idx % 130; int r = (idx / 130) % 10; int icc = idx / 1300;
            int gy = y0 - 1 + r, gx = xbase - 1 + c;
            float v = 0.f;
            if (gy >= 0 && gy < 256 && gx >= 0 && gx < 256)
                v = g_u2[(((size_t)b * 64 + ic0 + icc) * 256 + gy) * 256 + gx];
            sin_[icc][r][c] = v;
        }
        __syncthreads();
        for (int icc = 0; icc < 4; icc++) {
#pragma unroll
            for (int ky = 0; ky < 3; ky++) {
                float in6[6];
#pragma unroll
                for (int t = 0; t < 6; t++) in6[t] = sin_[icc][yr + ky][x0 + t];
#pragma unroll
                for (int kx = 0; kx < 3; kx++) {
#pragma unroll
                    for (int oc = 0; oc < 3; oc++) {
                        float wv = sw[(oc * 64 + ic0 + icc) * 9 + ky * 3 + kx];
#pragma unroll
                        for (int xi = 0; xi < 4; xi++)
                            acc[oc][xi] += wv * in6[kx + xi];
                    }
                }
            }
        }
    }
    int gy = y0 + yr, gx0 = xbase + x0;
#pragma unroll
    for (int oc = 0; oc < 3; oc++) {
        float4 v = make_float4(acc[oc][0], acc[oc][1], acc[oc][2], acc[oc][3]);
        *(float4*)&out[(((size_t)b * 3 + oc) * 256 + gy) * 256 + gx0] = v;
    }
}

// ---------------- launcher ----------------
extern "C" void kernel_launch(void* const* d_in, const int* in_sizes, int n_in,
                              void* d_out, int out_size) {
    const float* x      = (const float*)d_in[0];
    const float* th     = (const float*)d_in[1];
    const float* proj_w = (const float*)d_in[2];
    const float* proj_b = (const float*)d_in[3];
    const float* cf_w   = (const float*)d_in[4];
    const float* cf_b   = (const float*)d_in[5];
    const float* qw     = (const float*)d_in[6];
    const float* qb     = (const float*)d_in[7];
    const float* kw     = (const float*)d_in[8];
    const float* kb     = (const float*)d_in[9];
    const float* vw     = (const float*)d_in[10];
    const float* vb     = (const float*)d_in[11];
    const float* ow     = (const float*)d_in[12];
    const float* ob     = (const float*)d_in[13];
    const float* l1w    = (const float*)d_in[14];
    const float* l1b    = (const float*)d_in[15];
    const float* l2w    = (const float*)d_in[16];
    const float* l2b    = (const float*)d_in[17];
    const float* up_w   = (const float*)d_in[18];
    const float* up_b   = (const float*)d_in[19];
    const float* cl_w   = (const float*)d_in[20];
    const float* cl_b   = (const float*)d_in[21];
    float* out = (float*)d_out;

    const int ATTN_SMEM = (2 * LSEQ * 64 + 2 * 128 * 72) * 4;   // 113152 B
    cudaFuncSetAttribute(k_attn_stack,
                         cudaFuncAttributeMaxDynamicSharedMemorySize, ATTN_SMEM);

    k_textproj<<<BATCH * LSEQ, 64>>>(th, proj_w, proj_b, up_w);
    k_convin<<<BATCH * HH, 64>>>(x, cf_w, cf_b);
    k_kvall<<<dim3(NBLK, BATCH, 2), 256>>>(kw, kb, vw, vb, l2w, l2b);
    k_attn_stack<<<BATCH * 32, 512, ATTN_SMEM>>>(qw, qb, ow, ob, l1w, l1b);
    k_upconv_tc<<<dim3(4, 8, BATCH * 4), 256>>>(0, 64, 64, up_b);
    k_upconv_tc<<<dim3(8, 16, BATCH * 4), 256>>>(1, 128, 128, up_b);
    k_cl<<<dim3(2, 32, BATCH), 256>>>(cl_w, cl_b, out);

    (void)in_sizes; (void)n_in; (void)out_size;
}

// round 13
// speedup vs baseline: 2.0764x; 1.3965x over previous
#include <cuda_runtime.h>
#include <cuda_bf16.h>
#include <cstdint>

// ---------------- problem constants ----------------
#define BATCH 8
#define CCH   64
#define HH    64
#define WW    64
#define NPOS  4096
#define LSEQ  77
#define DTXT  512
#define NBLK  16
#define NHEAD 8
#define HDIM  8

// ---------------- device scratch ----------------
__device__ float g_tf  [BATCH*LSEQ*CCH];
__device__ float g_kn  [NBLK*BATCH*LSEQ*CCH];
__device__ float g_v   [NBLK*BATCH*LSEQ*CCH];
__device__ float g_feat[BATCH*CCH*HH*WW];
__device__ float g_u1  [BATCH*CCH*128*128];
__device__ float g_u2  [(size_t)BATCH*CCH*256*256];
__device__ float g_wupT[2*9*4*64*64];   // [lvl][tap][ocg][oc(64)][ic(64)], tf32

__device__ __forceinline__ float to_tf32(float x) {
    float r; asm("cvt.rna.tf32.f32 %0, %1;" : "=f"(r) : "f"(x)); return r;
}
__device__ __forceinline__ void mma_tf32(float* d, const uint32_t* a, const uint32_t* b) {
    asm volatile(
        "mma.sync.aligned.m16n8k8.row.col.f32.tf32.tf32.f32 "
        "{%0,%1,%2,%3}, {%4,%5,%6,%7}, {%8,%9}, {%0,%1,%2,%3};"
        : "+f"(d[0]), "+f"(d[1]), "+f"(d[2]), "+f"(d[3])
        : "r"(a[0]), "r"(a[1]), "r"(a[2]), "r"(a[3]), "r"(b[0]), "r"(b[1]));
}
// permuted channel index: ic = ks*8 + tig + 4h  ->  pic = ks*8 + tig*2 + h
__device__ __forceinline__ int picf(int ic) {
    int r = ic & 7;
    return (ic & ~7) + ((r & 3) * 2) + (r >> 2);
}

// ---------------- text projection (+ fused tf32 up-weight transpose) ----------------
__global__ void k_textproj(const float* __restrict__ th,
                           const float* __restrict__ pw,
                           const float* __restrict__ pb,
                           const float* __restrict__ upw) {
    __shared__ float s[DTXT];
    int bl = blockIdx.x;
    const float* row = th + (size_t)bl * DTXT;
    for (int i = threadIdx.x; i < DTXT; i += 64) s[i] = row[i];
    __syncthreads();
    int c = threadIdx.x;
    const float* w = pw + (size_t)c * DTXT;
    float acc = pb[c];
#pragma unroll 8
    for (int d = 0; d < DTXT; ++d) acc += s[d] * w[d];
    g_tf[bl * CCH + c] = acc;
    for (int idx = blockIdx.x * 64 + threadIdx.x; idx < 2 * 256 * 64 * 9;
         idx += gridDim.x * 64) {
        int k = idx % 9;
        int t = idx / 9;
        int ic = t % 64; t /= 64;
        int oc4 = t % 256;
        int lvl = t / 256;
        g_wupT[((((lvl * 9 + k) * 4 + (oc4 >> 6)) * 64 + (oc4 & 63)) * 64) + ic]
            = to_tf32(upw[idx]);
    }
}

// ---------------- input conv 3->64, 3x3 ----------------
__global__ void k_convin(const float* __restrict__ x,
                         const float* __restrict__ w,
                         const float* __restrict__ bias) {
    __shared__ float sw[64 * 27];
    __shared__ float sb[64];
    __shared__ float sin_[3][3][66];
    int bid = blockIdx.x; int b = bid >> 6; int y = bid & 63;
    int tid = threadIdx.x;
    for (int i = tid; i < 64 * 27; i += 64) sw[i] = w[i];
    sb[tid] = bias[tid];
    for (int ic = 0; ic < 3; ic++)
        for (int r = 0; r < 3; r++) {
            int yy = y + r - 1;
            float v = 0.f;
            if (yy >= 0 && yy < HH) v = x[(((size_t)b * 3 + ic) * HH + yy) * WW + tid];
            sin_[ic][r][tid + 1] = v;
            if (tid == 0) { sin_[ic][r][0] = 0.f; sin_[ic][r][65] = 0.f; }
        }
    __syncthreads();
    int xx = tid;
    for (int oc = 0; oc < 64; oc++) {
        float acc = sb[oc];
#pragma unroll
        for (int ic = 0; ic < 3; ic++)
#pragma unroll
            for (int r = 0; r < 3; r++)
#pragma unroll
                for (int kx = 0; kx < 3; kx++)
                    acc += sin_[ic][r][xx + kx] * sw[(oc * 3 + ic) * 9 + r * 3 + kx];
        g_feat[(((size_t)b * CCH + oc) * HH + y) * WW + xx] = acc;
    }
}

// ---------------- K/V projection + LN(K), all blocks, L-split ----------------
__global__ void __launch_bounds__(256) k_kvall(
        const float* __restrict__ kw, const float* __restrict__ kb,
        const float* __restrict__ vw, const float* __restrict__ vb,
        const float* __restrict__ l2w, const float* __restrict__ l2b) {
    __shared__ float tfs[LSEQ * 64];
    __shared__ float kws[64 * 68];
    __shared__ float vws[64 * 68];
    __shared__ float ksm[4 * 64];
    int blk = blockIdx.x, b = blockIdx.y, z = blockIdx.z;
    int tid = threadIdx.x;
    for (int i = tid; i < LSEQ * 64; i += 256) tfs[i] = g_tf[b * LSEQ * 64 + i];
    for (int idx = tid; idx < 4096; idx += 256) {
        int o = idx >> 6, c = idx & 63;
        kws[c * 68 + o] = kw[blk * 4096 + idx];
        vws[c * 68 + o] = vw[blk * 4096 + idx];
    }
    __syncthreads();
    int o = tid & 63, rr = tid >> 6;
    float kbv = kb[blk * 64 + o], vbv = vb[blk * 64 + o];
    float lwv = l2w[blk * 64 + o], lbv = l2b[blk * 64 + o];
    size_t base = ((size_t)(blk * BATCH + b)) * LSEQ * 64;
    int rbeg = z * 40, rend = rbeg + 40;
    for (int r0 = rbeg; r0 < rend; r0 += 4) {
        int r = r0 + rr;
        bool act = r < LSEQ;
        float ka = kbv, va = vbv;
        if (act) {
#pragma unroll 8
            for (int c = 0; c < 64; c++) {
                float t = tfs[r * 64 + c];
                ka += t * kws[c * 68 + o];
                va += t * vws[c * 68 + o];
            }
            ksm[rr * 64 + o] = ka;
        }
        __syncthreads();
        if (act) {
            float m = 0.f;
#pragma unroll 8
            for (int i = 0; i < 64; i++) m += ksm[rr * 64 + i];
            m *= (1.f / 64.f);
            float vv = 0.f;
#pragma unroll 8
            for (int i = 0; i < 64; i++) { float d = ksm[rr * 64 + i] - m; vv += d * d; }
            vv *= (1.f / 64.f);
            float rs = rsqrtf(vv + 1e-5f);
            g_kn[base + r * 64 + o] = (ka - m) * rs * lwv + lbv;
            g_v [base + r * 64 + o] = va;
        }
        __syncthreads();
    }
}

// ---------------- Tensor-core attention stack: PER-HEAD MMA, 4 rows/CTA ----------------
// dyn smem floats: U1[80*72] | VT[64*104] (slot-indexed) | sF[256*72] | sQ[256*72]
__global__ void __launch_bounds__(512, 1) k_attn_stack(
        const float* __restrict__ qw, const float* __restrict__ qb,
        const float* __restrict__ ow, const float* __restrict__ ob,
        const float* __restrict__ l1w, const float* __restrict__ l1b) {
    extern __shared__ __align__(16) float dyn[];
    float* U1  = dyn;                 // 5760
    float* VT  = U1 + 80 * 72;        // 6656
    float* sF  = VT + 64 * 104;       // 18432
    float* sQ  = sF + 256 * 72;       // 18432

    int b = blockIdx.x >> 4, yp = blockIdx.x & 15;
    int tid = threadIdx.x;
    int w = tid >> 5, lane = tid & 31;
    int g = lane >> 2, tig = lane & 3;
    int wm = w & 7, wn = w >> 3;       // phase B/E mapping (M=256, N split 2)
    int mA = wm * 32 + g;              // phase B/E rows
    int rowA = w * 16 + g;             // attention rows (16/warp)
    const float scale = 0.35355339059327373f;

    // load 4 feat rows -> sF[p][pic(c)]
    for (int idx = tid; idx < 16384; idx += 512) {
        int c = idx >> 8, p = idx & 255;
        int row = p >> 6, xx = p & 63;
        sF[p * 72 + picf(c)] =
            g_feat[(((size_t)b * 64 + c) * 64 + (yp * 4 + row)) * 64 + xx];
    }
    // zero VT pad keys 77..79 for all 64 slots
    if (tid < 192) VT[(tid / 3) * 104 + 77 + (tid % 3)] = 0.f;

#pragma unroll 1
    for (int blk = 0; blk < NBLK; blk++) {
        size_t kvbase = ((size_t)(blk * BATCH + b)) * LSEQ * 64;
        __syncthreads();
        // stage Wq -> U1, V -> VT (slot-indexed), consts -> sF tails
        for (int idx = tid; idx < 4096; idx += 512) {
            int o = idx >> 6, i = idx & 63;
            U1[o * 72 + picf(i)] = to_tf32(qw[blk * 4096 + idx]);
        }
        for (int idx = tid; idx < LSEQ * 64; idx += 512) {
            int l = idx >> 6, c = idx & 63;
            VT[picf(c) * 104 + l] = g_v[kvbase + idx];
        }
        if (tid < 64) {
            int s = picf(tid);
            sF[s * 72 + 64] = qb[blk * 64 + tid];
            sF[s * 72 + 65] = l1w[blk * 64 + tid];
            sF[s * 72 + 66] = l1b[blk * 64 + tid];
            sF[s * 72 + 67] = ob[blk * 64 + tid];
        }
        __syncthreads();

        // ---- phase B: q_raw = sF @ Wq  (M=256, N=64) ----
        {
            float d[2][4][4];
#pragma unroll
            for (int mt = 0; mt < 2; mt++)
#pragma unroll
                for (int nt = 0; nt < 4; nt++)
#pragma unroll
                    for (int e = 0; e < 4; e++) d[mt][nt][e] = 0.f;
#pragma unroll
            for (int ks = 0; ks < 8; ks++) {
                int po = ks * 8 + tig * 2;
                uint32_t A[2][4];
#pragma unroll
                for (int mt = 0; mt < 2; mt++) {
                    float2 lo = *(const float2*)&sF[(mA + mt * 16) * 72 + po];
                    float2 hi = *(const float2*)&sF[(mA + mt * 16 + 8) * 72 + po];
                    A[mt][0] = __float_as_uint(lo.x); A[mt][1] = __float_as_uint(hi.x);
                    A[mt][2] = __float_as_uint(lo.y); A[mt][3] = __float_as_uint(hi.y);
                }
#pragma unroll
                for (int nt = 0; nt < 4; nt++) {
                    int n = wn * 32 + nt * 8 + g;
                    float2 bv = *(const float2*)&U1[n * 72 + po];
                    uint32_t B[2] = { __float_as_uint(bv.x), __float_as_uint(bv.y) };
                    mma_tf32(d[0][nt], A[0], B);
                    mma_tf32(d[1][nt], A[1], B);
                }
            }
#pragma unroll
            for (int mt = 0; mt < 2; mt++)
#pragma unroll
                for (int nt = 0; nt < 4; nt++) {
                    int c0 = wn * 32 + nt * 8 + tig * 2;
                    int s0 = picf(c0), s1 = picf(c0 + 1);
                    float q0 = sF[s0 * 72 + 64], q1 = sF[s1 * 72 + 64];
                    int r0 = mA + mt * 16, r1 = r0 + 8;
                    sQ[r0 * 72 + s0] = d[mt][nt][0] + q0;
                    sQ[r0 * 72 + s1] = d[mt][nt][1] + q1;
                    sQ[r1 * 72 + s0] = d[mt][nt][2] + q0;
                    sQ[r1 * 72 + s1] = d[mt][nt][3] + q1;
                }
        }
        __syncthreads();

        // ---- LN (2 threads per position) + stage K -> U1 (tf32, slot space) ----
        {
            int pp = tid >> 1, j = tid & 1;
            float v[32];
#pragma unroll
            for (int q = 0; q < 8; q++) {
                float4 t = *(const float4*)&sQ[pp * 72 + j * 32 + q * 4];
                v[q * 4 + 0] = t.x; v[q * 4 + 1] = t.y;
                v[q * 4 + 2] = t.z; v[q * 4 + 3] = t.w;
            }
            int xx = pp & 63, yl = pp >> 6;
            float pe = (j == 0) ? (float)xx * (0.05f / 63.f)
                                : (float)(yp * 4 + yl) * (0.05f / 63.f);
            float s = 0.f;
#pragma unroll
            for (int e = 0; e < 32; e++) { v[e] += pe; s += v[e]; }
            s += __shfl_xor_sync(0xffffffffu, s, 1);
            float mean = s * (1.f / 64.f);
            float sq = 0.f;
#pragma unroll
            for (int e = 0; e < 32; e++) { float dl = v[e] - mean; sq += dl * dl; }
            sq += __shfl_xor_sync(0xffffffffu, sq, 1);
            float rs = rsqrtf(sq * (1.f / 64.f) + 1e-5f);
#pragma unroll
            for (int q = 0; q < 8; q++) {
                int s0 = j * 32 + q * 4;
                float4 o;
                o.x = to_tf32((v[q * 4 + 0] - mean) * rs * sF[(s0 + 0) * 72 + 65] + sF[(s0 + 0) * 72 + 66]);
                o.y = to_tf32((v[q * 4 + 1] - mean) * rs * sF[(s0 + 1) * 72 + 65] + sF[(s0 + 1) * 72 + 66]);
                o.z = to_tf32((v[q * 4 + 2] - mean) * rs * sF[(s0 + 2) * 72 + 65] + sF[(s0 + 2) * 72 + 66]);
                o.w = to_tf32((v[q * 4 + 3] - mean) * rs * sF[(s0 + 3) * 72 + 65] + sF[(s0 + 3) * 72 + 66]);
                *(float4*)&sQ[pp * 72 + s0] = o;
            }
        }
        for (int idx = tid; idx < LSEQ * 64; idx += 512) {
            int l = idx >> 6, c = idx & 63;
            U1[l * 72 + picf(c)] = to_tf32(g_kn[kvbase + idx]);
        }
        __syncthreads();

        // ---- attention: per-head MMA (K=8 per head), warp owns 16 rows ----
#pragma unroll 1
        for (int h = 0; h < NHEAD; h++) {
            int hs = h * 8;
            // A: q fragment for this head (one k-step)
            float2 qlo = *(const float2*)&sQ[rowA * 72 + hs + tig * 2];
            float2 qhi = *(const float2*)&sQ[(rowA + 8) * 72 + hs + tig * 2];
            uint32_t Aq[4] = { __float_as_uint(qlo.x), __float_as_uint(qhi.x),
                               __float_as_uint(qlo.y), __float_as_uint(qhi.y) };
            // MMA1: S over 80 keys
            float e[10][4];
#pragma unroll
            for (int nt = 0; nt < 10; nt++) {
                e[nt][0] = e[nt][1] = e[nt][2] = e[nt][3] = 0.f;
                int n = nt * 8 + g;
                float2 kv = *(const float2*)&U1[n * 72 + hs + tig * 2];
                uint32_t B[2] = { __float_as_uint(kv.x), __float_as_uint(kv.y) };
                mma_tf32(e[nt], Aq, B);
            }
            // masked exp + per-row denominators (quad reduce)
            float dlo = 0.f, dhi = 0.f;
#pragma unroll
            for (int nt = 0; nt < 10; nt++) {
                int l0 = nt * 8 + tig * 2, l1 = l0 + 1;
                float e0 = (l0 < LSEQ) ? to_tf32(__expf(e[nt][0] * scale)) : 0.f;
                float e1 = (l1 < LSEQ) ? to_tf32(__expf(e[nt][1] * scale)) : 0.f;
                float e2 = (l0 < LSEQ) ? to_tf32(__expf(e[nt][2] * scale)) : 0.f;
                float e3 = (l1 < LSEQ) ? to_tf32(__expf(e[nt][3] * scale)) : 0.f;
                e[nt][0] = e0; e[nt][1] = e1; e[nt][2] = e2; e[nt][3] = e3;
                dlo += e0 + e1; dhi += e2 + e3;
            }
            dlo += __shfl_xor_sync(0xffffffffu, dlo, 1);
            dlo += __shfl_xor_sync(0xffffffffu, dlo, 2);
            dhi += __shfl_xor_sync(0xffffffffu, dhi, 1);
            dhi += __shfl_xor_sync(0xffffffffu, dhi, 2);
            float ilo = 1.f / dlo, ihi = 1.f / dhi;
            // MMA2: O_h = P_h @ V_h (K=80, N=8)
            float dO[4] = { 0.f, 0.f, 0.f, 0.f };
#pragma unroll
            for (int kt = 0; kt < 10; kt++) {
                uint32_t A2[4] = { __float_as_uint(e[kt][0]), __float_as_uint(e[kt][2]),
                                   __float_as_uint(e[kt][1]), __float_as_uint(e[kt][3]) };
                float2 vv = *(const float2*)&VT[(hs + g) * 104 + kt * 8 + tig * 2];
                uint32_t B[2] = { __float_as_uint(vv.x), __float_as_uint(vv.y) };
                mma_tf32(dO, A2, B);
            }
            sQ[rowA * 72 + hs + tig * 2]       = dO[0] * ilo;
            sQ[rowA * 72 + hs + tig * 2 + 1]   = dO[1] * ilo;
            sQ[(rowA + 8) * 72 + hs + tig * 2]     = dO[2] * ihi;
            sQ[(rowA + 8) * 72 + hs + tig * 2 + 1] = dO[3] * ihi;
        }
        __syncthreads();
        // stage Wo -> U1
        for (int idx = tid; idx < 4096; idx += 512) {
            int o = idx >> 6, i = idx & 63;
            U1[o * 72 + picf(i)] = to_tf32(ow[blk * 4096 + idx]);
        }
        __syncthreads();

        // ---- phase E: out-proj + residual into sF ----
        {
            float d[2][4][4];
#pragma unroll
            for (int mt = 0; mt < 2; mt++)
#pragma unroll
                for (int nt = 0; nt < 4; nt++)
#pragma unroll
                    for (int q = 0; q < 4; q++) d[mt][nt][q] = 0.f;
#pragma unroll
            for (int ks = 0; ks < 8; ks++) {
                int po = ks * 8 + tig * 2;
                uint32_t A[2][4];
#pragma unroll
                for (int mt = 0; mt < 2; mt++) {
                    float2 lo = *(const float2*)&sQ[(mA + mt * 16) * 72 + po];
                    float2 hi = *(const float2*)&sQ[(mA + mt * 16 + 8) * 72 + po];
                    A[mt][0] = __float_as_uint(lo.x); A[mt][1] = __float_as_uint(hi.x);
                    A[mt][2] = __float_as_uint(lo.y); A[mt][3] = __float_as_uint(hi.y);
                }
#pragma unroll
                for (int nt = 0; nt < 4; nt++) {
                    int n = wn * 32 + nt * 8 + g;
                    float2 bv = *(const float2*)&U1[n * 72 + po];
                    uint32_t B[2] = { __float_as_uint(bv.x), __float_as_uint(bv.y) };
                    mma_tf32(d[0][nt], A[0], B);
                    mma_tf32(d[1][nt], A[1], B);
                }
            }
#pragma unroll
            for (int mt = 0; mt < 2; mt++)
#pragma unroll
                for (int nt = 0; nt < 4; nt++) {
                    int c0 = wn * 32 + nt * 8 + tig * 2;
                    int s0 = picf(c0), s1 = picf(c0 + 1);
                    float o0 = sF[s0 * 72 + 67], o1 = sF[s1 * 72 + 67];
                    int r0 = mA + mt * 16, r1 = r0 + 8;
                    sF[r0 * 72 + s0] += d[mt][nt][0] + o0;
                    sF[r0 * 72 + s1] += d[mt][nt][1] + o1;
                    sF[r1 * 72 + s0] += d[mt][nt][2] + o0;
                    sF[r1 * 72 + s1] += d[mt][nt][3] + o1;
                }
        }
    }
    __syncthreads();
    // write final feat rows back (depermute)
    for (int idx = tid; idx < 16384; idx += 512) {
        int c = idx >> 8, p = idx & 255;
        int row = p >> 6, xx = p & 63;
        g_feat[(((size_t)b * 64 + c) * 64 + (yp * 4 + row)) * 64 + xx]
            = sF[p * 72 + picf(c)];
    }
}

// ---------------- TF32 tensor-core up-conv + pixel-shuffle + relu ----------------
__global__ void __launch_bounds__(256, 3) k_upconv_tc(int lvl, int IH, int IW,
                                                      const float* __restrict__ up_b) {
    const float* in   = lvl ? g_u1 : g_feat;
    float*       outp = lvl ? g_u2 : g_u1;
    __shared__ float sA[180 * 72];
    __shared__ float sBT[64 * 72];
    int x0 = blockIdx.x * 16, y0 = blockIdx.y * 8;
    int bz = blockIdx.z; int b = bz >> 2, ocg = bz & 3;
    int tid = threadIdx.x;
    int w = tid >> 5, lane = tid & 31;
    int g = lane >> 2, tig = lane & 3;
    int wm = w & 3, wn = w >> 2;

    for (int idx = tid; idx < 180 * 64; idx += 256) {
        int ic = idx / 180; int sp = idx % 180;
        int r = sp / 18, c = sp % 18;
        int gy = y0 - 1 + r, gx = x0 - 1 + c;
        float v = 0.f;
        if (gy >= 0 && gy < IH && gx >= 0 && gx < IW)
            v = in[(((size_t)b * 64 + ic) * IH + gy) * IW + gx];
        sA[sp * 72 + picf(ic)] = to_tf32(v);
    }

    float d[2][4][4];
#pragma unroll
    for (int nt = 0; nt < 4; nt++) {
        int oc = ocg * 64 + wn * 32 + nt * 8 + tig * 2;
        float b0v = up_b[lvl * 256 + oc];
        float b1v = up_b[lvl * 256 + oc + 1];
#pragma unroll
        for (int mt = 0; mt < 2; mt++) {
            d[mt][nt][0] = b0v; d[mt][nt][1] = b1v;
            d[mt][nt][2] = b0v; d[mt][nt][3] = b1v;
        }
    }

#pragma unroll 1
    for (int t = 0; t < 9; t++) {
        int ky = t / 3, kx = t % 3;
        __syncthreads();
        for (int idx = tid; idx < 4096; idx += 256) {
            int ic = idx & 63, oc = idx >> 6;
            sBT[oc * 72 + picf(ic)] =
                g_wupT[((((lvl * 9 + t) * 4 + ocg) * 64 + oc) * 64) + ic];
        }
        __syncthreads();
        int sp_base[2][2];
#pragma unroll
        for (int mt = 0; mt < 2; mt++) {
            int m_lo = wm * 32 + mt * 16 + g;
            int m_hi = m_lo + 8;
            sp_base[mt][0] = ((m_lo >> 4) + ky) * 18 + (m_lo & 15) + kx;
            sp_base[mt][1] = ((m_hi >> 4) + ky) * 18 + (m_hi & 15) + kx;
        }
#pragma unroll
        for (int ks = 0; ks < 8; ks++) {
            int po = ks * 8 + tig * 2;
            uint32_t A[2][4];
#pragma unroll
            for (int mt = 0; mt < 2; mt++) {
                float2 lo = *(const float2*)&sA[sp_base[mt][0] * 72 + po];
                float2 hi = *(const float2*)&sA[sp_base[mt][1] * 72 + po];
                A[mt][0] = __float_as_uint(lo.x);
                A[mt][1] = __float_as_uint(hi.x);
                A[mt][2] = __float_as_uint(lo.y);
                A[mt][3] = __float_as_uint(hi.y);
            }
            uint32_t Bf[4][2];
#pragma unroll
            for (int nt = 0; nt < 4; nt++) {
                int nc = wn * 32 + nt * 8 + g;
                float2 bv = *(const float2*)&sBT[nc * 72 + po];
                Bf[nt][0] = __float_as_uint(bv.x);
                Bf[nt][1] = __float_as_uint(bv.y);
            }
#pragma unroll
            for (int mt = 0; mt < 2; mt++)
#pragma unroll
                for (int nt = 0; nt < 4; nt++)
                    mma_tf32(d[mt][nt], A[mt], Bf[nt]);
        }
    }

    int OW = IW * 2;
#pragma unroll
    for (int mt = 0; mt < 2; mt++) {
#pragma unroll
        for (int half = 0; half < 2; half++) {
            int m = wm * 32 + mt * 16 + g + half * 8;
            int gy = y0 + (m >> 4), gx = x0 + (m & 15);
#pragma unroll
            for (int nt = 0; nt < 4; nt++) {
                int oc4a = ocg * 64 + wn * 32 + nt * 8 + tig * 2;
                float v0 = d[mt][nt][half * 2 + 0];
                float v1 = d[mt][nt][half * 2 + 1];
                int ca = oc4a >> 2, r1a = (oc4a >> 1) & 1, r2a = oc4a & 1;
                int oc4b = oc4a + 1;
                int cb = oc4b >> 2, r1b = (oc4b >> 1) & 1, r2b = oc4b & 1;
                outp[(((size_t)b * 64 + ca) * (size_t)(IH * 2) + (size_t)(2 * gy + r1a)) * (size_t)OW
                     + 2 * gx + r2a] = fmaxf(v0, 0.f);
                outp[(((size_t)b * 64 + cb) * (size_t)(IH * 2) + (size_t)(2 * gy + r1b)) * (size_t)OW
                     + 2 * gx + r2b] = fmaxf(v1, 0.f);
            }
        }
    }
}

// ---------------- final conv 64->3 at 256x256 ----------------
__global__ void __launch_bounds__(256) k_cl(const float* __restrict__ w,
                                            const float* __restrict__ bias,
                                            float* __restrict__ out) {
    __shared__ float sw[3 * 64 * 9];
    __shared__ float sin_[4][10][132];
    int xbase = blockIdx.x * 128;
    int y0 = blockIdx.y * 8;
    int b = blockIdx.z;
    int tid = threadIdx.x;
    int xg = tid & 31; int yr = tid >> 5;
    int x0 = xg * 4;
    for (int i = tid; i < 1728; i += 256) sw[i] = w[i];
    float acc[3][4];
#pragma unroll
    for (int oc = 0; oc < 3; oc++) {
        float bb = bias[oc];
#pragma unroll
        for (int xi = 0; xi < 4; xi++) acc[oc][xi] = bb;
    }
    for (int ic0 = 0; ic0 < 64; ic0 += 4) {
        __syncthreads();
        for (int idx = tid; idx < 4 * 10 * 130; idx += 256) {
            int c = idx % 130; int r = (idx / 130) % 10; int icc = idx / 1300;
            int gy = y0 - 1 + r, gx = xbase - 1 + c;
            float v = 0.f;
            if (gy >= 0 && gy < 256 && gx >= 0 && gx < 256)
                v = g_u2[(((size_t)b * 64 + ic0 + icc) * 256 + gy) * 256 + gx];
            sin_[icc][r][c] = v;
        }
        __syncthreads();
        for (int icc = 0; icc < 4; icc++) {
#pragma unroll
            for (int ky = 0; ky < 3; ky++) {
                float in6[6];
#pragma unroll
                for (int t = 0; t < 6; t++) in6[t] = sin_[icc][yr + ky][x0 + t];
#pragma unroll
                for (int kx = 0; kx < 3; kx++) {
#pragma unroll
                    for (int oc = 0; oc < 3; oc++) {
                        float wv = sw[(oc * 64 + ic0 + icc) * 9 + ky * 3 + kx];
#pragma unroll
                        for (int xi = 0; xi < 4; xi++)
                            acc[oc][xi] += wv * in6[kx + xi];
                    }
                }
            }
        }
    }
    int gy = y0 + yr, gx0 = xbase + x0;
#pragma unroll
    for (int oc = 0; oc < 3; oc++) {
        float4 v = make_float4(acc[oc][0], acc[oc][1], acc[oc][2], acc[oc][3]);
        *(float4*)&out[(((size_t)b * 3 + oc) * 256 + gy) * 256 + gx0] = v;
    }
}

// ---------------- launcher ----------------
extern "C" void kernel_launch(void* const* d_in, const int* in_sizes, int n_in,
                              void* d_out, int out_size) {
    const float* x      = (const float*)d_in[0];
    const float* th     = (const float*)d_in[1];
    const float* proj_w = (const float*)d_in[2];
    const float* proj_b = (const float*)d_in[3];
    const float* cf_w   = (const float*)d_in[4];
    const float* cf_b   = (const float*)d_in[5];
    const float* qw     = (const float*)d_in[6];
    const float* qb     = (const float*)d_in[7];
    const float* kw     = (const float*)d_in[8];
    const float* kb     = (const float*)d_in[9];
    const float* vw     = (const float*)d_in[10];
    const float* vb     = (const float*)d_in[11];
    const float* ow     = (const float*)d_in[12];
    const float* ob     = (const float*)d_in[13];
    const float* l1w    = (const float*)d_in[14];
    const float* l1b    = (const float*)d_in[15];
    const float* l2w    = (const float*)d_in[16];
    const float* l2b    = (const float*)d_in[17];
    const float* up_w   = (const float*)d_in[18];
    const float* up_b   = (const float*)d_in[19];
    const float* cl_w   = (const float*)d_in[20];
    const float* cl_b   = (const float*)d_in[21];
    float* out = (float*)d_out;

    const int ATTN_SMEM = (80 * 72 + 64 * 104 + 2 * 256 * 72) * 4;  // 197120 B
    cudaFuncSetAttribute(k_attn_stack,
                         cudaFuncAttributeMaxDynamicSharedMemorySize, ATTN_SMEM);

    k_textproj<<<BATCH * LSEQ, 64>>>(th, proj_w, proj_b, up_w);
    k_convin<<<BATCH * HH, 64>>>(x, cf_w, cf_b);
    k_kvall<<<dim3(NBLK, BATCH, 2), 256>>>(kw, kb, vw, vb, l2w, l2b);
    k_attn_stack<<<BATCH * 16, 512, ATTN_SMEM>>>(qw, qb, ow, ob, l1w, l1b);
    k_upconv_tc<<<dim3(4, 8, BATCH * 4), 256>>>(0, 64, 64, up_b);
    k_upconv_tc<<<dim3(8, 16, BATCH * 4), 256>>>(1, 128, 128, up_b);
    k_cl<<<dim3(2, 32, BATCH), 256>>>(cl_w, cl_b, out);

    (void)in_sizes; (void)n_in; (void)out_size;
}

// round 14
// speedup vs baseline: 2.1536x; 1.0372x over previous
#include <cuda_runtime.h>
#include <cuda_bf16.h>
#include <cstdint>

// ---------------- problem constants ----------------
#define BATCH 8
#define CCH   64
#define HH    64
#define WW    64
#define NPOS  4096
#define LSEQ  77
#define DTXT  512
#define NBLK  16
#define NHEAD 8
#define HDIM  8

// ---------------- device scratch ----------------
__device__ float g_tf  [BATCH*LSEQ*CCH];
__device__ float g_kn  [NBLK*BATCH*LSEQ*CCH];   // pic-permuted, tf32
__device__ float g_v   [NBLK*BATCH*LSEQ*CCH];   // pic-permuted
__device__ float g_qwT [NBLK*64*64];            // [blk][o][pic(i)], tf32
__device__ float g_owT [NBLK*64*64];            // [blk][o][pic(i)], tf32
__device__ float g_feat[BATCH*CCH*HH*WW];
__device__ float g_u1  [BATCH*CCH*128*128];
__device__ float g_u2  [(size_t)BATCH*CCH*256*256];
__device__ float g_wupT[2*9*4*64*64];           // [lvl][tap][ocg][oc][ic], tf32

__device__ __forceinline__ float to_tf32(float x) {
    float r; asm("cvt.rna.tf32.f32 %0, %1;" : "=f"(r) : "f"(x)); return r;
}
__device__ __forceinline__ void mma_tf32(float* d, const uint32_t* a, const uint32_t* b) {
    asm volatile(
        "mma.sync.aligned.m16n8k8.row.col.f32.tf32.tf32.f32 "
        "{%0,%1,%2,%3}, {%4,%5,%6,%7}, {%8,%9}, {%0,%1,%2,%3};"
        : "+f"(d[0]), "+f"(d[1]), "+f"(d[2]), "+f"(d[3])
        : "r"(a[0]), "r"(a[1]), "r"(a[2]), "r"(a[3]), "r"(b[0]), "r"(b[1]));
}
// permuted channel index: ic = ks*8 + tig + 4h  ->  pic = ks*8 + tig*2 + h
__device__ __forceinline__ int picf(int ic) {
    int r = ic & 7;
    return (ic & ~7) + ((r & 3) * 2) + (r >> 2);
}

// ---------------- text projection (+ fused weight preps) ----------------
__global__ void k_textproj(const float* __restrict__ th,
                           const float* __restrict__ pw,
                           const float* __restrict__ pb,
                           const float* __restrict__ upw,
                           const float* __restrict__ qw,
                           const float* __restrict__ ow) {
    __shared__ float s[DTXT];
    int bl = blockIdx.x;
    const float* row = th + (size_t)bl * DTXT;
    for (int i = threadIdx.x; i < DTXT; i += 64) s[i] = row[i];
    __syncthreads();
    int c = threadIdx.x;
    const float* w = pw + (size_t)c * DTXT;
    float acc = pb[c];
#pragma unroll 8
    for (int d = 0; d < DTXT; ++d) acc += s[d] * w[d];
    g_tf[bl * CCH + c] = acc;
    // up weights -> [lvl,k,ocg,oc,ic] tf32
    for (int idx = blockIdx.x * 64 + threadIdx.x; idx < 2 * 256 * 64 * 9;
         idx += gridDim.x * 64) {
        int k = idx % 9;
        int t = idx / 9;
        int ic = t % 64; t /= 64;
        int oc4 = t % 256;
        int lvl = t / 256;
        g_wupT[((((lvl * 9 + k) * 4 + (oc4 >> 6)) * 64 + (oc4 & 63)) * 64) + ic]
            = to_tf32(upw[idx]);
    }
    // attn weights -> [blk][o][pic(i)] tf32
    for (int idx = blockIdx.x * 64 + threadIdx.x; idx < NBLK * 4096;
         idx += gridDim.x * 64) {
        int i = idx & 63;
        int base = idx & ~63;
        g_qwT[base + picf(i)] = to_tf32(qw[idx]);
        g_owT[base + picf(i)] = to_tf32(ow[idx]);
    }
}

// ---------------- input conv 3->64, 3x3 ----------------
__global__ void k_convin(const float* __restrict__ x,
                         const float* __restrict__ w,
                         const float* __restrict__ bias) {
    __shared__ float sw[64 * 27];
    __shared__ float sb[64];
    __shared__ float sin_[3][3][66];
    int bid = blockIdx.x; int b = bid >> 6; int y = bid & 63;
    int tid = threadIdx.x;
    for (int i = tid; i < 64 * 27; i += 64) sw[i] = w[i];
    sb[tid] = bias[tid];
    for (int ic = 0; ic < 3; ic++)
        for (int r = 0; r < 3; r++) {
            int yy = y + r - 1;
            float v = 0.f;
            if (yy >= 0 && yy < HH) v = x[(((size_t)b * 3 + ic) * HH + yy) * WW + tid];
            sin_[ic][r][tid + 1] = v;
            if (tid == 0) { sin_[ic][r][0] = 0.f; sin_[ic][r][65] = 0.f; }
        }
    __syncthreads();
    int xx = tid;
    for (int oc = 0; oc < 64; oc++) {
        float acc = sb[oc];
#pragma unroll
        for (int ic = 0; ic < 3; ic++)
#pragma unroll
            for (int r = 0; r < 3; r++)
#pragma unroll
                for (int kx = 0; kx < 3; kx++)
                    acc += sin_[ic][r][xx + kx] * sw[(oc * 3 + ic) * 9 + r * 3 + kx];
        g_feat[(((size_t)b * CCH + oc) * HH + y) * WW + xx] = acc;
    }
}

// ---------------- K/V projection + LN(K); outputs pic-permuted (K tf32) ----------------
__global__ void __launch_bounds__(256) k_kvall(
        const float* __restrict__ kw, const float* __restrict__ kb,
        const float* __restrict__ vw, const float* __restrict__ vb,
        const float* __restrict__ l2w, const float* __restrict__ l2b) {
    __shared__ float tfs[LSEQ * 64];
    __shared__ float kws[64 * 68];
    __shared__ float vws[64 * 68];
    __shared__ float ksm[4 * 64];
    int blk = blockIdx.x, b = blockIdx.y, z = blockIdx.z;
    int tid = threadIdx.x;
    for (int i = tid; i < LSEQ * 64; i += 256) tfs[i] = g_tf[b * LSEQ * 64 + i];
    for (int idx = tid; idx < 4096; idx += 256) {
        int o = idx >> 6, c = idx & 63;
        kws[c * 68 + o] = kw[blk * 4096 + idx];
        vws[c * 68 + o] = vw[blk * 4096 + idx];
    }
    __syncthreads();
    int o = tid & 63, rr = tid >> 6;
    int so = picf(o);
    float kbv = kb[blk * 64 + o], vbv = vb[blk * 64 + o];
    float lwv = l2w[blk * 64 + o], lbv = l2b[blk * 64 + o];
    size_t base = ((size_t)(blk * BATCH + b)) * LSEQ * 64;
    int rbeg = z * 40, rend = rbeg + 40;
    for (int r0 = rbeg; r0 < rend; r0 += 4) {
        int r = r0 + rr;
        bool act = r < LSEQ;
        float ka = kbv, va = vbv;
        if (act) {
#pragma unroll 8
            for (int c = 0; c < 64; c++) {
                float t = tfs[r * 64 + c];
                ka += t * kws[c * 68 + o];
                va += t * vws[c * 68 + o];
            }
            ksm[rr * 64 + o] = ka;
        }
        __syncthreads();
        if (act) {
            float m = 0.f;
#pragma unroll 8
            for (int i = 0; i < 64; i++) m += ksm[rr * 64 + i];
            m *= (1.f / 64.f);
            float vv = 0.f;
#pragma unroll 8
            for (int i = 0; i < 64; i++) { float d = ksm[rr * 64 + i] - m; vv += d * d; }
            vv *= (1.f / 64.f);
            float rs = rsqrtf(vv + 1e-5f);
            g_kn[base + r * 64 + so] = to_tf32((ka - m) * rs * lwv + lbv);
            g_v [base + r * 64 + so] = va;
        }
        __syncthreads();
    }
}

// ---------------- Tensor-core attention stack: per-head MMA, 4 rows/CTA ----------------
// dyn smem floats: U1[80*72] | VT[64*104] | sF[256*72] | sQ[256*72]
__global__ void __launch_bounds__(512, 1) k_attn_stack(
        const float* __restrict__ qb, const float* __restrict__ ob,
        const float* __restrict__ l1w, const float* __restrict__ l1b) {
    extern __shared__ __align__(16) float dyn[];
    float* U1  = dyn;                 // 5760
    float* VT  = U1 + 80 * 72;        // 6656
    float* sF  = VT + 64 * 104;       // 18432
    float* sQ  = sF + 256 * 72;       // 18432

    int b = blockIdx.x >> 4, yp = blockIdx.x & 15;
    int tid = threadIdx.x;
    int w = tid >> 5, lane = tid & 31;
    int g = lane >> 2, tig = lane & 3;
    int wm = w & 7, wn = w >> 3;
    int mA = wm * 32 + g;
    int rowA = w * 16 + g;
    const float scale = 0.35355339059327373f;

    // load 4 feat rows -> sF[p][pic(c)]
    for (int idx = tid; idx < 16384; idx += 512) {
        int c = idx >> 8, p = idx & 255;
        int row = p >> 6, xx = p & 63;
        sF[p * 72 + picf(c)] =
            g_feat[(((size_t)b * 64 + c) * 64 + (yp * 4 + row)) * 64 + xx];
    }
    // zero VT pad keys 77..79 for all 64 slots, and U1 pad rows 77..79
    if (tid < 192) VT[(tid / 3) * 104 + 77 + (tid % 3)] = 0.f;
    if (tid >= 192 && tid < 408) U1[77 * 72 + (tid - 192)] = 0.f;

#pragma unroll 1
    for (int blk = 0; blk < NBLK; blk++) {
        size_t kvbase = ((size_t)(blk * BATCH + b)) * LSEQ * 64;
        __syncthreads();
        // stage Wq -> U1 (float4 copies), V -> VT, consts -> sF tails
        for (int idx = tid; idx < 1024; idx += 512) {
            int o = idx >> 4, j4 = (idx & 15) * 4;
            *(float4*)&U1[o * 72 + j4] = *(const float4*)&g_qwT[blk * 4096 + o * 64 + j4];
        }
        for (int idx = tid; idx < LSEQ * 64; idx += 512) {
            int l = idx >> 6, s = idx & 63;
            VT[s * 104 + l] = g_v[kvbase + idx];
        }
        if (tid < 64) {
            int s = picf(tid);
            sF[s * 72 + 64] = qb[blk * 64 + tid];
            sF[s * 72 + 65] = l1w[blk * 64 + tid];
            sF[s * 72 + 66] = l1b[blk * 64 + tid];
            sF[s * 72 + 67] = ob[blk * 64 + tid];
        }
        __syncthreads();

        // ---- phase B: q_raw = sF @ Wq  (M=256, N=64) ----
        {
            float d[2][4][4];
#pragma unroll
            for (int mt = 0; mt < 2; mt++)
#pragma unroll
                for (int nt = 0; nt < 4; nt++)
#pragma unroll
                    for (int e = 0; e < 4; e++) d[mt][nt][e] = 0.f;
#pragma unroll
            for (int ks = 0; ks < 8; ks++) {
                int po = ks * 8 + tig * 2;
                uint32_t A[2][4];
#pragma unroll
                for (int mt = 0; mt < 2; mt++) {
                    float2 lo = *(const float2*)&sF[(mA + mt * 16) * 72 + po];
                    float2 hi = *(const float2*)&sF[(mA + mt * 16 + 8) * 72 + po];
                    A[mt][0] = __float_as_uint(lo.x); A[mt][1] = __float_as_uint(hi.x);
                    A[mt][2] = __float_as_uint(lo.y); A[mt][3] = __float_as_uint(hi.y);
                }
#pragma unroll
                for (int nt = 0; nt < 4; nt++) {
                    int n = wn * 32 + nt * 8 + g;
                    float2 bv = *(const float2*)&U1[n * 72 + po];
                    uint32_t B[2] = { __float_as_uint(bv.x), __float_as_uint(bv.y) };
                    mma_tf32(d[0][nt], A[0], B);
                    mma_tf32(d[1][nt], A[1], B);
                }
            }
#pragma unroll
            for (int mt = 0; mt < 2; mt++)
#pragma unroll
                for (int nt = 0; nt < 4; nt++) {
                    int c0 = wn * 32 + nt * 8 + tig * 2;
                    int s0 = picf(c0), s1 = picf(c0 + 1);
                    float q0 = sF[s0 * 72 + 64], q1 = sF[s1 * 72 + 64];
                    int r0 = mA + mt * 16, r1 = r0 + 8;
                    sQ[r0 * 72 + s0] = d[mt][nt][0] + q0;
                    sQ[r0 * 72 + s1] = d[mt][nt][1] + q1;
                    sQ[r1 * 72 + s0] = d[mt][nt][2] + q0;
                    sQ[r1 * 72 + s1] = d[mt][nt][3] + q1;
                }
        }
        __syncthreads();

        // ---- LN (2 threads per position) + stage K -> U1 (float copies) ----
        {
            int pp = tid >> 1, j = tid & 1;
            float v[32];
#pragma unroll
            for (int q = 0; q < 8; q++) {
                float4 t = *(const float4*)&sQ[pp * 72 + j * 32 + q * 4];
                v[q * 4 + 0] = t.x; v[q * 4 + 1] = t.y;
                v[q * 4 + 2] = t.z; v[q * 4 + 3] = t.w;
            }
            int xx = pp & 63, yl = pp >> 6;
            float pe = (j == 0) ? (float)xx * (0.05f / 63.f)
                                : (float)(yp * 4 + yl) * (0.05f / 63.f);
            float s = 0.f;
#pragma unroll
            for (int e = 0; e < 32; e++) { v[e] += pe; s += v[e]; }
            s += __shfl_xor_sync(0xffffffffu, s, 1);
            float mean = s * (1.f / 64.f);
            float sq = 0.f;
#pragma unroll
            for (int e = 0; e < 32; e++) { float dl = v[e] - mean; sq += dl * dl; }
            sq += __shfl_xor_sync(0xffffffffu, sq, 1);
            float rs = rsqrtf(sq * (1.f / 64.f) + 1e-5f);
#pragma unroll
            for (int q = 0; q < 8; q++) {
                int s0 = j * 32 + q * 4;
                float4 o;
                o.x = to_tf32((v[q * 4 + 0] - mean) * rs * sF[(s0 + 0) * 72 + 65] + sF[(s0 + 0) * 72 + 66]);
                o.y = to_tf32((v[q * 4 + 1] - mean) * rs * sF[(s0 + 1) * 72 + 65] + sF[(s0 + 1) * 72 + 66]);
                o.z = to_tf32((v[q * 4 + 2] - mean) * rs * sF[(s0 + 2) * 72 + 65] + sF[(s0 + 2) * 72 + 66]);
                o.w = to_tf32((v[q * 4 + 3] - mean) * rs * sF[(s0 + 3) * 72 + 65] + sF[(s0 + 3) * 72 + 66]);
                *(float4*)&sQ[pp * 72 + s0] = o;
            }
        }
        for (int idx = tid; idx < LSEQ * 16; idx += 512) {
            int l = idx >> 4, j4 = (idx & 15) * 4;
            *(float4*)&U1[l * 72 + j4] = *(const float4*)&g_kn[kvbase + l * 64 + j4];
        }
        __syncthreads();

        // ---- attention: per-head MMA, unmasked (pads exact: e=1, V=0, den-=3) ----
#pragma unroll 1
        for (int h = 0; h < NHEAD; h++) {
            int hs = h * 8;
            float2 qlo = *(const float2*)&sQ[rowA * 72 + hs + tig * 2];
            float2 qhi = *(const float2*)&sQ[(rowA + 8) * 72 + hs + tig * 2];
            uint32_t Aq[4] = { __float_as_uint(qlo.x), __float_as_uint(qhi.x),
                               __float_as_uint(qlo.y), __float_as_uint(qhi.y) };
            float e[10][4];
#pragma unroll
            for (int nt = 0; nt < 10; nt++) {
                e[nt][0] = e[nt][1] = e[nt][2] = e[nt][3] = 0.f;
                int n = nt * 8 + g;
                float2 kv = *(const float2*)&U1[n * 72 + hs + tig * 2];
                uint32_t B[2] = { __float_as_uint(kv.x), __float_as_uint(kv.y) };
                mma_tf32(e[nt], Aq, B);
            }
            float dlo = 0.f, dhi = 0.f;
#pragma unroll
            for (int nt = 0; nt < 10; nt++) {
                float e0 = to_tf32(__expf(e[nt][0] * scale));
                float e1 = to_tf32(__expf(e[nt][1] * scale));
                float e2 = to_tf32(__expf(e[nt][2] * scale));
                float e3 = to_tf32(__expf(e[nt][3] * scale));
                e[nt][0] = e0; e[nt][1] = e1; e[nt][2] = e2; e[nt][3] = e3;
                dlo += e0 + e1; dhi += e2 + e3;
            }
            dlo += __shfl_xor_sync(0xffffffffu, dlo, 1);
            dlo += __shfl_xor_sync(0xffffffffu, dlo, 2);
            dhi += __shfl_xor_sync(0xffffffffu, dhi, 1);
            dhi += __shfl_xor_sync(0xffffffffu, dhi, 2);
            float ilo = 1.f / (dlo - 3.f), ihi = 1.f / (dhi - 3.f);
            float dO[4] = { 0.f, 0.f, 0.f, 0.f };
#pragma unroll
            for (int kt = 0; kt < 10; kt++) {
                uint32_t A2[4] = { __float_as_uint(e[kt][0]), __float_as_uint(e[kt][2]),
                                   __float_as_uint(e[kt][1]), __float_as_uint(e[kt][3]) };
                float2 vv = *(const float2*)&VT[(hs + g) * 104 + kt * 8 + tig * 2];
                uint32_t B[2] = { __float_as_uint(vv.x), __float_as_uint(vv.y) };
                mma_tf32(dO, A2, B);
            }
            sQ[rowA * 72 + hs + tig * 2]       = dO[0] * ilo;
            sQ[rowA * 72 + hs + tig * 2 + 1]   = dO[1] * ilo;
            sQ[(rowA + 8) * 72 + hs + tig * 2]     = dO[2] * ihi;
            sQ[(rowA + 8) * 72 + hs + tig * 2 + 1] = dO[3] * ihi;
        }
        __syncthreads();
        // stage Wo -> U1 (float4 copies)
        for (int idx = tid; idx < 1024; idx += 512) {
            int o = idx >> 4, j4 = (idx & 15) * 4;
            *(float4*)&U1[o * 72 + j4] = *(const float4*)&g_owT[blk * 4096 + o * 64 + j4];
        }
        __syncthreads();

        // ---- phase E: out-proj + residual into sF ----
        {
            float d[2][4][4];
#pragma unroll
            for (int mt = 0; mt < 2; mt++)
#pragma unroll
                for (int nt = 0; nt < 4; nt++)
#pragma unroll
                    for (int q = 0; q < 4; q++) d[mt][nt][q] = 0.f;
#pragma unroll
            for (int ks = 0; ks < 8; ks++) {
                int po = ks * 8 + tig * 2;
                uint32_t A[2][4];
#pragma unroll
                for (int mt = 0; mt < 2; mt++) {
                    float2 lo = *(const float2*)&sQ[(mA + mt * 16) * 72 + po];
                    float2 hi = *(const float2*)&sQ[(mA + mt * 16 + 8) * 72 + po];
                    A[mt][0] = __float_as_uint(lo.x); A[mt][1] = __float_as_uint(hi.x);
                    A[mt][2] = __float_as_uint(lo.y); A[mt][3] = __float_as_uint(hi.y);
                }
#pragma unroll
                for (int nt = 0; nt < 4; nt++) {
                    int n = wn * 32 + nt * 8 + g;
                    float2 bv = *(const float2*)&U1[n * 72 + po];
                    uint32_t B[2] = { __float_as_uint(bv.x), __float_as_uint(bv.y) };
                    mma_tf32(d[0][nt], A[0], B);
                    mma_tf32(d[1][nt], A[1], B);
                }
            }
#pragma unroll
            for (int mt = 0; mt < 2; mt++)
#pragma unroll
                for (int nt = 0; nt < 4; nt++) {
                    int c0 = wn * 32 + nt * 8 + tig * 2;
                    int s0 = picf(c0), s1 = picf(c0 + 1);
                    float o0 = sF[s0 * 72 + 67], o1 = sF[s1 * 72 + 67];
                    int r0 = mA + mt * 16, r1 = r0 + 8;
                    sF[r0 * 72 + s0] += d[mt][nt][0] + o0;
                    sF[r0 * 72 + s1] += d[mt][nt][1] + o1;
                    sF[r1 * 72 + s0] += d[mt][nt][2] + o0;
                    sF[r1 * 72 + s1] += d[mt][nt][3] + o1;
                }
        }
    }
    __syncthreads();
    for (int idx = tid; idx < 16384; idx += 512) {
        int c = idx >> 8, p = idx & 255;
        int row = p >> 6, xx = p & 63;
        g_feat[(((size_t)b * 64 + c) * 64 + (yp * 4 + row)) * 64 + xx]
            = sF[p * 72 + picf(c)];
    }
}

// ---------------- TF32 tensor-core up-conv + pixel-shuffle + relu ----------------
__global__ void __launch_bounds__(256, 3) k_upconv_tc(int lvl, int IH, int IW,
                                                      const float* __restrict__ up_b) {
    const float* in   = lvl ? g_u1 : g_feat;
    float*       outp = lvl ? g_u2 : g_u1;
    __shared__ float sA[180 * 72];
    __shared__ float sBT[64 * 72];
    int x0 = blockIdx.x * 16, y0 = blockIdx.y * 8;
    int bz = blockIdx.z; int b = bz >> 2, ocg = bz & 3;
    int tid = threadIdx.x;
    int w = tid >> 5, lane = tid & 31;
    int g = lane >> 2, tig = lane & 3;
    int wm = w & 3, wn = w >> 2;

    for (int idx = tid; idx < 180 * 64; idx += 256) {
        int ic = idx / 180; int sp = idx % 180;
        int r = sp / 18, c = sp % 18;
        int gy = y0 - 1 + r, gx = x0 - 1 + c;
        float v = 0.f;
        if (gy >= 0 && gy < IH && gx >= 0 && gx < IW)
            v = in[(((size_t)b * 64 + ic) * IH + gy) * IW + gx];
        sA[sp * 72 + picf(ic)] = to_tf32(v);
    }

    float d[2][4][4];
#pragma unroll
    for (int nt = 0; nt < 4; nt++) {
        int oc = ocg * 64 + wn * 32 + nt * 8 + tig * 2;
        float b0v = up_b[lvl * 256 + oc];
        float b1v = up_b[lvl * 256 + oc + 1];
#pragma unroll
        for (int mt = 0; mt < 2; mt++) {
            d[mt][nt][0] = b0v; d[mt][nt][1] = b1v;
            d[mt][nt][2] = b0v; d[mt][nt][3] = b1v;
        }
    }

#pragma unroll 1
    for (int t = 0; t < 9; t++) {
        int ky = t / 3, kx = t % 3;
        __syncthreads();
        for (int idx = tid; idx < 4096; idx += 256) {
            int ic = idx & 63, oc = idx >> 6;
            sBT[oc * 72 + picf(ic)] =
                g_wupT[((((lvl * 9 + t) * 4 + ocg) * 64 + oc) * 64) + ic];
        }
        __syncthreads();
        int sp_base[2][2];
#pragma unroll
        for (int mt = 0; mt < 2; mt++) {
            int m_lo = wm * 32 + mt * 16 + g;
            int m_hi = m_lo + 8;
            sp_base[mt][0] = ((m_lo >> 4) + ky) * 18 + (m_lo & 15) + kx;
            sp_base[mt][1] = ((m_hi >> 4) + ky) * 18 + (m_hi & 15) + kx;
        }
#pragma unroll
        for (int ks = 0; ks < 8; ks++) {
            int po = ks * 8 + tig * 2;
            uint32_t A[2][4];
#pragma unroll
            for (int mt = 0; mt < 2; mt++) {
                float2 lo = *(const float2*)&sA[sp_base[mt][0] * 72 + po];
                float2 hi = *(const float2*)&sA[sp_base[mt][1] * 72 + po];
                A[mt][0] = __float_as_uint(lo.x);
                A[mt][1] = __float_as_uint(hi.x);
                A[mt][2] = __float_as_uint(lo.y);
                A[mt][3] = __float_as_uint(hi.y);
            }
            uint32_t Bf[4][2];
#pragma unroll
            for (int nt = 0; nt < 4; nt++) {
                int nc = wn * 32 + nt * 8 + g;
                float2 bv = *(const float2*)&sBT[nc * 72 + po];
                Bf[nt][0] = __float_as_uint(bv.x);
                Bf[nt][1] = __float_as_uint(bv.y);
            }
#pragma unroll
            for (int mt = 0; mt < 2; mt++)
#pragma unroll
                for (int nt = 0; nt < 4; nt++)
                    mma_tf32(d[mt][nt], A[mt], Bf[nt]);
        }
    }

    int OW = IW * 2;
#pragma unroll
    for (int mt = 0; mt < 2; mt++) {
#pragma unroll
        for (int half = 0; half < 2; half++) {
            int m = wm * 32 + mt * 16 + g + half * 8;
            int gy = y0 + (m >> 4), gx = x0 + (m & 15);
#pragma unroll
            for (int nt = 0; nt < 4; nt++) {
                int oc4a = ocg * 64 + wn * 32 + nt * 8 + tig * 2;
                float v0 = d[mt][nt][half * 2 + 0];
                float v1 = d[mt][nt][half * 2 + 1];
                int ca = oc4a >> 2, r1a = (oc4a >> 1) & 1, r2a = oc4a & 1;
                int oc4b = oc4a + 1;
                int cb = oc4b >> 2, r1b = (oc4b >> 1) & 1, r2b = oc4b & 1;
                outp[(((size_t)b * 64 + ca) * (size_t)(IH * 2) + (size_t)(2 * gy + r1a)) * (size_t)OW
                     + 2 * gx + r2a] = fmaxf(v0, 0.f);
                outp[(((size_t)b * 64 + cb) * (size_t)(IH * 2) + (size_t)(2 * gy + r1b)) * (size_t)OW
                     + 2 * gx + r2b] = fmaxf(v1, 0.f);
            }
        }
    }
}

// ---------------- final conv 64->3 at 256x256 ----------------
__global__ void __launch_bounds__(256) k_cl(const float* __restrict__ w,
                                            const float* __restrict__ bias,
                                            float* __restrict__ out) {
    __shared__ float sw[3 * 64 * 9];
    __shared__ float sin_[4][10][132];
    int xbase = blockIdx.x * 128;
    int y0 = blockIdx.y * 8;
    int b = blockIdx.z;
    int tid = threadIdx.x;
    int xg = tid & 31; int yr = tid >> 5;
    int x0 = xg * 4;
    for (int i = tid; i < 1728; i += 256) sw[i] = w[i];
    float acc[3][4];
#pragma unroll
    for (int oc = 0; oc < 3; oc++) {
        float bb = bias[oc];
#pragma unroll
        for (int xi = 0; xi < 4; xi++) acc[oc][xi] = bb;
    }
    for (int ic0 = 0; ic0 < 64; ic0 += 4) {
        __syncthreads();
        for (int idx = tid; idx < 4 * 10 * 130; idx += 256) {
            int c = idx % 130; int r = (idx / 130) % 10; int icc = idx / 1300;
            int gy = y0 - 1 + r, gx = xbase - 1 + c;
            float v = 0.f;
            if (gy >= 0 && gy < 256 && gx >= 0 && gx < 256)
                v = g_u2[(((size_t)b * 64 + ic0 + icc) * 256 + gy) * 256 + gx];
            sin_[icc][r][c] = v;
        }
        __syncthreads();
        for (int icc = 0; icc < 4; icc++) {
#pragma unroll
            for (int ky = 0; ky < 3; ky++) {
                float in6[6];
#pragma unroll
                for (int t = 0; t < 6; t++) in6[t] = sin_[icc][yr + ky][x0 + t];
#pragma unroll
                for (int kx = 0; kx < 3; kx++) {
#pragma unroll
                    for (int oc = 0; oc < 3; oc++) {
                        float wv = sw[(oc * 64 + ic0 + icc) * 9 + ky * 3 + kx];
#pragma unroll
                        for (int xi = 0; xi < 4; xi++)
                            acc[oc][xi] += wv * in6[kx + xi];
                    }
                }
            }
        }
    }
    int gy = y0 + yr, gx0 = xbase + x0;
#pragma unroll
    for (int oc = 0; oc < 3; oc++) {
        float4 v = make_float4(acc[oc][0], acc[oc][1], acc[oc][2], acc[oc][3]);
        *(float4*)&out[(((size_t)b * 3 + oc) * 256 + gy) * 256 + gx0] = v;
    }
}

// ---------------- launcher ----------------
extern "C" void kernel_launch(void* const* d_in, const int* in_sizes, int n_in,
                              void* d_out, int out_size) {
    const float* x      = (const float*)d_in[0];
    const float* th     = (const float*)d_in[1];
    const float* proj_w = (const float*)d_in[2];
    const float* proj_b = (const float*)d_in[3];
    const float* cf_w   = (const float*)d_in[4];
    const float* cf_b   = (const float*)d_in[5];
    const float* qw     = (const float*)d_in[6];
    const float* qb     = (const float*)d_in[7];
    const float* kw     = (const float*)d_in[8];
    const float* kb     = (const float*)d_in[9];
    const float* vw     = (const float*)d_in[10];
    const float* vb     = (const float*)d_in[11];
    const float* ow     = (const float*)d_in[12];
    const float* ob     = (const float*)d_in[13];
    const float* l1w    = (const float*)d_in[14];
    const float* l1b    = (const float*)d_in[15];
    const float* l2w    = (const float*)d_in[16];
    const float* l2b    = (const float*)d_in[17];
    const float* up_w   = (const float*)d_in[18];
    const float* up_b   = (const float*)d_in[19];
    const float* cl_w   = (const float*)d_in[20];
    const float* cl_b   = (const float*)d_in[21];
    float* out = (float*)d_out;

    const int ATTN_SMEM = (80 * 72 + 64 * 104 + 2 * 256 * 72) * 4;  // 197120 B
    cudaFuncSetAttribute(k_attn_stack,
                         cudaFuncAttributeMaxDynamicSharedMemorySize, ATTN_SMEM);

    k_textproj<<<BATCH * LSEQ, 64>>>(th, proj_w, proj_b, up_w, qw, ow);
    k_convin<<<BATCH * HH, 64>>>(x, cf_w, cf_b);
    k_kvall<<<dim3(NBLK, BATCH, 2), 256>>>(kw, kb, vw, vb, l2w, l2b);
    k_attn_stack<<<BATCH * 16, 512, ATTN_SMEM>>>(qb, ob, l1w, l1b);
    k_upconv_tc<<<dim3(4, 8, BATCH * 4), 256>>>(0, 64, 64, up_b);
    k_upconv_tc<<<dim3(8, 16, BATCH * 4), 256>>>(1, 128, 128, up_b);
    k_cl<<<dim3(2, 32, BATCH), 256>>>(cl_w, cl_b, out);

    (void)in_sizes; (void)n_in; (void)out_size;
}

// round 15
// speedup vs baseline: 2.2112x; 1.0268x over previous
#include <cuda_runtime.h>
#include <cuda_bf16.h>
#include <cstdint>

// ---------------- problem constants ----------------
#define BATCH 8
#define CCH   64
#define HH    64
#define WW    64
#define NPOS  4096
#define LSEQ  77
#define DTXT  512
#define NBLK  16
#define NHEAD 8
#define HDIM  8

// ---------------- device scratch ----------------
__device__ float g_tf  [BATCH*LSEQ*CCH];
__device__ float g_kn  [NBLK*BATCH*LSEQ*CCH];   // pic-permuted, tf32
__device__ float g_v   [NBLK*BATCH*LSEQ*CCH];   // pic-permuted
__device__ float g_qwT [NBLK*64*64];            // [blk][o][pic(i)], tf32
__device__ float g_owT [NBLK*64*64];            // [blk][o][pic(i)], tf32
__device__ float g_feat[BATCH*CCH*HH*WW];
__device__ float g_u1  [BATCH*CCH*128*128];
__device__ float g_u2  [(size_t)BATCH*CCH*256*256];
__device__ float g_wupT[2*9*4*64*64];           // [lvl][tap][ocg][oc][ic], tf32

__device__ __forceinline__ float to_tf32(float x) {
    float r; asm("cvt.rna.tf32.f32 %0, %1;" : "=f"(r) : "f"(x)); return r;
}
__device__ __forceinline__ void mma_tf32(float* d, const uint32_t* a, const uint32_t* b) {
    asm volatile(
        "mma.sync.aligned.m16n8k8.row.col.f32.tf32.tf32.f32 "
        "{%0,%1,%2,%3}, {%4,%5,%6,%7}, {%8,%9}, {%0,%1,%2,%3};"
        : "+f"(d[0]), "+f"(d[1]), "+f"(d[2]), "+f"(d[3])
        : "r"(a[0]), "r"(a[1]), "r"(a[2]), "r"(a[3]), "r"(b[0]), "r"(b[1]));
}
// permuted channel index: ic = ks*8 + tig + 4h  ->  pic = ks*8 + tig*2 + h
__device__ __forceinline__ int picf(int ic) {
    int r = ic & 7;
    return (ic & ~7) + ((r & 3) * 2) + (r >> 2);
}

// ---------------- text projection (+ fused weight preps) ----------------
__global__ void k_textproj(const float* __restrict__ th,
                           const float* __restrict__ pw,
                           const float* __restrict__ pb,
                           const float* __restrict__ upw,
                           const float* __restrict__ qw,
                           const float* __restrict__ ow) {
    __shared__ float s[DTXT];
    int bl = blockIdx.x;
    const float* row = th + (size_t)bl * DTXT;
    for (int i = threadIdx.x; i < DTXT; i += 64) s[i] = row[i];
    __syncthreads();
    int c = threadIdx.x;
    const float* w = pw + (size_t)c * DTXT;
    float acc = pb[c];
#pragma unroll 8
    for (int d = 0; d < DTXT; ++d) acc += s[d] * w[d];
    g_tf[bl * CCH + c] = acc;
    for (int idx = blockIdx.x * 64 + threadIdx.x; idx < 2 * 256 * 64 * 9;
         idx += gridDim.x * 64) {
        int k = idx % 9;
        int t = idx / 9;
        int ic = t % 64; t /= 64;
        int oc4 = t % 256;
        int lvl = t / 256;
        g_wupT[((((lvl * 9 + k) * 4 + (oc4 >> 6)) * 64 + (oc4 & 63)) * 64) + ic]
            = to_tf32(upw[idx]);
    }
    for (int idx = blockIdx.x * 64 + threadIdx.x; idx < NBLK * 4096;
         idx += gridDim.x * 64) {
        int i = idx & 63;
        int base = idx & ~63;
        g_qwT[base + picf(i)] = to_tf32(qw[idx]);
        g_owT[base + picf(i)] = to_tf32(ow[idx]);
    }
}

// ---------------- input conv 3->64, 3x3 (256 threads) ----------------
__global__ void __launch_bounds__(256) k_convin(const float* __restrict__ x,
                                                const float* __restrict__ w,
                                                const float* __restrict__ bias) {
    __shared__ float sw[64 * 27];
    __shared__ float sb[64];
    __shared__ float sin_[3][3][66];
    int bid = blockIdx.x; int b = bid >> 6; int y = bid & 63;
    int tid = threadIdx.x;
    for (int i = tid; i < 64 * 27; i += 256) sw[i] = w[i];
    if (tid < 64) sb[tid] = bias[tid];
    for (int idx = tid; idx < 9 * 66; idx += 256) {
        int c = idx % 66; int t = idx / 66;
        int ic = t / 3, r = t % 3;
        int yy = y + r - 1, xx = c - 1;
        float v = 0.f;
        if (yy >= 0 && yy < HH && xx >= 0 && xx < WW)
            v = x[(((size_t)b * 3 + ic) * HH + yy) * WW + xx];
        sin_[ic][r][c] = v;
    }
    __syncthreads();
    int xx = tid & 63, oq = tid >> 6;   // 16 oc per thread
    for (int oj = 0; oj < 16; oj++) {
        int oc = oq * 16 + oj;
        float acc = sb[oc];
#pragma unroll
        for (int ic = 0; ic < 3; ic++)
#pragma unroll
            for (int r = 0; r < 3; r++)
#pragma unroll
                for (int kx = 0; kx < 3; kx++)
                    acc += sin_[ic][r][xx + kx] * sw[(oc * 3 + ic) * 9 + r * 3 + kx];
        g_feat[(((size_t)b * CCH + oc) * HH + y) * WW + xx] = acc;
    }
}

// ---------------- K/V projection + LN(K); outputs pic-permuted (K tf32) ----------------
__global__ void __launch_bounds__(256) k_kvall(
        const float* __restrict__ kw, const float* __restrict__ kb,
        const float* __restrict__ vw, const float* __restrict__ vb,
        const float* __restrict__ l2w, const float* __restrict__ l2b) {
    __shared__ float tfs[LSEQ * 64];
    __shared__ float kws[64 * 68];
    __shared__ float vws[64 * 68];
    __shared__ float ksm[4 * 64];
    int blk = blockIdx.x, b = blockIdx.y, z = blockIdx.z;
    int tid = threadIdx.x;
    for (int i = tid; i < LSEQ * 64; i += 256) tfs[i] = g_tf[b * LSEQ * 64 + i];
    for (int idx = tid; idx < 4096; idx += 256) {
        int o = idx >> 6, c = idx & 63;
        kws[c * 68 + o] = kw[blk * 4096 + idx];
        vws[c * 68 + o] = vw[blk * 4096 + idx];
    }
    __syncthreads();
    int o = tid & 63, rr = tid >> 6;
    int so = picf(o);
    float kbv = kb[blk * 64 + o], vbv = vb[blk * 64 + o];
    float lwv = l2w[blk * 64 + o], lbv = l2b[blk * 64 + o];
    size_t base = ((size_t)(blk * BATCH + b)) * LSEQ * 64;
    int rbeg = z * 40, rend = rbeg + 40;
    for (int r0 = rbeg; r0 < rend; r0 += 4) {
        int r = r0 + rr;
        bool act = r < LSEQ;
        float ka = kbv, va = vbv;
        if (act) {
#pragma unroll 8
            for (int c = 0; c < 64; c++) {
                float t = tfs[r * 64 + c];
                ka += t * kws[c * 68 + o];
                va += t * vws[c * 68 + o];
            }
            ksm[rr * 64 + o] = ka;
        }
        __syncthreads();
        if (act) {
            float m = 0.f;
#pragma unroll 8
            for (int i = 0; i < 64; i++) m += ksm[rr * 64 + i];
            m *= (1.f / 64.f);
            float vv = 0.f;
#pragma unroll 8
            for (int i = 0; i < 64; i++) { float d = ksm[rr * 64 + i] - m; vv += d * d; }
            vv *= (1.f / 64.f);
            float rs = rsqrtf(vv + 1e-5f);
            g_kn[base + r * 64 + so] = to_tf32((ka - m) * rs * lwv + lbv);
            g_v [base + r * 64 + so] = va;
        }
        __syncthreads();
    }
}

// ---------------- Tensor-core attention stack: per-head MMA, 4 rows/CTA ----------------
// Logit scale*log2(e) folded into LN affine -> exp2f only.
__global__ void __launch_bounds__(512, 1) k_attn_stack(
        const float* __restrict__ qb, const float* __restrict__ ob,
        const float* __restrict__ l1w, const float* __restrict__ l1b) {
    extern __shared__ __align__(16) float dyn[];
    float* U1  = dyn;                 // 80*72
    float* VT  = U1 + 80 * 72;        // 64*104
    float* sF  = VT + 64 * 104;       // 256*72
    float* sQ  = sF + 256 * 72;       // 256*72

    int b = blockIdx.x >> 4, yp = blockIdx.x & 15;
    int tid = threadIdx.x;
    int w = tid >> 5, lane = tid & 31;
    int g = lane >> 2, tig = lane & 3;
    int wm = w & 7, wn = w >> 3;
    int mA = wm * 32 + g;
    int rowA = w * 16 + g;
    const float SC = 0.35355339059327373f * 1.4426950408889634f;  // scale*log2(e)

    for (int idx = tid; idx < 16384; idx += 512) {
        int c = idx >> 8, p = idx & 255;
        int row = p >> 6, xx = p & 63;
        sF[p * 72 + picf(c)] =
            g_feat[(((size_t)b * 64 + c) * 64 + (yp * 4 + row)) * 64 + xx];
    }
    if (tid < 192) VT[(tid / 3) * 104 + 77 + (tid % 3)] = 0.f;
    if (tid >= 192 && tid < 408) U1[77 * 72 + (tid - 192)] = 0.f;

    // hoisted attention base pointers
    float* sQa = &sQ[rowA * 72 + tig * 2];
    float* sQb = &sQ[(rowA + 8) * 72 + tig * 2];
    const float* U1a = &U1[g * 72 + tig * 2];
    const float* VTa = &VT[g * 104 + tig * 2];

#pragma unroll 1
    for (int blk = 0; blk < NBLK; blk++) {
        size_t kvbase = ((size_t)(blk * BATCH + b)) * LSEQ * 64;
        __syncthreads();
        for (int idx = tid; idx < 1024; idx += 512) {
            int o = idx >> 4, j4 = (idx & 15) * 4;
            *(float4*)&U1[o * 72 + j4] = *(const float4*)&g_qwT[blk * 4096 + o * 64 + j4];
        }
        for (int idx = tid; idx < LSEQ * 64; idx += 512) {
            int l = idx >> 6, s = idx & 63;
            VT[s * 104 + l] = g_v[kvbase + idx];
        }
        if (tid < 64) {
            int s = picf(tid);
            sF[s * 72 + 64] = qb[blk * 64 + tid];
            sF[s * 72 + 65] = l1w[blk * 64 + tid] * SC;
            sF[s * 72 + 66] = l1b[blk * 64 + tid] * SC;
            sF[s * 72 + 67] = ob[blk * 64 + tid];
        }
        __syncthreads();

        // ---- phase B: q_raw = sF @ Wq ----
        {
            float d[2][4][4];
#pragma unroll
            for (int mt = 0; mt < 2; mt++)
#pragma unroll
                for (int nt = 0; nt < 4; nt++)
#pragma unroll
                    for (int e = 0; e < 4; e++) d[mt][nt][e] = 0.f;
#pragma unroll
            for (int ks = 0; ks < 8; ks++) {
                int po = ks * 8 + tig * 2;
                uint32_t A[2][4];
#pragma unroll
                for (int mt = 0; mt < 2; mt++) {
                    float2 lo = *(const float2*)&sF[(mA + mt * 16) * 72 + po];
                    float2 hi = *(const float2*)&sF[(mA + mt * 16 + 8) * 72 + po];
                    A[mt][0] = __float_as_uint(lo.x); A[mt][1] = __float_as_uint(hi.x);
                    A[mt][2] = __float_as_uint(lo.y); A[mt][3] = __float_as_uint(hi.y);
                }
#pragma unroll
                for (int nt = 0; nt < 4; nt++) {
                    int n = wn * 32 + nt * 8 + g;
                    float2 bv = *(const float2*)&U1[n * 72 + po];
                    uint32_t B[2] = { __float_as_uint(bv.x), __float_as_uint(bv.y) };
                    mma_tf32(d[0][nt], A[0], B);
                    mma_tf32(d[1][nt], A[1], B);
                }
            }
#pragma unroll
            for (int mt = 0; mt < 2; mt++)
#pragma unroll
                for (int nt = 0; nt < 4; nt++) {
                    int c0 = wn * 32 + nt * 8 + tig * 2;
                    int s0 = picf(c0), s1 = picf(c0 + 1);
                    float q0 = sF[s0 * 72 + 64], q1 = sF[s1 * 72 + 64];
                    int r0 = mA + mt * 16, r1 = r0 + 8;
                    sQ[r0 * 72 + s0] = d[mt][nt][0] + q0;
                    sQ[r0 * 72 + s1] = d[mt][nt][1] + q1;
                    sQ[r1 * 72 + s0] = d[mt][nt][2] + q0;
                    sQ[r1 * 72 + s1] = d[mt][nt][3] + q1;
                }
        }
        __syncthreads();

        // ---- LN (pre-scaled by SC) + stage K ----
        {
            int pp = tid >> 1, j = tid & 1;
            float v[32];
#pragma unroll
            for (int q = 0; q < 8; q++) {
                float4 t = *(const float4*)&sQ[pp * 72 + j * 32 + q * 4];
                v[q * 4 + 0] = t.x; v[q * 4 + 1] = t.y;
                v[q * 4 + 2] = t.z; v[q * 4 + 3] = t.w;
            }
            int xx = pp & 63, yl = pp >> 6;
            float pe = (j == 0) ? (float)xx * (0.05f / 63.f)
                                : (float)(yp * 4 + yl) * (0.05f / 63.f);
            float s = 0.f;
#pragma unroll
            for (int e = 0; e < 32; e++) { v[e] += pe; s += v[e]; }
            s += __shfl_xor_sync(0xffffffffu, s, 1);
            float mean = s * (1.f / 64.f);
            float sq = 0.f;
#pragma unroll
            for (int e = 0; e < 32; e++) { float dl = v[e] - mean; sq += dl * dl; }
            sq += __shfl_xor_sync(0xffffffffu, sq, 1);
            float rs = rsqrtf(sq * (1.f / 64.f) + 1e-5f);
#pragma unroll
            for (int q = 0; q < 8; q++) {
                int s0 = j * 32 + q * 4;
                float4 o;
                o.x = to_tf32((v[q * 4 + 0] - mean) * rs * sF[(s0 + 0) * 72 + 65] + sF[(s0 + 0) * 72 + 66]);
                o.y = to_tf32((v[q * 4 + 1] - mean) * rs * sF[(s0 + 1) * 72 + 65] + sF[(s0 + 1) * 72 + 66]);
                o.z = to_tf32((v[q * 4 + 2] - mean) * rs * sF[(s0 + 2) * 72 + 65] + sF[(s0 + 2) * 72 + 66]);
                o.w = to_tf32((v[q * 4 + 3] - mean) * rs * sF[(s0 + 3) * 72 + 65] + sF[(s0 + 3) * 72 + 66]);
                *(float4*)&sQ[pp * 72 + s0] = o;
            }
        }
        for (int idx = tid; idx < LSEQ * 16; idx += 512) {
            int l = idx >> 4, j4 = (idx & 15) * 4;
            *(float4*)&U1[l * 72 + j4] = *(const float4*)&g_kn[kvbase + l * 64 + j4];
        }
        __syncthreads();

        // ---- attention: per-head MMA, logits pre-scaled -> exp2f ----
#pragma unroll 1
        for (int h = 0; h < NHEAD; h++) {
            int hs = h * 8;
            float2 qlo = *(const float2*)(sQa + hs);
            float2 qhi = *(const float2*)(sQb + hs);
            uint32_t Aq[4] = { __float_as_uint(qlo.x), __float_as_uint(qhi.x),
                               __float_as_uint(qlo.y), __float_as_uint(qhi.y) };
            float e[10][4];
#pragma unroll
            for (int nt = 0; nt < 10; nt++) {
                e[nt][0] = e[nt][1] = e[nt][2] = e[nt][3] = 0.f;
                float2 kv = *(const float2*)(U1a + nt * 8 * 72 + hs);
                uint32_t B[2] = { __float_as_uint(kv.x), __float_as_uint(kv.y) };
                mma_tf32(e[nt], Aq, B);
            }
            float dlo = 0.f, dhi = 0.f;
#pragma unroll
            for (int nt = 0; nt < 10; nt++) {
                float e0 = to_tf32(exp2f(e[nt][0]));
                float e1 = to_tf32(exp2f(e[nt][1]));
                float e2 = to_tf32(exp2f(e[nt][2]));
                float e3 = to_tf32(exp2f(e[nt][3]));
                e[nt][0] = e0; e[nt][1] = e1; e[nt][2] = e2; e[nt][3] = e3;
                dlo += e0 + e1; dhi += e2 + e3;
            }
            dlo += __shfl_xor_sync(0xffffffffu, dlo, 1);
            dlo += __shfl_xor_sync(0xffffffffu, dlo, 2);
            dhi += __shfl_xor_sync(0xffffffffu, dhi, 1);
            dhi += __shfl_xor_sync(0xffffffffu, dhi, 2);
            float ilo = 1.f / (dlo - 3.f), ihi = 1.f / (dhi - 3.f);
            float dO[4] = { 0.f, 0.f, 0.f, 0.f };
#pragma unroll
            for (int kt = 0; kt < 10; kt++) {
                uint32_t A2[4] = { __float_as_uint(e[kt][0]), __float_as_uint(e[kt][2]),
                                   __float_as_uint(e[kt][1]), __float_as_uint(e[kt][3]) };
                float2 vv = *(const float2*)(VTa + hs * 104 + kt * 8);
                uint32_t B[2] = { __float_as_uint(vv.x), __float_as_uint(vv.y) };
                mma_tf32(dO, A2, B);
            }
            *(sQa + hs)     = dO[0] * ilo;
            *(sQa + hs + 1) = dO[1] * ilo;
            *(sQb + hs)     = dO[2] * ihi;
            *(sQb + hs + 1) = dO[3] * ihi;
        }
        __syncthreads();
        for (int idx = tid; idx < 1024; idx += 512) {
            int o = idx >> 4, j4 = (idx & 15) * 4;
            *(float4*)&U1[o * 72 + j4] = *(const float4*)&g_owT[blk * 4096 + o * 64 + j4];
        }
        __syncthreads();

        // ---- phase E: out-proj + residual into sF ----
        {
            float d[2][4][4];
#pragma unroll
            for (int mt = 0; mt < 2; mt++)
#pragma unroll
                for (int nt = 0; nt < 4; nt++)
#pragma unroll
                    for (int q = 0; q < 4; q++) d[mt][nt][q] = 0.f;
#pragma unroll
            for (int ks = 0; ks < 8; ks++) {
                int po = ks * 8 + tig * 2;
                uint32_t A[2][4];
#pragma unroll
                for (int mt = 0; mt < 2; mt++) {
                    float2 lo = *(const float2*)&sQ[(mA + mt * 16) * 72 + po];
                    float2 hi = *(const float2*)&sQ[(mA + mt * 16 + 8) * 72 + po];
                    A[mt][0] = __float_as_uint(lo.x); A[mt][1] = __float_as_uint(hi.x);
                    A[mt][2] = __float_as_uint(lo.y); A[mt][3] = __float_as_uint(hi.y);
                }
#pragma unroll
                for (int nt = 0; nt < 4; nt++) {
                    int n = wn * 32 + nt * 8 + g;
                    float2 bv = *(const float2*)&U1[n * 72 + po];
                    uint32_t B[2] = { __float_as_uint(bv.x), __float_as_uint(bv.y) };
                    mma_tf32(d[0][nt], A[0], B);
                    mma_tf32(d[1][nt], A[1], B);
                }
            }
#pragma unroll
            for (int mt = 0; mt < 2; mt++)
#pragma unroll
                for (int nt = 0; nt < 4; nt++) {
                    int c0 = wn * 32 + nt * 8 + tig * 2;
                    int s0 = picf(c0), s1 = picf(c0 + 1);
                    float o0 = sF[s0 * 72 + 67], o1 = sF[s1 * 72 + 67];
                    int r0 = mA + mt * 16, r1 = r0 + 8;
                    sF[r0 * 72 + s0] += d[mt][nt][0] + o0;
                    sF[r0 * 72 + s1] += d[mt][nt][1] + o1;
                    sF[r1 * 72 + s0] += d[mt][nt][2] + o0;
                    sF[r1 * 72 + s1] += d[mt][nt][3] + o1;
                }
        }
    }
    __syncthreads();
    for (int idx = tid; idx < 16384; idx += 512) {
        int c = idx >> 8, p = idx & 255;
        int row = p >> 6, xx = p & 63;
        g_feat[(((size_t)b * 64 + c) * 64 + (yp * 4 + row)) * 64 + xx]
            = sF[p * 72 + picf(c)];
    }
}

// ---------------- TF32 tensor-core up-conv + pixel-shuffle + relu ----------------
__global__ void __launch_bounds__(256, 3) k_upconv_tc(int lvl, int IH, int IW,
                                                      const float* __restrict__ up_b) {
    const float* in   = lvl ? g_u1 : g_feat;
    float*       outp = lvl ? g_u2 : g_u1;
    __shared__ float sA[180 * 72];
    __shared__ float sBT[64 * 72];
    int x0 = blockIdx.x * 16, y0 = blockIdx.y * 8;
    int bz = blockIdx.z; int b = bz >> 2, ocg = bz & 3;
    int tid = threadIdx.x;
    int w = tid >> 5, lane = tid & 31;
    int g = lane >> 2, tig = lane & 3;
    int wm = w & 3, wn = w >> 2;

    for (int idx = tid; idx < 180 * 64; idx += 256) {
        int ic = idx / 180; int sp = idx % 180;
        int r = sp / 18, c = sp % 18;
        int gy = y0 - 1 + r, gx = x0 - 1 + c;
        float v = 0.f;
        if (gy >= 0 && gy < IH && gx >= 0 && gx < IW)
            v = in[(((size_t)b * 64 + ic) * IH + gy) * IW + gx];
        sA[sp * 72 + picf(ic)] = to_tf32(v);
    }

    float d[2][4][4];
#pragma unroll
    for (int nt = 0; nt < 4; nt++) {
        int oc = ocg * 64 + wn * 32 + nt * 8 + tig * 2;
        float b0v = up_b[lvl * 256 + oc];
        float b1v = up_b[lvl * 256 + oc + 1];
#pragma unroll
        for (int mt = 0; mt < 2; mt++) {
            d[mt][nt][0] = b0v; d[mt][nt][1] = b1v;
            d[mt][nt][2] = b0v; d[mt][nt][3] = b1v;
        }
    }

#pragma unroll 1
    for (int t = 0; t < 9; t++) {
        int ky = t / 3, kx = t % 3;
        __syncthreads();
        for (int idx = tid; idx < 4096; idx += 256) {
            int ic = idx & 63, oc = idx >> 6;
            sBT[oc * 72 + picf(ic)] =
                g_wupT[((((lvl * 9 + t) * 4 + ocg) * 64 + oc) * 64) + ic];
        }
        __syncthreads();
        int sp_base[2][2];
#pragma unroll
        for (int mt = 0; mt < 2; mt++) {
            int m_lo = wm * 32 + mt * 16 + g;
            int m_hi = m_lo + 8;
            sp_base[mt][0] = ((m_lo >> 4) + ky) * 18 + (m_lo & 15) + kx;
            sp_base[mt][1] = ((m_hi >> 4) + ky) * 18 + (m_hi & 15) + kx;
        }
#pragma unroll
        for (int ks = 0; ks < 8; ks++) {
            int po = ks * 8 + tig * 2;
            uint32_t A[2][4];
#pragma unroll
            for (int mt = 0; mt < 2; mt++) {
                float2 lo = *(const float2*)&sA[sp_base[mt][0] * 72 + po];
                float2 hi = *(const float2*)&sA[sp_base[mt][1] * 72 + po];
                A[mt][0] = __float_as_uint(lo.x);
                A[mt][1] = __float_as_uint(hi.x);
                A[mt][2] = __float_as_uint(lo.y);
                A[mt][3] = __float_as_uint(hi.y);
            }
            uint32_t Bf[4][2];
#pragma unroll
            for (int nt = 0; nt < 4; nt++) {
                int nc = wn * 32 + nt * 8 + g;
                float2 bv = *(const float2*)&sBT[nc * 72 + po];
                Bf[nt][0] = __float_as_uint(bv.x);
                Bf[nt][1] = __float_as_uint(bv.y);
            }
#pragma unroll
            for (int mt = 0; mt < 2; mt++)
#pragma unroll
                for (int nt = 0; nt < 4; nt++)
                    mma_tf32(d[mt][nt], A[mt], Bf[nt]);
        }
    }

    int OW = IW * 2;
#pragma unroll
    for (int mt = 0; mt < 2; mt++) {
#pragma unroll
        for (int half = 0; half < 2; half++) {
            int m = wm * 32 + mt * 16 + g + half * 8;
            int gy = y0 + (m >> 4), gx = x0 + (m & 15);
#pragma unroll
            for (int nt = 0; nt < 4; nt++) {
                int oc4a = ocg * 64 + wn * 32 + nt * 8 + tig * 2;
                float v0 = d[mt][nt][half * 2 + 0];
                float v1 = d[mt][nt][half * 2 + 1];
                int ca = oc4a >> 2, r1a = (oc4a >> 1) & 1, r2a = oc4a & 1;
                int oc4b = oc4a + 1;
                int cb = oc4b >> 2, r1b = (oc4b >> 1) & 1, r2b = oc4b & 1;
                outp[(((size_t)b * 64 + ca) * (size_t)(IH * 2) + (size_t)(2 * gy + r1a)) * (size_t)OW
                     + 2 * gx + r2a] = fmaxf(v0, 0.f);
                outp[(((size_t)b * 64 + cb) * (size_t)(IH * 2) + (size_t)(2 * gy + r1b)) * (size_t)OW
                     + 2 * gx + r2b] = fmaxf(v1, 0.f);
            }
        }
    }
}

// ---------------- final conv 64->3 at 256x256 ----------------
__global__ void __launch_bounds__(256) k_cl(const float* __restrict__ w,
                                            const float* __restrict__ bias,
                                            float* __restrict__ out) {
    __shared__ float sw[3 * 64 * 9];
    __shared__ float sin_[4][10][132];
    int xbase = blockIdx.x * 128;
    int y0 = blockIdx.y * 8;
    int b = blockIdx.z;
    int tid = threadIdx.x;
    int xg = tid & 31; int yr = tid >> 5;
    int x0 = xg * 4;
    for (int i = tid; i < 1728; i += 256) sw[i] = w[i];
    float acc[3][4];
#pragma unroll
    for (int oc = 0; oc < 3; oc++) {
        float bb = bias[oc];
#pragma unroll
        for (int xi = 0; xi < 4; xi++) acc[oc][xi] = bb;
    }
    for (int ic0 = 0; ic0 < 64; ic0 += 4) {
        __syncthreads();
        for (int idx = tid; idx < 4 * 10 * 130; idx += 256) {
            int c = idx % 130; int r = (idx / 130) % 10; int icc = idx / 1300;
            int gy = y0 - 1 + r, gx = xbase - 1 + c;
            float v = 0.f;
            if (gy >= 0 && gy < 256 && gx >= 0 && gx < 256)
                v = g_u2[(((size_t)b * 64 + ic0 + icc) * 256 + gy) * 256 + gx];
            sin_[icc][r][c] = v;
        }
        __syncthreads();
        for (int icc = 0; icc < 4; icc++) {
#pragma unroll
            for (int ky = 0; ky < 3; ky++) {
                float in6[6];
#pragma unroll
                for (int t = 0; t < 6; t++) in6[t] = sin_[icc][yr + ky][x0 + t];
#pragma unroll
                for (int kx = 0; kx < 3; kx++) {
#pragma unroll
                    for (int oc = 0; oc < 3; oc++) {
                        float wv = sw[(oc * 64 + ic0 + icc) * 9 + ky * 3 + kx];
#pragma unroll
                        for (int xi = 0; xi < 4; xi++)
                            acc[oc][xi] += wv * in6[kx + xi];
                    }
                }
            }
        }
    }
    int gy = y0 + yr, gx0 = xbase + x0;
#pragma unroll
    for (int oc = 0; oc < 3; oc++) {
        float4 v = make_float4(acc[oc][0], acc[oc][1], acc[oc][2], acc[oc][3]);
        *(float4*)&out[(((size_t)b * 3 + oc) * 256 + gy) * 256 + gx0] = v;
    }
}

// ---------------- launcher ----------------
extern "C" void kernel_launch(void* const* d_in, const int* in_sizes, int n_in,
                              void* d_out, int out_size) {
    const float* x      = (const float*)d_in[0];
    const float* th     = (const float*)d_in[1];
    const float* proj_w = (const float*)d_in[2];
    const float* proj_b = (const float*)d_in[3];
    const float* cf_w   = (const float*)d_in[4];
    const float* cf_b   = (const float*)d_in[5];
    const float* qw     = (const float*)d_in[6];
    const float* qb     = (const float*)d_in[7];
    const float* kw     = (const float*)d_in[8];
    const float* kb     = (const float*)d_in[9];
    const float* vw     = (const float*)d_in[10];
    const float* vb     = (const float*)d_in[11];
    const float* ow     = (const float*)d_in[12];
    const float* ob     = (const float*)d_in[13];
    const float* l1w    = (const float*)d_in[14];
    const float* l1b    = (const float*)d_in[15];
    const float* l2w    = (const float*)d_in[16];
    const float* l2b    = (const float*)d_in[17];
    const float* up_w   = (const float*)d_in[18];
    const float* up_b   = (const float*)d_in[19];
    const float* cl_w   = (const float*)d_in[20];
    const float* cl_b   = (const float*)d_in[21];
    float* out = (float*)d_out;

    const int ATTN_SMEM = (80 * 72 + 64 * 104 + 2 * 256 * 72) * 4;  // 197120 B
    cudaFuncSetAttribute(k_attn_stack,
                         cudaFuncAttributeMaxDynamicSharedMemorySize, ATTN_SMEM);

    k_textproj<<<BATCH * LSEQ, 64>>>(th, proj_w, proj_b, up_w, qw, ow);
    k_convin<<<BATCH * HH, 256>>>(x, cf_w, cf_b);
    k_kvall<<<dim3(NBLK, BATCH, 2), 256>>>(kw, kb, vw, vb, l2w, l2b);
    k_attn_stack<<<BATCH * 16, 512, ATTN_SMEM>>>(qb, ob, l1w, l1b);
    k_upconv_tc<<<dim3(4, 8, BATCH * 4), 256>>>(0, 64, 64, up_b);
    k_upconv_tc<<<dim3(8, 16, BATCH * 4), 256>>>(1, 128, 128, up_b);
    k_cl<<<dim3(2, 32, BATCH), 256>>>(cl_w, cl_b, out);

    (void)in_sizes; (void)n_in; (void)out_size;
}

// round 16
// speedup vs baseline: 2.6260x; 1.1876x over previous
#include <cuda_runtime.h>
#include <cuda_bf16.h>
#include <cuda_fp16.h>
#include <cstdint>

// ---------------- problem constants ----------------
#define BATCH 8
#define CCH   64
#define HH    64
#define WW    64
#define NPOS  4096
#define LSEQ  77
#define DTXT  512
#define NBLK  16
#define NHEAD 8
#define HDIM  8

// ---------------- device scratch ----------------
__device__ float g_tf  [BATCH*LSEQ*CCH];
__device__ float g_kn  [NBLK*BATCH*LSEQ*CCH];   // pic-permuted, tf32
__device__ float g_v   [NBLK*BATCH*LSEQ*CCH];   // pic-permuted
__device__ float g_qwT [NBLK*64*64];            // [blk][o][pic(i)], tf32
__device__ float g_owT [NBLK*64*64];            // [blk][o][pic(i)], tf32
__device__ float g_feat[BATCH*CCH*HH*WW];
__device__ float g_u1  [BATCH*CCH*128*128];
__device__ float g_u2  [(size_t)BATCH*CCH*256*256];
__device__ __half g_wupH[2*9*4*64*64];          // [lvl][tap][ocg][oc][ic], fp16

__device__ __forceinline__ float to_tf32(float x) {
    float r; asm("cvt.rna.tf32.f32 %0, %1;" : "=f"(r) : "f"(x)); return r;
}
__device__ __forceinline__ void mma_tf32(float* d, const uint32_t* a, const uint32_t* b) {
    asm volatile(
        "mma.sync.aligned.m16n8k8.row.col.f32.tf32.tf32.f32 "
        "{%0,%1,%2,%3}, {%4,%5,%6,%7}, {%8,%9}, {%0,%1,%2,%3};"
        : "+f"(d[0]), "+f"(d[1]), "+f"(d[2]), "+f"(d[3])
        : "r"(a[0]), "r"(a[1]), "r"(a[2]), "r"(a[3]), "r"(b[0]), "r"(b[1]));
}
__device__ __forceinline__ void mma_f16(float* d, const uint32_t* a, const uint32_t* b) {
    asm volatile(
        "mma.sync.aligned.m16n8k16.row.col.f32.f16.f16.f32 "
        "{%0,%1,%2,%3}, {%4,%5,%6,%7}, {%8,%9}, {%0,%1,%2,%3};"
        : "+f"(d[0]), "+f"(d[1]), "+f"(d[2]), "+f"(d[3])
        : "r"(a[0]), "r"(a[1]), "r"(a[2]), "r"(a[3]), "r"(b[0]), "r"(b[1]));
}
// permuted channel index: ic = ks*8 + tig + 4h  ->  pic = ks*8 + tig*2 + h
__device__ __forceinline__ int picf(int ic) {
    int r = ic & 7;
    return (ic & ~7) + ((r & 3) * 2) + (r >> 2);
}

// ---------------- text projection (+ fused weight preps) ----------------
__global__ void k_textproj(const float* __restrict__ th,
                           const float* __restrict__ pw,
                           const float* __restrict__ pb,
                           const float* __restrict__ upw,
                           const float* __restrict__ qw,
                           const float* __restrict__ ow) {
    __shared__ float s[DTXT];
    int bl = blockIdx.x;
    const float* row = th + (size_t)bl * DTXT;
    for (int i = threadIdx.x; i < DTXT; i += 64) s[i] = row[i];
    __syncthreads();
    int c = threadIdx.x;
    const float* w = pw + (size_t)c * DTXT;
    float acc = pb[c];
#pragma unroll 8
    for (int d = 0; d < DTXT; ++d) acc += s[d] * w[d];
    g_tf[bl * CCH + c] = acc;
    for (int idx = blockIdx.x * 64 + threadIdx.x; idx < 2 * 256 * 64 * 9;
         idx += gridDim.x * 64) {
        int k = idx % 9;
        int t = idx / 9;
        int ic = t % 64; t /= 64;
        int oc4 = t % 256;
        int lvl = t / 256;
        g_wupH[((((lvl * 9 + k) * 4 + (oc4 >> 6)) * 64 + (oc4 & 63)) * 64) + ic]
            = __float2half(upw[idx]);
    }
    for (int idx = blockIdx.x * 64 + threadIdx.x; idx < NBLK * 4096;
         idx += gridDim.x * 64) {
        int i = idx & 63;
        int base = idx & ~63;
        g_qwT[base + picf(i)] = to_tf32(qw[idx]);
        g_owT[base + picf(i)] = to_tf32(ow[idx]);
    }
}

// ---------------- input conv 3->64, 3x3 (256 threads) ----------------
__global__ void __launch_bounds__(256) k_convin(const float* __restrict__ x,
                                                const float* __restrict__ w,
                                                const float* __restrict__ bias) {
    __shared__ float sw[64 * 27];
    __shared__ float sb[64];
    __shared__ float sin_[3][3][66];
    int bid = blockIdx.x; int b = bid >> 6; int y = bid & 63;
    int tid = threadIdx.x;
    for (int i = tid; i < 64 * 27; i += 256) sw[i] = w[i];
    if (tid < 64) sb[tid] = bias[tid];
    for (int idx = tid; idx < 9 * 66; idx += 256) {
        int c = idx % 66; int t = idx / 66;
        int ic = t / 3, r = t % 3;
        int yy = y + r - 1, xx = c - 1;
        float v = 0.f;
        if (yy >= 0 && yy < HH && xx >= 0 && xx < WW)
            v = x[(((size_t)b * 3 + ic) * HH + yy) * WW + xx];
        sin_[ic][r][c] = v;
    }
    __syncthreads();
    int xx = tid & 63, oq = tid >> 6;
    for (int oj = 0; oj < 16; oj++) {
        int oc = oq * 16 + oj;
        float acc = sb[oc];
#pragma unroll
        for (int ic = 0; ic < 3; ic++)
#pragma unroll
            for (int r = 0; r < 3; r++)
#pragma unroll
                for (int kx = 0; kx < 3; kx++)
                    acc += sin_[ic][r][xx + kx] * sw[(oc * 3 + ic) * 9 + r * 3 + kx];
        g_feat[(((size_t)b * CCH + oc) * HH + y) * WW + xx] = acc;
    }
}

// ---------------- K/V projection + LN(K); outputs pic-permuted (K tf32) ----------------
__global__ void __launch_bounds__(256) k_kvall(
        const float* __restrict__ kw, const float* __restrict__ kb,
        const float* __restrict__ vw, const float* __restrict__ vb,
        const float* __restrict__ l2w, const float* __restrict__ l2b) {
    __shared__ float tfs[LSEQ * 64];
    __shared__ float kws[64 * 68];
    __shared__ float vws[64 * 68];
    __shared__ float ksm[4 * 64];
    int blk = blockIdx.x, b = blockIdx.y, z = blockIdx.z;
    int tid = threadIdx.x;
    for (int i = tid; i < LSEQ * 64; i += 256) tfs[i] = g_tf[b * LSEQ * 64 + i];
    for (int idx = tid; idx < 4096; idx += 256) {
        int o = idx >> 6, c = idx & 63;
        kws[c * 68 + o] = kw[blk * 4096 + idx];
        vws[c * 68 + o] = vw[blk * 4096 + idx];
    }
    __syncthreads();
    int o = tid & 63, rr = tid >> 6;
    int so = picf(o);
    float kbv = kb[blk * 64 + o], vbv = vb[blk * 64 + o];
    float lwv = l2w[blk * 64 + o], lbv = l2b[blk * 64 + o];
    size_t base = ((size_t)(blk * BATCH + b)) * LSEQ * 64;
    int rbeg = z * 40, rend = rbeg + 40;
    for (int r0 = rbeg; r0 < rend; r0 += 4) {
        int r = r0 + rr;
        bool act = r < LSEQ;
        float ka = kbv, va = vbv;
        if (act) {
#pragma unroll 8
            for (int c = 0; c < 64; c++) {
                float t = tfs[r * 64 + c];
                ka += t * kws[c * 68 + o];
                va += t * vws[c * 68 + o];
            }
            ksm[rr * 64 + o] = ka;
        }
        __syncthreads();
        if (act) {
            float m = 0.f;
#pragma unroll 8
            for (int i = 0; i < 64; i++) m += ksm[rr * 64 + i];
            m *= (1.f / 64.f);
            float vv = 0.f;
#pragma unroll 8
            for (int i = 0; i < 64; i++) { float d = ksm[rr * 64 + i] - m; vv += d * d; }
            vv *= (1.f / 64.f);
            float rs = rsqrtf(vv + 1e-5f);
            g_kn[base + r * 64 + so] = to_tf32((ka - m) * rs * lwv + lbv);
            g_v [base + r * 64 + so] = va;
        }
        __syncthreads();
    }
}

// ---------------- Tensor-core attention stack (unchanged from R15) ----------------
__global__ void __launch_bounds__(512, 1) k_attn_stack(
        const float* __restrict__ qb, const float* __restrict__ ob,
        const float* __restrict__ l1w, const float* __restrict__ l1b) {
    extern __shared__ __align__(16) float dyn[];
    float* U1  = dyn;
    float* VT  = U1 + 80 * 72;
    float* sF  = VT + 64 * 104;
    float* sQ  = sF + 256 * 72;

    int b = blockIdx.x >> 4, yp = blockIdx.x & 15;
    int tid = threadIdx.x;
    int w = tid >> 5, lane = tid & 31;
    int g = lane >> 2, tig = lane & 3;
    int wm = w & 7, wn = w >> 3;
    int mA = wm * 32 + g;
    int rowA = w * 16 + g;
    const float SC = 0.35355339059327373f * 1.4426950408889634f;

    for (int idx = tid; idx < 16384; idx += 512) {
        int c = idx >> 8, p = idx & 255;
        int row = p >> 6, xx = p & 63;
        sF[p * 72 + picf(c)] =
            g_feat[(((size_t)b * 64 + c) * 64 + (yp * 4 + row)) * 64 + xx];
    }
    if (tid < 192) VT[(tid / 3) * 104 + 77 + (tid % 3)] = 0.f;
    if (tid >= 192 && tid < 408) U1[77 * 72 + (tid - 192)] = 0.f;

    float* sQa = &sQ[rowA * 72 + tig * 2];
    float* sQb = &sQ[(rowA + 8) * 72 + tig * 2];
    const float* U1a = &U1[g * 72 + tig * 2];
    const float* VTa = &VT[g * 104 + tig * 2];

#pragma unroll 1
    for (int blk = 0; blk < NBLK; blk++) {
        size_t kvbase = ((size_t)(blk * BATCH + b)) * LSEQ * 64;
        __syncthreads();
        for (int idx = tid; idx < 1024; idx += 512) {
            int o = idx >> 4, j4 = (idx & 15) * 4;
            *(float4*)&U1[o * 72 + j4] = *(const float4*)&g_qwT[blk * 4096 + o * 64 + j4];
        }
        for (int idx = tid; idx < LSEQ * 64; idx += 512) {
            int l = idx >> 6, s = idx & 63;
            VT[s * 104 + l] = g_v[kvbase + idx];
        }
        if (tid < 64) {
            int s = picf(tid);
            sF[s * 72 + 64] = qb[blk * 64 + tid];
            sF[s * 72 + 65] = l1w[blk * 64 + tid] * SC;
            sF[s * 72 + 66] = l1b[blk * 64 + tid] * SC;
            sF[s * 72 + 67] = ob[blk * 64 + tid];
        }
        __syncthreads();

        {
            float d[2][4][4];
#pragma unroll
            for (int mt = 0; mt < 2; mt++)
#pragma unroll
                for (int nt = 0; nt < 4; nt++)
#pragma unroll
                    for (int e = 0; e < 4; e++) d[mt][nt][e] = 0.f;
#pragma unroll
            for (int ks = 0; ks < 8; ks++) {
                int po = ks * 8 + tig * 2;
                uint32_t A[2][4];
#pragma unroll
                for (int mt = 0; mt < 2; mt++) {
                    float2 lo = *(const float2*)&sF[(mA + mt * 16) * 72 + po];
                    float2 hi = *(const float2*)&sF[(mA + mt * 16 + 8) * 72 + po];
                    A[mt][0] = __float_as_uint(lo.x); A[mt][1] = __float_as_uint(hi.x);
                    A[mt][2] = __float_as_uint(lo.y); A[mt][3] = __float_as_uint(hi.y);
                }
#pragma unroll
                for (int nt = 0; nt < 4; nt++) {
                    int n = wn * 32 + nt * 8 + g;
                    float2 bv = *(const float2*)&U1[n * 72 + po];
                    uint32_t B[2] = { __float_as_uint(bv.x), __float_as_uint(bv.y) };
                    mma_tf32(d[0][nt], A[0], B);
                    mma_tf32(d[1][nt], A[1], B);
                }
            }
#pragma unroll
            for (int mt = 0; mt < 2; mt++)
#pragma unroll
                for (int nt = 0; nt < 4; nt++) {
                    int c0 = wn * 32 + nt * 8 + tig * 2;
                    int s0 = picf(c0), s1 = picf(c0 + 1);
                    float q0 = sF[s0 * 72 + 64], q1 = sF[s1 * 72 + 64];
                    int r0 = mA + mt * 16, r1 = r0 + 8;
                    sQ[r0 * 72 + s0] = d[mt][nt][0] + q0;
                    sQ[r0 * 72 + s1] = d[mt][nt][1] + q1;
                    sQ[r1 * 72 + s0] = d[mt][nt][2] + q0;
                    sQ[r1 * 72 + s1] = d[mt][nt][3] + q1;
                }
        }
        __syncthreads();

        {
            int pp = tid >> 1, j = tid & 1;
            float v[32];
#pragma unroll
            for (int q = 0; q < 8; q++) {
                float4 t = *(const float4*)&sQ[pp * 72 + j * 32 + q * 4];
                v[q * 4 + 0] = t.x; v[q * 4 + 1] = t.y;
                v[q * 4 + 2] = t.z; v[q * 4 + 3] = t.w;
            }
            int xx = pp & 63, yl = pp >> 6;
            float pe = (j == 0) ? (float)xx * (0.05f / 63.f)
                                : (float)(yp * 4 + yl) * (0.05f / 63.f);
            float s = 0.f;
#pragma unroll
            for (int e = 0; e < 32; e++) { v[e] += pe; s += v[e]; }
            s += __shfl_xor_sync(0xffffffffu, s, 1);
            float mean = s * (1.f / 64.f);
            float sq = 0.f;
#pragma unroll
            for (int e = 0; e < 32; e++) { float dl = v[e] - mean; sq += dl * dl; }
            sq += __shfl_xor_sync(0xffffffffu, sq, 1);
            float rs = rsqrtf(sq * (1.f / 64.f) + 1e-5f);
#pragma unroll
            for (int q = 0; q < 8; q++) {
                int s0 = j * 32 + q * 4;
                float4 o;
                o.x = to_tf32((v[q * 4 + 0] - mean) * rs * sF[(s0 + 0) * 72 + 65] + sF[(s0 + 0) * 72 + 66]);
                o.y = to_tf32((v[q * 4 + 1] - mean) * rs * sF[(s0 + 1) * 72 + 65] + sF[(s0 + 1) * 72 + 66]);
                o.z = to_tf32((v[q * 4 + 2] - mean) * rs * sF[(s0 + 2) * 72 + 65] + sF[(s0 + 2) * 72 + 66]);
                o.w = to_tf32((v[q * 4 + 3] - mean) * rs * sF[(s0 + 3) * 72 + 65] + sF[(s0 + 3) * 72 + 66]);
                *(float4*)&sQ[pp * 72 + s0] = o;
            }
        }
        for (int idx = tid; idx < LSEQ * 16; idx += 512) {
            int l = idx >> 4, j4 = (idx & 15) * 4;
            *(float4*)&U1[l * 72 + j4] = *(const float4*)&g_kn[kvbase + l * 64 + j4];
        }
        __syncthreads();

#pragma unroll 1
        for (int h = 0; h < NHEAD; h++) {
            int hs = h * 8;
            float2 qlo = *(const float2*)(sQa + hs);
            float2 qhi = *(const float2*)(sQb + hs);
            uint32_t Aq[4] = { __float_as_uint(qlo.x), __float_as_uint(qhi.x),
                               __float_as_uint(qlo.y), __float_as_uint(qhi.y) };
            float e[10][4];
#pragma unroll
            for (int nt = 0; nt < 10; nt++) {
                e[nt][0] = e[nt][1] = e[nt][2] = e[nt][3] = 0.f;
                float2 kv = *(const float2*)(U1a + nt * 8 * 72 + hs);
                uint32_t B[2] = { __float_as_uint(kv.x), __float_as_uint(kv.y) };
                mma_tf32(e[nt], Aq, B);
            }
            float dlo = 0.f, dhi = 0.f;
#pragma unroll
            for (int nt = 0; nt < 10; nt++) {
                float e0 = to_tf32(exp2f(e[nt][0]));
                float e1 = to_tf32(exp2f(e[nt][1]));
                float e2 = to_tf32(exp2f(e[nt][2]));
                float e3 = to_tf32(exp2f(e[nt][3]));
                e[nt][0] = e0; e[nt][1] = e1; e[nt][2] = e2; e[nt][3] = e3;
                dlo += e0 + e1; dhi += e2 + e3;
            }
            dlo += __shfl_xor_sync(0xffffffffu, dlo, 1);
            dlo += __shfl_xor_sync(0xffffffffu, dlo, 2);
            dhi += __shfl_xor_sync(0xffffffffu, dhi, 1);
            dhi += __shfl_xor_sync(0xffffffffu, dhi, 2);
            float ilo = 1.f / (dlo - 3.f), ihi = 1.f / (dhi - 3.f);
            float dO[4] = { 0.f, 0.f, 0.f, 0.f };
#pragma unroll
            for (int kt = 0; kt < 10; kt++) {
                uint32_t A2[4] = { __float_as_uint(e[kt][0]), __float_as_uint(e[kt][2]),
                                   __float_as_uint(e[kt][1]), __float_as_uint(e[kt][3]) };
                float2 vv = *(const float2*)(VTa + hs * 104 + kt * 8);
                uint32_t B[2] = { __float_as_uint(vv.x), __float_as_uint(vv.y) };
                mma_tf32(dO, A2, B);
            }
            *(sQa + hs)     = dO[0] * ilo;
            *(sQa + hs + 1) = dO[1] * ilo;
            *(sQb + hs)     = dO[2] * ihi;
            *(sQb + hs + 1) = dO[3] * ihi;
        }
        __syncthreads();
        for (int idx = tid; idx < 1024; idx += 512) {
            int o = idx >> 4, j4 = (idx & 15) * 4;
            *(float4*)&U1[o * 72 + j4] = *(const float4*)&g_owT[blk * 4096 + o * 64 + j4];
        }
        __syncthreads();

        {
            float d[2][4][4];
#pragma unroll
            for (int mt = 0; mt < 2; mt++)
#pragma unroll
                for (int nt = 0; nt < 4; nt++)
#pragma unroll
                    for (int q = 0; q < 4; q++) d[mt][nt][q] = 0.f;
#pragma unroll
            for (int ks = 0; ks < 8; ks++) {
                int po = ks * 8 + tig * 2;
                uint32_t A[2][4];
#pragma unroll
                for (int mt = 0; mt < 2; mt++) {
                    float2 lo = *(const float2*)&sQ[(mA + mt * 16) * 72 + po];
                    float2 hi = *(const float2*)&sQ[(mA + mt * 16 + 8) * 72 + po];
                    A[mt][0] = __float_as_uint(lo.x); A[mt][1] = __float_as_uint(hi.x);
                    A[mt][2] = __float_as_uint(lo.y); A[mt][3] = __float_as_uint(hi.y);
                }
#pragma unroll
                for (int nt = 0; nt < 4; nt++) {
                    int n = wn * 32 + nt * 8 + g;
                    float2 bv = *(const float2*)&U1[n * 72 + po];
                    uint32_t B[2] = { __float_as_uint(bv.x), __float_as_uint(bv.y) };
                    mma_tf32(d[0][nt], A[0], B);
                    mma_tf32(d[1][nt], A[1], B);
                }
            }
#pragma unroll
            for (int mt = 0; mt < 2; mt++)
#pragma unroll
                for (int nt = 0; nt < 4; nt++) {
                    int c0 = wn * 32 + nt * 8 + tig * 2;
                    int s0 = picf(c0), s1 = picf(c0 + 1);
                    float o0 = sF[s0 * 72 + 67], o1 = sF[s1 * 72 + 67];
                    int r0 = mA + mt * 16, r1 = r0 + 8;
                    sF[r0 * 72 + s0] += d[mt][nt][0] + o0;
                    sF[r0 * 72 + s1] += d[mt][nt][1] + o1;
                    sF[r1 * 72 + s0] += d[mt][nt][2] + o0;
                    sF[r1 * 72 + s1] += d[mt][nt][3] + o1;
                }
        }
    }
    __syncthreads();
    for (int idx = tid; idx < 16384; idx += 512) {
        int c = idx >> 8, p = idx & 255;
        int row = p >> 6, xx = p & 63;
        g_feat[(((size_t)b * 64 + c) * 64 + (yp * 4 + row)) * 64 + xx]
            = sF[p * 72 + picf(c)];
    }
}

// ---------------- FP16 tensor-core up-conv + pixel-shuffle + relu ----------------
// m16n8k16 f16: natural channel order, stride 72 halves (144B) conflict-free.
__global__ void __launch_bounds__(256, 3) k_upconv_h(int lvl, int IH, int IW,
                                                     const float* __restrict__ up_b) {
    const float* in   = lvl ? g_u1 : g_feat;
    float*       outp = lvl ? g_u2 : g_u1;
    __shared__ __half sA[180 * 72];
    __shared__ __half sBT[64 * 72];
    int x0 = blockIdx.x * 16, y0 = blockIdx.y * 8;
    int bz = blockIdx.z; int b = bz >> 2, ocg = bz & 3;
    int tid = threadIdx.x;
    int w = tid >> 5, lane = tid & 31;
    int g = lane >> 2, tig = lane & 3;
    int wm = w & 3, wn = w >> 2;

    // stage input tile with halo -> fp16
    for (int idx = tid; idx < 180 * 64; idx += 256) {
        int ic = idx / 180; int sp = idx % 180;
        int r = sp / 18, c = sp % 18;
        int gy = y0 - 1 + r, gx = x0 - 1 + c;
        float v = 0.f;
        if (gy >= 0 && gy < IH && gx >= 0 && gx < IW)
            v = in[(((size_t)b * 64 + ic) * IH + gy) * IW + gx];
        sA[sp * 72 + ic] = __float2half(v);
    }

    float d[2][4][4];
#pragma unroll
    for (int nt = 0; nt < 4; nt++) {
        int oc = ocg * 64 + wn * 32 + nt * 8 + tig * 2;
        float b0v = up_b[lvl * 256 + oc];
        float b1v = up_b[lvl * 256 + oc + 1];
#pragma unroll
        for (int mt = 0; mt < 2; mt++) {
            d[mt][nt][0] = b0v; d[mt][nt][1] = b1v;
            d[mt][nt][2] = b0v; d[mt][nt][3] = b1v;
        }
    }

    const __half2* wsrc = (const __half2*)g_wupH;

#pragma unroll 1
    for (int t = 0; t < 9; t++) {
        int ky = t / 3, kx = t % 3;
        __syncthreads();
        // stage weights (half2): [oc][ic] natural order
        for (int idx = tid; idx < 2048; idx += 256) {
            int ic2 = idx & 31, oc = idx >> 5;
            *(__half2*)&sBT[oc * 72 + ic2 * 2] =
                wsrc[((((lvl * 9 + t) * 4 + ocg) * 64 + oc) * 32) + ic2];
        }
        __syncthreads();
        int sp_base[2][2];
#pragma unroll
        for (int mt = 0; mt < 2; mt++) {
            int m_lo = wm * 32 + mt * 16 + g;
            int m_hi = m_lo + 8;
            sp_base[mt][0] = ((m_lo >> 4) + ky) * 18 + (m_lo & 15) + kx;
            sp_base[mt][1] = ((m_hi >> 4) + ky) * 18 + (m_hi & 15) + kx;
        }
#pragma unroll
        for (int ks = 0; ks < 4; ks++) {
            int kb = ks * 16 + tig * 2;
            uint32_t A[2][4];
#pragma unroll
            for (int mt = 0; mt < 2; mt++) {
                A[mt][0] = *(const uint32_t*)&sA[sp_base[mt][0] * 72 + kb];
                A[mt][1] = *(const uint32_t*)&sA[sp_base[mt][1] * 72 + kb];
                A[mt][2] = *(const uint32_t*)&sA[sp_base[mt][0] * 72 + kb + 8];
                A[mt][3] = *(const uint32_t*)&sA[sp_base[mt][1] * 72 + kb + 8];
            }
#pragma unroll
            for (int nt = 0; nt < 4; nt++) {
                int nc = wn * 32 + nt * 8 + g;
                uint32_t B[2];
                B[0] = *(const uint32_t*)&sBT[nc * 72 + kb];
                B[1] = *(const uint32_t*)&sBT[nc * 72 + kb + 8];
                mma_f16(d[0][nt], A[0], B);
                mma_f16(d[1][nt], A[1], B);
            }
        }
    }

    int OW = IW * 2;
#pragma unroll
    for (int mt = 0; mt < 2; mt++) {
#pragma unroll
        for (int half = 0; half < 2; half++) {
            int m = wm * 32 + mt * 16 + g + half * 8;
            int gy = y0 + (m >> 4), gx = x0 + (m & 15);
#pragma unroll
            for (int nt = 0; nt < 4; nt++) {
                int oc4a = ocg * 64 + wn * 32 + nt * 8 + tig * 2;
                float v0 = d[mt][nt][half * 2 + 0];
                float v1 = d[mt][nt][half * 2 + 1];
                int ca = oc4a >> 2, r1a = (oc4a >> 1) & 1, r2a = oc4a & 1;
                int oc4b = oc4a + 1;
                int cb = oc4b >> 2, r1b = (oc4b >> 1) & 1, r2b = oc4b & 1;
                outp[(((size_t)b * 64 + ca) * (size_t)(IH * 2) + (size_t)(2 * gy + r1a)) * (size_t)OW
                     + 2 * gx + r2a] = fmaxf(v0, 0.f);
                outp[(((size_t)b * 64 + cb) * (size_t)(IH * 2) + (size_t)(2 * gy + r1b)) * (size_t)OW
                     + 2 * gx + r2b] = fmaxf(v1, 0.f);
            }
        }
    }
}

// ---------------- final conv 64->3 at 256x256 ----------------
__global__ void __launch_bounds__(256) k_cl(const float* __restrict__ w,
                                            const float* __restrict__ bias,
                                            float* __restrict__ out) {
    __shared__ float sw[3 * 64 * 9];
    __shared__ float sin_[4][10][132];
    int xbase = blockIdx.x * 128;
    int y0 = blockIdx.y * 8;
    int b = blockIdx.z;
    int tid = threadIdx.x;
    int xg = tid & 31; int yr = tid >> 5;
    int x0 = xg * 4;
    for (int i = tid; i < 1728; i += 256) sw[i] = w[i];
    float acc[3][4];
#pragma unroll
    for (int oc = 0; oc < 3; oc++) {
        float bb = bias[oc];
#pragma unroll
        for (int xi = 0; xi < 4; xi++) acc[oc][xi] = bb;
    }
    for (int ic0 = 0; ic0 < 64; ic0 += 4) {
        __syncthreads();
        for (int idx = tid; idx < 4 * 10 * 130; idx += 256) {
            int c = idx % 130; int r = (idx / 130) % 10; int icc = idx / 1300;
            int gy = y0 - 1 + r, gx = xbase - 1 + c;
            float v = 0.f;
            if (gy >= 0 && gy < 256 && gx >= 0 && gx < 256)
                v = g_u2[(((size_t)b * 64 + ic0 + icc) * 256 + gy) * 256 + gx];
            sin_[icc][r][c] = v;
        }
        __syncthreads();
        for (int icc = 0; icc < 4; icc++) {
#pragma unroll
            for (int ky = 0; ky < 3; ky++) {
                float in6[6];
#pragma unroll
                for (int t = 0; t < 6; t++) in6[t] = sin_[icc][yr + ky][x0 + t];
#pragma unroll
                for (int kx = 0; kx < 3; kx++) {
#pragma unroll
                    for (int oc = 0; oc < 3; oc++) {
                        float wv = sw[(oc * 64 + ic0 + icc) * 9 + ky * 3 + kx];
#pragma unroll
                        for (int xi = 0; xi < 4; xi++)
                            acc[oc][xi] += wv * in6[kx + xi];
                    }
                }
            }
        }
    }
    int gy = y0 + yr, gx0 = xbase + x0;
#pragma unroll
    for (int oc = 0; oc < 3; oc++) {
        float4 v = make_float4(acc[oc][0], acc[oc][1], acc[oc][2], acc[oc][3]);
        *(float4*)&out[(((size_t)b * 3 + oc) * 256 + gy) * 256 + gx0] = v;
    }
}

// ---------------- launcher ----------------
extern "C" void kernel_launch(void* const* d_in, const int* in_sizes, int n_in,
                              void* d_out, int out_size) {
    const float* x      = (const float*)d_in[0];
    const float* th     = (const float*)d_in[1];
    const float* proj_w = (const float*)d_in[2];
    const float* proj_b = (const float*)d_in[3];
    const float* cf_w   = (const float*)d_in[4];
    const float* cf_b   = (const float*)d_in[5];
    const float* qw     = (const float*)d_in[6];
    const float* qb     = (const float*)d_in[7];
    const float* kw     = (const float*)d_in[8];
    const float* kb     = (const float*)d_in[9];
    const float* vw     = (const float*)d_in[10];
    const float* vb     = (const float*)d_in[11];
    const float* ow     = (const float*)d_in[12];
    const float* ob     = (const float*)d_in[13];
    const float* l1w    = (const float*)d_in[14];
    const float* l1b    = (const float*)d_in[15];
    const float* l2w    = (const float*)d_in[16];
    const float* l2b    = (const float*)d_in[17];
    const float* up_w   = (const float*)d_in[18];
    const float* up_b   = (const float*)d_in[19];
    const float* cl_w   = (const float*)d_in[20];
    const float* cl_b   = (const float*)d_in[21];
    float* out = (float*)d_out;

    const int ATTN_SMEM = (80 * 72 + 64 * 104 + 2 * 256 * 72) * 4;  // 197120 B
    cudaFuncSetAttribute(k_attn_stack,
                         cudaFuncAttributeMaxDynamicSharedMemorySize, ATTN_SMEM);

    k_textproj<<<BATCH * LSEQ, 64>>>(th, proj_w, proj_b, up_w, qw, ow);
    k_convin<<<BATCH * HH, 256>>>(x, cf_w, cf_b);
    k_kvall<<<dim3(NBLK, BATCH, 2), 256>>>(kw, kb, vw, vb, l2w, l2b);
    k_attn_stack<<<BATCH * 16, 512, ATTN_SMEM>>>(qb, ob, l1w, l1b);
    k_upconv_h<<<dim3(4, 8, BATCH * 4), 256>>>(0, 64, 64, up_b);
    k_upconv_h<<<dim3(8, 16, BATCH * 4), 256>>>(1, 128, 128, up_b);
    k_cl<<<dim3(2, 32, BATCH), 256>>>(cl_w, cl_b, out);

    (void)in_sizes; (void)n_in; (void)out_size;
}

// round 17
// speedup vs baseline: 2.9111x; 1.1086x over previous
#include <cuda_runtime.h>
#include <cuda_bf16.h>
#include <cuda_fp16.h>
#include <cstdint>

// ---------------- problem constants ----------------
#define BATCH 8
#define CCH   64
#define HH    64
#define WW    64
#define NPOS  4096
#define LSEQ  77
#define DTXT  512
#define NBLK  16
#define NHEAD 8
#define HDIM  8

// ---------------- device scratch ----------------
__device__ float  g_tf  [BATCH*LSEQ*CCH];
__device__ __half g_knH [NBLK*BATCH*LSEQ*CCH];  // pic-permuted, fp16
__device__ __half g_vH  [NBLK*BATCH*LSEQ*CCH];  // pic-permuted, fp16
__device__ __half g_qwH [NBLK*64*64];           // [blk][o][pic(i)], fp16
__device__ __half g_owH [NBLK*64*64];           // [blk][o][pic(i)], fp16
__device__ float  g_feat[BATCH*CCH*HH*WW];
__device__ float  g_u1  [BATCH*CCH*128*128];
__device__ float  g_u2  [(size_t)BATCH*CCH*256*256];
__device__ __half g_wupH[2*9*4*64*64];          // [lvl][tap][ocg][oc][ic], fp16

__device__ __forceinline__ void mma_f16(float* d, const uint32_t* a, const uint32_t* b) {
    asm volatile(
        "mma.sync.aligned.m16n8k16.row.col.f32.f16.f16.f32 "
        "{%0,%1,%2,%3}, {%4,%5,%6,%7}, {%8,%9}, {%0,%1,%2,%3};"
        : "+f"(d[0]), "+f"(d[1]), "+f"(d[2]), "+f"(d[3])
        : "r"(a[0]), "r"(a[1]), "r"(a[2]), "r"(a[3]), "r"(b[0]), "r"(b[1]));
}
__device__ __forceinline__ void mma_f16k8(float* d, const uint32_t* a, uint32_t b) {
    asm volatile(
        "mma.sync.aligned.m16n8k8.row.col.f32.f16.f16.f32 "
        "{%0,%1,%2,%3}, {%4,%5}, {%6}, {%0,%1,%2,%3};"
        : "+f"(d[0]), "+f"(d[1]), "+f"(d[2]), "+f"(d[3])
        : "r"(a[0]), "r"(a[1]), "r"(b));
}
__device__ __forceinline__ uint32_t h2u(float lo, float hi) {
    __half2 h = __floats2half2_rn(lo, hi);
    return *(uint32_t*)&h;
}
// permuted channel index: ic = ks*8 + tig + 4h  ->  pic = ks*8 + tig*2 + h
__device__ __forceinline__ int picf(int ic) {
    int r = ic & 7;
    return (ic & ~7) + ((r & 3) * 2) + (r >> 2);
}

// ---------------- text projection (+ fused weight preps) ----------------
__global__ void k_textproj(const float* __restrict__ th,
                           const float* __restrict__ pw,
                           const float* __restrict__ pb,
                           const float* __restrict__ upw,
                           const float* __restrict__ qw,
                           const float* __restrict__ ow) {
    __shared__ float s[DTXT];
    int bl = blockIdx.x;
    const float* row = th + (size_t)bl * DTXT;
    for (int i = threadIdx.x; i < DTXT; i += 64) s[i] = row[i];
    __syncthreads();
    int c = threadIdx.x;
    const float* w = pw + (size_t)c * DTXT;
    float acc = pb[c];
#pragma unroll 8
    for (int d = 0; d < DTXT; ++d) acc += s[d] * w[d];
    g_tf[bl * CCH + c] = acc;
    for (int idx = blockIdx.x * 64 + threadIdx.x; idx < 2 * 256 * 64 * 9;
         idx += gridDim.x * 64) {
        int k = idx % 9;
        int t = idx / 9;
        int ic = t % 64; t /= 64;
        int oc4 = t % 256;
        int lvl = t / 256;
        g_wupH[((((lvl * 9 + k) * 4 + (oc4 >> 6)) * 64 + (oc4 & 63)) * 64) + ic]
            = __float2half(upw[idx]);
    }
    for (int idx = blockIdx.x * 64 + threadIdx.x; idx < NBLK * 4096;
         idx += gridDim.x * 64) {
        int i = idx & 63;
        int base = idx & ~63;
        g_qwH[base + picf(i)] = __float2half(qw[idx]);
        g_owH[base + picf(i)] = __float2half(ow[idx]);
    }
}

// ---------------- input conv 3->64, 3x3 (256 threads) ----------------
__global__ void __launch_bounds__(256) k_convin(const float* __restrict__ x,
                                                const float* __restrict__ w,
                                                const float* __restrict__ bias) {
    __shared__ float sw[64 * 27];
    __shared__ float sb[64];
    __shared__ float sin_[3][3][66];
    int bid = blockIdx.x; int b = bid >> 6; int y = bid & 63;
    int tid = threadIdx.x;
    for (int i = tid; i < 64 * 27; i += 256) sw[i] = w[i];
    if (tid < 64) sb[tid] = bias[tid];
    for (int idx = tid; idx < 9 * 66; idx += 256) {
        int c = idx % 66; int t = idx / 66;
        int ic = t / 3, r = t % 3;
        int yy = y + r - 1, xx = c - 1;
        float v = 0.f;
        if (yy >= 0 && yy < HH && xx >= 0 && xx < WW)
            v = x[(((size_t)b * 3 + ic) * HH + yy) * WW + xx];
        sin_[ic][r][c] = v;
    }
    __syncthreads();
    int xx = tid & 63, oq = tid >> 6;
    for (int oj = 0; oj < 16; oj++) {
        int oc = oq * 16 + oj;
        float acc = sb[oc];
#pragma unroll
        for (int ic = 0; ic < 3; ic++)
#pragma unroll
            for (int r = 0; r < 3; r++)
#pragma unroll
                for (int kx = 0; kx < 3; kx++)
                    acc += sin_[ic][r][xx + kx] * sw[(oc * 3 + ic) * 9 + r * 3 + kx];
        g_feat[(((size_t)b * CCH + oc) * HH + y) * WW + xx] = acc;
    }
}

// ---------------- K/V projection + LN(K); outputs pic-permuted fp16 ----------------
__global__ void __launch_bounds__(256) k_kvall(
        const float* __restrict__ kw, const float* __restrict__ kb,
        const float* __restrict__ vw, const float* __restrict__ vb,
        const float* __restrict__ l2w, const float* __restrict__ l2b) {
    __shared__ float tfs[LSEQ * 64];
    __shared__ float kws[64 * 68];
    __shared__ float vws[64 * 68];
    __shared__ float ksm[4 * 64];
    int blk = blockIdx.x, b = blockIdx.y, z = blockIdx.z;
    int tid = threadIdx.x;
    for (int i = tid; i < LSEQ * 64; i += 256) tfs[i] = g_tf[b * LSEQ * 64 + i];
    for (int idx = tid; idx < 4096; idx += 256) {
        int o = idx >> 6, c = idx & 63;
        kws[c * 68 + o] = kw[blk * 4096 + idx];
        vws[c * 68 + o] = vw[blk * 4096 + idx];
    }
    __syncthreads();
    int o = tid & 63, rr = tid >> 6;
    int so = picf(o);
    float kbv = kb[blk * 64 + o], vbv = vb[blk * 64 + o];
    float lwv = l2w[blk * 64 + o], lbv = l2b[blk * 64 + o];
    size_t base = ((size_t)(blk * BATCH + b)) * LSEQ * 64;
    int rbeg = z * 40, rend = rbeg + 40;
    for (int r0 = rbeg; r0 < rend; r0 += 4) {
        int r = r0 + rr;
        bool act = r < LSEQ;
        float ka = kbv, va = vbv;
        if (act) {
#pragma unroll 8
            for (int c = 0; c < 64; c++) {
                float t = tfs[r * 64 + c];
                ka += t * kws[c * 68 + o];
                va += t * vws[c * 68 + o];
            }
            ksm[rr * 64 + o] = ka;
        }
        __syncthreads();
        if (act) {
            float m = 0.f;
#pragma unroll 8
            for (int i = 0; i < 64; i++) m += ksm[rr * 64 + i];
            m *= (1.f / 64.f);
            float vv = 0.f;
#pragma unroll 8
            for (int i = 0; i < 64; i++) { float d = ksm[rr * 64 + i] - m; vv += d * d; }
            vv *= (1.f / 64.f);
            float rs = rsqrtf(vv + 1e-5f);
            g_knH[base + r * 64 + so] = __float2half((ka - m) * rs * lwv + lbv);
            g_vH [base + r * 64 + so] = __float2half(va);
        }
        __syncthreads();
    }
}

// ---------------- FP16 tensor-core attention stack: 4 rows/CTA ----------------
// smem: U1h[80*72]h | VTh[64*104]h | sQh[256*72]h | sF[256*72]f | sQ[256*72]f = 209152 B
__global__ void __launch_bounds__(512, 1) k_attn_stack(
        const float* __restrict__ qb, const float* __restrict__ ob,
        const float* __restrict__ l1w, const float* __restrict__ l1b) {
    extern __shared__ __align__(16) char dynraw[];
    __half* U1h = (__half*)dynraw;               // 11520 B
    __half* VTh = U1h + 80 * 72;                 // 13312 B
    __half* sQh = VTh + 64 * 104;                // 36864 B
    float*  sF  = (float*)(sQh + 256 * 72);      // 73728 B
    float*  sQ  = sF + 256 * 72;                 // 73728 B

    int b = blockIdx.x >> 4, yp = blockIdx.x & 15;
    int tid = threadIdx.x;
    int w = tid >> 5, lane = tid & 31;
    int g = lane >> 2, tig = lane & 3;
    int wm = w & 7, wn = w >> 3;
    int mA = wm * 32 + g;
    int rowA = w * 16 + g;
    const float SC = 0.35355339059327373f * 1.4426950408889634f;

    for (int idx = tid; idx < 16384; idx += 512) {
        int c = idx >> 8, p = idx & 255;
        int row = p >> 6, xx = p & 63;
        sF[p * 72 + picf(c)] =
            g_feat[(((size_t)b * 64 + c) * 64 + (yp * 4 + row)) * 64 + xx];
    }
    if (tid < 192) VTh[(tid / 3) * 104 + 77 + (tid % 3)] = __float2half(0.f);
    if (tid >= 192 && tid < 408) U1h[77 * 72 + (tid - 192)] = __float2half(0.f);

    __half* sQha = sQh + rowA * 72 + tig * 2;
    __half* sQhb = sQh + (rowA + 8) * 72 + tig * 2;
    const __half* U1ha = U1h + g * 72 + tig * 2;
    const __half* VTha = VTh + g * 104 + tig * 2;

#pragma unroll 1
    for (int blk = 0; blk < NBLK; blk++) {
        size_t kvbase = ((size_t)(blk * BATCH + b)) * LSEQ * 64;
        __syncthreads();
        // stage Wq (uint4), V -> VTh (transpose), consts -> sF tails
        for (int idx = tid; idx < 512; idx += 512) { }
        for (int idx = tid; idx < 512; idx += 512) {
            int o = idx >> 3, j8 = (idx & 7) * 8;
            *(uint4*)&U1h[o * 72 + j8] = *(const uint4*)&g_qwH[blk * 4096 + o * 64 + j8];
        }
        for (int idx = tid; idx < LSEQ * 64; idx += 512) {
            int l = idx >> 6, s = idx & 63;
            VTh[s * 104 + l] = g_vH[kvbase + idx];
        }
        if (tid < 64) {
            int s = picf(tid);
            sF[s * 72 + 64] = qb[blk * 64 + tid];
            sF[s * 72 + 65] = l1w[blk * 64 + tid] * SC;
            sF[s * 72 + 66] = l1b[blk * 64 + tid] * SC;
            sF[s * 72 + 67] = ob[blk * 64 + tid];
        }
        __syncthreads();

        // ---- phase B: q_raw = sF @ Wq (fp16 mma, A converted on the fly) ----
        {
            float d[2][4][4];
#pragma unroll
            for (int mt = 0; mt < 2; mt++)
#pragma unroll
                for (int nt = 0; nt < 4; nt++)
#pragma unroll
                    for (int e = 0; e < 4; e++) d[mt][nt][e] = 0.f;
#pragma unroll
            for (int ks = 0; ks < 4; ks++) {
                int kb = ks * 16 + tig * 2;
                uint32_t A[2][4];
#pragma unroll
                for (int mt = 0; mt < 2; mt++) {
                    int r0 = (mA + mt * 16) * 72, r1 = (mA + mt * 16 + 8) * 72;
                    float2 f0 = *(const float2*)&sF[r0 + kb];
                    float2 f1 = *(const float2*)&sF[r1 + kb];
                    float2 f2 = *(const float2*)&sF[r0 + kb + 8];
                    float2 f3 = *(const float2*)&sF[r1 + kb + 8];
                    A[mt][0] = h2u(f0.x, f0.y);
                    A[mt][1] = h2u(f1.x, f1.y);
                    A[mt][2] = h2u(f2.x, f2.y);
                    A[mt][3] = h2u(f3.x, f3.y);
                }
#pragma unroll
                for (int nt = 0; nt < 4; nt++) {
                    int n = wn * 32 + nt * 8 + g;
                    uint32_t B[2];
                    B[0] = *(const uint32_t*)&U1h[n * 72 + kb];
                    B[1] = *(const uint32_t*)&U1h[n * 72 + kb + 8];
                    mma_f16(d[0][nt], A[0], B);
                    mma_f16(d[1][nt], A[1], B);
                }
            }
#pragma unroll
            for (int mt = 0; mt < 2; mt++)
#pragma unroll
                for (int nt = 0; nt < 4; nt++) {
                    int c0 = wn * 32 + nt * 8 + tig * 2;
                    int s0 = picf(c0), s1 = picf(c0 + 1);
                    float q0 = sF[s0 * 72 + 64], q1 = sF[s1 * 72 + 64];
                    int r0 = mA + mt * 16, r1 = r0 + 8;
                    sQ[r0 * 72 + s0] = d[mt][nt][0] + q0;
                    sQ[r0 * 72 + s1] = d[mt][nt][1] + q1;
                    sQ[r1 * 72 + s0] = d[mt][nt][2] + q0;
                    sQ[r1 * 72 + s1] = d[mt][nt][3] + q1;
                }
        }
        __syncthreads();

        // ---- LN (pre-scaled by SC) -> sQh fp16 ; stage K -> U1h ----
        {
            int pp = tid >> 1, j = tid & 1;
            float v[32];
#pragma unroll
            for (int q = 0; q < 8; q++) {
                float4 t = *(const float4*)&sQ[pp * 72 + j * 32 + q * 4];
                v[q * 4 + 0] = t.x; v[q * 4 + 1] = t.y;
                v[q * 4 + 2] = t.z; v[q * 4 + 3] = t.w;
            }
            int xx = pp & 63, yl = pp >> 6;
            float pe = (j == 0) ? (float)xx * (0.05f / 63.f)
                                : (float)(yp * 4 + yl) * (0.05f / 63.f);
            float s = 0.f;
#pragma unroll
            for (int e = 0; e < 32; e++) { v[e] += pe; s += v[e]; }
            s += __shfl_xor_sync(0xffffffffu, s, 1);
            float mean = s * (1.f / 64.f);
            float sq = 0.f;
#pragma unroll
            for (int e = 0; e < 32; e++) { float dl = v[e] - mean; sq += dl * dl; }
            sq += __shfl_xor_sync(0xffffffffu, sq, 1);
            float rs = rsqrtf(sq * (1.f / 64.f) + 1e-5f);
#pragma unroll
            for (int q = 0; q < 8; q++) {
                int s0 = j * 32 + q * 4;
                float o0 = (v[q * 4 + 0] - mean) * rs * sF[(s0 + 0) * 72 + 65] + sF[(s0 + 0) * 72 + 66];
                float o1 = (v[q * 4 + 1] - mean) * rs * sF[(s0 + 1) * 72 + 65] + sF[(s0 + 1) * 72 + 66];
                float o2 = (v[q * 4 + 2] - mean) * rs * sF[(s0 + 2) * 72 + 65] + sF[(s0 + 2) * 72 + 66];
                float o3 = (v[q * 4 + 3] - mean) * rs * sF[(s0 + 3) * 72 + 65] + sF[(s0 + 3) * 72 + 66];
                *(uint32_t*)&sQh[pp * 72 + s0]     = h2u(o0, o1);
                *(uint32_t*)&sQh[pp * 72 + s0 + 2] = h2u(o2, o3);
            }
        }
        for (int idx = tid; idx < 616; idx += 512) {
            int l = idx >> 3, j8 = (idx & 7) * 8;
            *(uint4*)&U1h[l * 72 + j8] = *(const uint4*)&g_knH[kvbase + l * 64 + j8];
        }
        __syncthreads();

        // ---- attention: per-head fp16 MMA ----
#pragma unroll 1
        for (int h = 0; h < NHEAD; h++) {
            int hs = h * 8;
            uint32_t Aq[2] = { *(const uint32_t*)(sQha + hs),
                               *(const uint32_t*)(sQhb + hs) };
            float e[10][4];
#pragma unroll
            for (int nt = 0; nt < 10; nt++) {
                e[nt][0] = e[nt][1] = e[nt][2] = e[nt][3] = 0.f;
                uint32_t B = *(const uint32_t*)(U1ha + nt * 8 * 72 + hs);
                mma_f16k8(e[nt], Aq, B);
            }
            float dlo = 0.f, dhi = 0.f;
#pragma unroll
            for (int nt = 0; nt < 10; nt++) {
                e[nt][0] = exp2f(e[nt][0]);
                e[nt][1] = exp2f(e[nt][1]);
                e[nt][2] = exp2f(e[nt][2]);
                e[nt][3] = exp2f(e[nt][3]);
                dlo += e[nt][0] + e[nt][1];
                dhi += e[nt][2] + e[nt][3];
            }
            dlo += __shfl_xor_sync(0xffffffffu, dlo, 1);
            dlo += __shfl_xor_sync(0xffffffffu, dlo, 2);
            dhi += __shfl_xor_sync(0xffffffffu, dhi, 1);
            dhi += __shfl_xor_sync(0xffffffffu, dhi, 2);
            float ilo = 1.f / (dlo - 3.f), ihi = 1.f / (dhi - 3.f);
            float dO[4] = { 0.f, 0.f, 0.f, 0.f };
#pragma unroll
            for (int kt = 0; kt < 5; kt++) {
                uint32_t A2[4];
                A2[0] = h2u(e[2 * kt][0], e[2 * kt][1]);
                A2[1] = h2u(e[2 * kt][2], e[2 * kt][3]);
                A2[2] = h2u(e[2 * kt + 1][0], e[2 * kt + 1][1]);
                A2[3] = h2u(e[2 * kt + 1][2], e[2 * kt + 1][3]);
                uint32_t B[2];
                B[0] = *(const uint32_t*)(VTha + hs * 104 + kt * 16);
                B[1] = *(const uint32_t*)(VTha + hs * 104 + kt * 16 + 8);
                mma_f16(dO, A2, B);
            }
            *(uint32_t*)(sQha + hs) = h2u(dO[0] * ilo, dO[1] * ilo);
            *(uint32_t*)(sQhb + hs) = h2u(dO[2] * ihi, dO[3] * ihi);
        }
        __syncthreads();
        // stage Wo -> U1h
        for (int idx = tid; idx < 512; idx += 512) {
            int o = idx >> 3, j8 = (idx & 7) * 8;
            *(uint4*)&U1h[o * 72 + j8] = *(const uint4*)&g_owH[blk * 4096 + o * 64 + j8];
        }
        __syncthreads();

        // ---- phase E: out-proj (fp16 mma) + residual into sF ----
        {
            float d[2][4][4];
#pragma unroll
            for (int mt = 0; mt < 2; mt++)
#pragma unroll
                for (int nt = 0; nt < 4; nt++)
#pragma unroll
                    for (int q = 0; q < 4; q++) d[mt][nt][q] = 0.f;
#pragma unroll
            for (int ks = 0; ks < 4; ks++) {
                int kb = ks * 16 + tig * 2;
                uint32_t A[2][4];
#pragma unroll
                for (int mt = 0; mt < 2; mt++) {
                    int r0 = (mA + mt * 16) * 72, r1 = (mA + mt * 16 + 8) * 72;
                    A[mt][0] = *(const uint32_t*)&sQh[r0 + kb];
                    A[mt][1] = *(const uint32_t*)&sQh[r1 + kb];
                    A[mt][2] = *(const uint32_t*)&sQh[r0 + kb + 8];
                    A[mt][3] = *(const uint32_t*)&sQh[r1 + kb + 8];
                }
#pragma unroll
                for (int nt = 0; nt < 4; nt++) {
                    int n = wn * 32 + nt * 8 + g;
                    uint32_t B[2];
                    B[0] = *(const uint32_t*)&U1h[n * 72 + kb];
                    B[1] = *(const uint32_t*)&U1h[n * 72 + kb + 8];
                    mma_f16(d[0][nt], A[0], B);
                    mma_f16(d[1][nt], A[1], B);
                }
            }
#pragma unroll
            for (int mt = 0; mt < 2; mt++)
#pragma unroll
                for (int nt = 0; nt < 4; nt++) {
                    int c0 = wn * 32 + nt * 8 + tig * 2;
                    int s0 = picf(c0), s1 = picf(c0 + 1);
                    float o0 = sF[s0 * 72 + 67], o1 = sF[s1 * 72 + 67];
                    int r0 = mA + mt * 16, r1 = r0 + 8;
                    sF[r0 * 72 + s0] += d[mt][nt][0] + o0;
                    sF[r0 * 72 + s1] += d[mt][nt][1] + o1;
                    sF[r1 * 72 + s0] += d[mt][nt][2] + o0;
                    sF[r1 * 72 + s1] += d[mt][nt][3] + o1;
                }
        }
    }
    __syncthreads();
    for (int idx = tid; idx < 16384; idx += 512) {
        int c = idx >> 8, p = idx & 255;
        int row = p >> 6, xx = p & 63;
        g_feat[(((size_t)b * 64 + c) * 64 + (yp * 4 + row)) * 64 + xx]
            = sF[p * 72 + picf(c)];
    }
}

// ---------------- FP16 tensor-core up-conv + pixel-shuffle + relu ----------------
__global__ void __launch_bounds__(256, 3) k_upconv_h(int lvl, int IH, int IW,
                                                     const float* __restrict__ up_b) {
    const float* in   = lvl ? g_u1 : g_feat;
    float*       outp = lvl ? g_u2 : g_u1;
    __shared__ __half sA[180 * 72];
    __shared__ __half sBT[64 * 72];
    int x0 = blockIdx.x * 16, y0 = blockIdx.y * 8;
    int bz = blockIdx.z; int b = bz >> 2, ocg = bz & 3;
    int tid = threadIdx.x;
    int w = tid >> 5, lane = tid & 31;
    int g = lane >> 2, tig = lane & 3;
    int wm = w & 3, wn = w >> 2;

    for (int idx = tid; idx < 180 * 64; idx += 256) {
        int ic = idx / 180; int sp = idx % 180;
        int r = sp / 18, c = sp % 18;
        int gy = y0 - 1 + r, gx = x0 - 1 + c;
        float v = 0.f;
        if (gy >= 0 && gy < IH && gx >= 0 && gx < IW)
            v = in[(((size_t)b * 64 + ic) * IH + gy) * IW + gx];
        sA[sp * 72 + ic] = __float2half(v);
    }

    float d[2][4][4];
#pragma unroll
    for (int nt = 0; nt < 4; nt++) {
        int oc = ocg * 64 + wn * 32 + nt * 8 + tig * 2;
        float b0v = up_b[lvl * 256 + oc];
        float b1v = up_b[lvl * 256 + oc + 1];
#pragma unroll
        for (int mt = 0; mt < 2; mt++) {
            d[mt][nt][0] = b0v; d[mt][nt][1] = b1v;
            d[mt][nt][2] = b0v; d[mt][nt][3] = b1v;
        }
    }

    const __half2* wsrc = (const __half2*)g_wupH;

#pragma unroll 1
    for (int t = 0; t < 9; t++) {
        int ky = t / 3, kx = t % 3;
        __syncthreads();
        for (int idx = tid; idx < 2048; idx += 256) {
            int ic2 = idx & 31, oc = idx >> 5;
            *(__half2*)&sBT[oc * 72 + ic2 * 2] =
                wsrc[((((lvl * 9 + t) * 4 + ocg) * 64 + oc) * 32) + ic2];
        }
        __syncthreads();
        int sp_base[2][2];
#pragma unroll
        for (int mt = 0; mt < 2; mt++) {
            int m_lo = wm * 32 + mt * 16 + g;
            int m_hi = m_lo + 8;
            sp_base[mt][0] = ((m_lo >> 4) + ky) * 18 + (m_lo & 15) + kx;
            sp_base[mt][1] = ((m_hi >> 4) + ky) * 18 + (m_hi & 15) + kx;
        }
#pragma unroll
        for (int ks = 0; ks < 4; ks++) {
            int kb = ks * 16 + tig * 2;
            uint32_t A[2][4];
#pragma unroll
            for (int mt = 0; mt < 2; mt++) {
                A[mt][0] = *(const uint32_t*)&sA[sp_base[mt][0] * 72 + kb];
                A[mt][1] = *(const uint32_t*)&sA[sp_base[mt][1] * 72 + kb];
                A[mt][2] = *(const uint32_t*)&sA[sp_base[mt][0] * 72 + kb + 8];
                A[mt][3] = *(const uint32_t*)&sA[sp_base[mt][1] * 72 + kb + 8];
            }
#pragma unroll
            for (int nt = 0; nt < 4; nt++) {
                int nc = wn * 32 + nt * 8 + g;
                uint32_t B[2];
                B[0] = *(const uint32_t*)&sBT[nc * 72 + kb];
                B[1] = *(const uint32_t*)&sBT[nc * 72 + kb + 8];
                mma_f16(d[0][nt], A[0], B);
                mma_f16(d[1][nt], A[1], B);
            }
        }
    }

    int OW = IW * 2;
#pragma unroll
    for (int mt = 0; mt < 2; mt++) {
#pragma unroll
        for (int half = 0; half < 2; half++) {
            int m = wm * 32 + mt * 16 + g + half * 8;
            int gy = y0 + (m >> 4), gx = x0 + (m & 15);
#pragma unroll
            for (int nt = 0; nt < 4; nt++) {
                int oc4a = ocg * 64 + wn * 32 + nt * 8 + tig * 2;
                float v0 = d[mt][nt][half * 2 + 0];
                float v1 = d[mt][nt][half * 2 + 1];
                int ca = oc4a >> 2, r1a = (oc4a >> 1) & 1, r2a = oc4a & 1;
                int oc4b = oc4a + 1;
                int cb = oc4b >> 2, r1b = (oc4b >> 1) & 1, r2b = oc4b & 1;
                outp[(((size_t)b * 64 + ca) * (size_t)(IH * 2) + (size_t)(2 * gy + r1a)) * (size_t)OW
                     + 2 * gx + r2a] = fmaxf(v0, 0.f);
                outp[(((size_t)b * 64 + cb) * (size_t)(IH * 2) + (size_t)(2 * gy + r1b)) * (size_t)OW
                     + 2 * gx + r2b] = fmaxf(v1, 0.f);
            }
        }
    }
}

// ---------------- final conv 64->3 at 256x256 ----------------
__global__ void __launch_bounds__(256) k_cl(const float* __restrict__ w,
                                            const float* __restrict__ bias,
                                            float* __restrict__ out) {
    __shared__ float sw[3 * 64 * 9];
    __shared__ float sin_[4][10][132];
    int xbase = blockIdx.x * 128;
    int y0 = blockIdx.y * 8;
    int b = blockIdx.z;
    int tid = threadIdx.x;
    int xg = tid & 31; int yr = tid >> 5;
    int x0 = xg * 4;
    for (int i = tid; i < 1728; i += 256) sw[i] = w[i];
    float acc[3][4];
#pragma unroll
    for (int oc = 0; oc < 3; oc++) {
        float bb = bias[oc];
#pragma unroll
        for (int xi = 0; xi < 4; xi++) acc[oc][xi] = bb;
    }
    for (int ic0 = 0; ic0 < 64; ic0 += 4) {
        __syncthreads();
        for (int idx = tid; idx < 4 * 10 * 130; idx += 256) {
            int c = idx % 130; int r = (idx / 130) % 10; int icc = idx / 1300;
            int gy = y0 - 1 + r, gx = xbase - 1 + c;
            float v = 0.f;
            if (gy >= 0 && gy < 256 && gx >= 0 && gx < 256)
                v = g_u2[(((size_t)b * 64 + ic0 + icc) * 256 + gy) * 256 + gx];
            sin_[icc][r][c] = v;
        }
        __syncthreads();
        for (int icc = 0; icc < 4; icc++) {
#pragma unroll
            for (int ky = 0; ky < 3; ky++) {
                float in6[6];
#pragma unroll
                for (int t = 0; t < 6; t++) in6[t] = sin_[icc][yr + ky][x0 + t];
#pragma unroll
                for (int kx = 0; kx < 3; kx++) {
#pragma unroll
                    for (int oc = 0; oc < 3; oc++) {
                        float wv = sw[(oc * 64 + ic0 + icc) * 9 + ky * 3 + kx];
#pragma unroll
                        for (int xi = 0; xi < 4; xi++)
                            acc[oc][xi] += wv * in6[kx + xi];
                    }
                }
            }
        }
    }
    int gy = y0 + yr, gx0 = xbase + x0;
#pragma unroll
    for (int oc = 0; oc < 3; oc++) {
        float4 v = make_float4(acc[oc][0], acc[oc][1], acc[oc][2], acc[oc][3]);
        *(float4*)&out[(((size_t)b * 3 + oc) * 256 + gy) * 256 + gx0] = v;
    }
}

// ---------------- launcher ----------------
extern "C" void kernel_launch(void* const* d_in, const int* in_sizes, int n_in,
                              void* d_out, int out_size) {
    const float* x      = (const float*)d_in[0];
    const float* th     = (const float*)d_in[1];
    const float* proj_w = (const float*)d_in[2];
    const float* proj_b = (const float*)d_in[3];
    const float* cf_w   = (const float*)d_in[4];
    const float* cf_b   = (const float*)d_in[5];
    const float* qw     = (const float*)d_in[6];
    const float* qb     = (const float*)d_in[7];
    const float* kw     = (const float*)d_in[8];
    const float* kb     = (const float*)d_in[9];
    const float* vw     = (const float*)d_in[10];
    const float* vb     = (const float*)d_in[11];
    const float* ow     = (const float*)d_in[12];
    const float* ob     = (const float*)d_in[13];
    const float* l1w    = (const float*)d_in[14];
    const float* l1b    = (const float*)d_in[15];
    const float* l2w    = (const float*)d_in[16];
    const float* l2b    = (const float*)d_in[17];
    const float* up_w   = (const float*)d_in[18];
    const float* up_b   = (const float*)d_in[19];
    const float* cl_w   = (const float*)d_in[20];
    const float* cl_b   = (const float*)d_in[21];
    float* out = (float*)d_out;

    const int ATTN_SMEM = (80 * 72 + 64 * 104 + 256 * 72) * 2 + (2 * 256 * 72) * 4;  // 209152 B
    cudaFuncSetAttribute(k_attn_stack,
                         cudaFuncAttributeMaxDynamicSharedMemorySize, ATTN_SMEM);

    k_textproj<<<BATCH * LSEQ, 64>>>(th, proj_w, proj_b, up_w, qw, ow);
    k_convin<<<BATCH * HH, 256>>>(x, cf_w, cf_b);
    k_kvall<<<dim3(NBLK, BATCH, 2), 256>>>(kw, kb, vw, vb, l2w, l2b);
    k_attn_stack<<<BATCH * 16, 512, ATTN_SMEM>>>(qb, ob, l1w, l1b);
    k_upconv_h<<<dim3(4, 8, BATCH * 4), 256>>>(0, 64, 64, up_b);
    k_upconv_h<<<dim3(8, 16, BATCH * 4), 256>>>(1, 128, 128, up_b);
    k_cl<<<dim3(2, 32, BATCH), 256>>>(cl_w, cl_b, out);

    (void)in_sizes; (void)n_in; (void)out_size;
}